// round 5
// baseline (speedup 1.0000x reference)
#include <cuda_runtime.h>
#include <cuda_bf16.h>
#include <stdint.h>
#include <math.h>

typedef __nv_bfloat16 bf16;

constexpr long OUT_ELEMS = 4194304L;   // B*S*D

// ---------------- scratch: device globals (no allocation) ----------------
__device__ __align__(256) bf16 g_xq_hi[4194304], g_xq_lo[4194304];
__device__ __align__(256) bf16 g_xk_hi[4194304], g_xk_lo[4194304];
__device__ __align__(256) bf16 g_xv_hi[4194304], g_xv_lo[4194304];
__device__ __align__(256) bf16 g_wq_hi[1048576], g_wq_lo[1048576];
__device__ __align__(256) bf16 g_wk_hi[1048576], g_wk_lo[1048576];
__device__ __align__(256) bf16 g_wv_hi[1048576], g_wv_lo[1048576];
__device__ __align__(256) bf16 g_wd_hi[1048576], g_wd_lo[1048576];
__device__ __align__(256) bf16 g_qp_hi[4194304], g_qp_lo[4194304];  // [bh][s][64]
__device__ __align__(256) bf16 g_kp_hi[4194304], g_kp_lo[4194304];
__device__ __align__(256) bf16 g_vp_hi[4194304], g_vp_lo[4194304];
__device__ __align__(256) bf16 g_ah[4194304], g_al[4194304];        // attn hi/lo [m][1024]
__device__ __align__(256) float g_part[2097152];                    // [bh][q][16][2]
__device__ __align__(256) float g_stats[131072];                    // [bh*2048+q][2] = M, invS

// ---------------- helpers ----------------
__device__ __forceinline__ uint32_t smem_u32(const void* p) {
    uint32_t a;
    asm("{ .reg .u64 t; cvta.to.shared.u64 t, %1; cvt.u32.u64 %0, t; }" : "=r"(a) : "l"(p));
    return a;
}
__device__ __forceinline__ void cpa16(uint32_t d, const void* g) {
    asm volatile("cp.async.cg.shared.global [%0], [%1], 16;" :: "r"(d), "l"(g));
}
#define CP_COMMIT() asm volatile("cp.async.commit_group;" ::: "memory")
#define CP_WAIT0()  asm volatile("cp.async.wait_group 0;" ::: "memory")
#define CP_WAIT1()  asm volatile("cp.async.wait_group 1;" ::: "memory")

__device__ __forceinline__ void ldm_x4(uint32_t& r0, uint32_t& r1, uint32_t& r2, uint32_t& r3, uint32_t a) {
    asm volatile("ldmatrix.sync.aligned.m8n8.x4.shared.b16 {%0,%1,%2,%3}, [%4];"
                 : "=r"(r0), "=r"(r1), "=r"(r2), "=r"(r3) : "r"(a));
}
__device__ __forceinline__ void ldm_x4t(uint32_t& r0, uint32_t& r1, uint32_t& r2, uint32_t& r3, uint32_t a) {
    asm volatile("ldmatrix.sync.aligned.m8n8.x4.trans.shared.b16 {%0,%1,%2,%3}, [%4];"
                 : "=r"(r0), "=r"(r1), "=r"(r2), "=r"(r3) : "r"(a));
}
__device__ __forceinline__ void mma16816(float* c, const uint32_t* a, const uint32_t* b) {
    asm volatile(
        "mma.sync.aligned.m16n8k16.row.col.f32.bf16.bf16.f32 "
        "{%0,%1,%2,%3}, {%4,%5,%6,%7}, {%8,%9}, {%0,%1,%2,%3};"
        : "+f"(c[0]), "+f"(c[1]), "+f"(c[2]), "+f"(c[3])
        : "r"(a[0]), "r"(a[1]), "r"(a[2]), "r"(a[3]), "r"(b[0]), "r"(b[1]));
}

__device__ __forceinline__ uint32_t pack2(bf16 a, bf16 b) {
    return (uint32_t)__bfloat16_as_ushort(a) | ((uint32_t)__bfloat16_as_ushort(b) << 16);
}
__device__ __forceinline__ void split1(float v, bf16& h, bf16& l) {
    h = __float2bfloat16_rn(v);
    l = __float2bfloat16_rn(v - __bfloat162float(h));
}

// --------------- warp-tile GEMM core (3-term compensated) ---------------
template<int MT, int NT, int NK, bool TRB>
__device__ __forceinline__ void gemm_pass(float (&acc)[MT][NT][4],
        uint32_t ab, uint32_t bb, int astr, int bstr, int lane)
{
    const int a_row = (lane & 7) + ((lane >> 3) & 1) * 8;
    const int a_k16 = (lane >> 4) * 16;
    const int b_row = (lane & 7) + (lane >> 4) * 8;
    const int b_k16 = ((lane >> 3) & 1) * 16;
    const int bt_row = (lane & 7) + ((lane >> 3) & 1) * 8;
    const int bt_col = (lane >> 4) * 8;
#pragma unroll
    for (int ks = 0; ks < NK; ks++) {
        uint32_t af[MT][4];
#pragma unroll
        for (int mt = 0; mt < MT; mt++)
            ldm_x4(af[mt][0], af[mt][1], af[mt][2], af[mt][3],
                   ab + (mt * 16 + a_row) * astr + ks * 32 + a_k16);
        uint32_t bfr[NT][2];
#pragma unroll
        for (int np = 0; np < NT / 2; np++) {
            uint32_t r0, r1, r2, r3;
            if (TRB)
                ldm_x4t(r0, r1, r2, r3, bb + (ks * 16 + bt_row) * bstr + (np * 16 + bt_col) * 2);
            else
                ldm_x4(r0, r1, r2, r3, bb + (np * 16 + b_row) * bstr + ks * 32 + b_k16);
            bfr[2*np][0] = r0; bfr[2*np][1] = r1;
            bfr[2*np+1][0] = r2; bfr[2*np+1][1] = r3;
        }
#pragma unroll
        for (int mt = 0; mt < MT; mt++)
#pragma unroll
            for (int nt = 0; nt < NT; nt++)
                mma16816(acc[mt][nt], af[mt], bfr[nt]);
    }
}

template<int MT, int NT, int NK, bool TRB>
__device__ __forceinline__ void gemm3(float (&acc)[MT][NT][4],
        uint32_t ahi, uint32_t alo, uint32_t bhi, uint32_t blo,
        int astr, int bstr, int lane)
{
    gemm_pass<MT, NT, NK, TRB>(acc, ahi, bhi, astr, bstr, lane);
    gemm_pass<MT, NT, NK, TRB>(acc, ahi, blo, astr, bstr, lane);
    gemm_pass<MT, NT, NK, TRB>(acc, alo, bhi, astr, bstr, lane);
}

// ---------------- split: fp32 -> hi/lo bf16 ----------------
__global__ void split_kernel(const float* __restrict__ x, bf16* __restrict__ hi,
                             bf16* __restrict__ lo, int n4) {
    for (long i = blockIdx.x * blockDim.x + threadIdx.x; i < n4; i += (long)gridDim.x * blockDim.x) {
        float4 v = *(const float4*)(x + i * 4);
        bf16 h0, l0, h1, l1, h2, l2, h3, l3;
        split1(v.x, h0, l0); split1(v.y, h1, l1);
        split1(v.z, h2, l2); split1(v.w, h3, l3);
        *(uint2*)(hi + i * 4) = make_uint2(pack2(h0, h1), pack2(h2, h3));
        *(uint2*)(lo + i * 4) = make_uint2(pack2(l0, l1), pack2(l2, l3));
    }
}

// ---------------- QKV proj: 3 GEMMs in one launch (z selects) ----------------
struct ProjSet { const bf16 *Ah, *Al, *Bh, *Bl; const float* bias; bf16 *Ph, *Pl; };
struct QKVArgs { ProjSet p[3]; };

// Block 128x128, 8 warps (2x4), BK=32, double-buffered. Writes split-head hi/lo.
__global__ __launch_bounds__(256) void qkv_kernel(QKVArgs args)
{
    extern __shared__ char smem[];
    const uint32_t sb = smem_u32(smem);
    const ProjSet ps = args.p[blockIdx.z];
    const int tid = threadIdx.x, lane = tid & 31, wid = tid >> 5;
    const int warp_m = wid >> 2, warp_n = wid & 3;
    const long m0 = (long)blockIdx.y * 128, n0 = (long)blockIdx.x * 128;

    float acc[4][4][4];
#pragma unroll
    for (int i = 0; i < 4; i++)
#pragma unroll
        for (int j = 0; j < 4; j++)
#pragma unroll
            for (int k = 0; k < 4; k++) acc[i][j][k] = 0.f;

    const bf16* srcs[4] = {ps.Ah + m0 * 1024, ps.Al + m0 * 1024,
                           ps.Bh + n0 * 1024, ps.Bl + n0 * 1024};
    auto load_chunk = [&](int buf, int kb) {
        uint32_t base = sb + buf * 40960;
#pragma unroll
        for (int t = 0; t < 4; t++) {
            const bf16* s = srcs[t] + kb;
            uint32_t db = base + t * 10240;
#pragma unroll
            for (int j = 0; j < 2; j++) {
                int idx = tid + j * 256;
                int r = idx >> 2, c = idx & 3;
                cpa16(db + r * 80 + c * 16, s + (long)r * 1024 + c * 8);
            }
        }
    };

    load_chunk(0, 0);
    CP_COMMIT();
    const int aoff = warp_m * 64 * 80, boff = warp_n * 32 * 80;
    for (int ch = 0; ch < 32; ch++) {
        if (ch < 31) { load_chunk((ch + 1) & 1, (ch + 1) * 32); CP_COMMIT(); CP_WAIT1(); }
        else CP_WAIT0();
        __syncthreads();
        uint32_t b = sb + (ch & 1) * 40960;
        gemm3<4, 4, 2, false>(acc, b + aoff, b + 10240 + aoff,
                              b + 20480 + boff, b + 30720 + boff, 80, 80, lane);
        __syncthreads();
    }

#pragma unroll
    for (int mt = 0; mt < 4; mt++) {
#pragma unroll
        for (int nt = 0; nt < 4; nt++) {
            int n = (int)n0 + warp_n * 32 + nt * 8 + (lane & 3) * 2;
            float bv0 = ps.bias[n], bv1 = ps.bias[n + 1];
            long r0 = m0 + warp_m * 64 + mt * 16 + (lane >> 2);
            long r1 = r0 + 8;
            float v00 = acc[mt][nt][0] + bv0, v01 = acc[mt][nt][1] + bv1;
            float v10 = acc[mt][nt][2] + bv0, v11 = acc[mt][nt][3] + bv1;
            int h = n >> 6, dh = n & 63;
            {
                int b_ = (int)(r0 >> 11), s_ = (int)(r0 & 2047);
                long a = ((long)(b_ * 16 + h) * 2048 + s_) * 64 + dh;
                bf16 hh0, ll0, hh1, ll1;
                split1(v00, hh0, ll0); split1(v01, hh1, ll1);
                *(uint32_t*)(ps.Ph + a) = pack2(hh0, hh1);
                *(uint32_t*)(ps.Pl + a) = pack2(ll0, ll1);
            }
            {
                int b_ = (int)(r1 >> 11), s_ = (int)(r1 & 2047);
                long a = ((long)(b_ * 16 + h) * 2048 + s_) * 64 + dh;
                bf16 hh0, ll0, hh1, ll1;
                split1(v10, hh0, ll0); split1(v11, hh1, ll1);
                *(uint32_t*)(ps.Ph + a) = pack2(hh0, hh1);
                *(uint32_t*)(ps.Pl + a) = pack2(ll0, ll1);
            }
        }
    }
}

// ---------------- dense: out = A @ W^T + b (fp32 out) ----------------
__global__ __launch_bounds__(256) void dense_kernel(
    const bf16* __restrict__ Ahi, const bf16* __restrict__ Alo,
    const bf16* __restrict__ Bhi, const bf16* __restrict__ Blo,
    const float* __restrict__ bias, float* __restrict__ outD)
{
    extern __shared__ char smem[];
    const uint32_t sb = smem_u32(smem);
    const int tid = threadIdx.x, lane = tid & 31, wid = tid >> 5;
    const int warp_m = wid >> 2, warp_n = wid & 3;
    const long m0 = (long)blockIdx.y * 128, n0 = (long)blockIdx.x * 128;

    float acc[4][4][4];
#pragma unroll
    for (int i = 0; i < 4; i++)
#pragma unroll
        for (int j = 0; j < 4; j++)
#pragma unroll
            for (int k = 0; k < 4; k++) acc[i][j][k] = 0.f;

    const bf16* srcs[4] = {Ahi + m0 * 1024, Alo + m0 * 1024,
                           Bhi + n0 * 1024, Blo + n0 * 1024};
    auto load_chunk = [&](int buf, int kb) {
        uint32_t base = sb + buf * 40960;
#pragma unroll
        for (int t = 0; t < 4; t++) {
            const bf16* s = srcs[t] + kb;
            uint32_t db = base + t * 10240;
#pragma unroll
            for (int j = 0; j < 2; j++) {
                int idx = tid + j * 256;
                int r = idx >> 2, c = idx & 3;
                cpa16(db + r * 80 + c * 16, s + (long)r * 1024 + c * 8);
            }
        }
    };

    load_chunk(0, 0);
    CP_COMMIT();
    const int aoff = warp_m * 64 * 80, boff = warp_n * 32 * 80;
    for (int ch = 0; ch < 32; ch++) {
        if (ch < 31) { load_chunk((ch + 1) & 1, (ch + 1) * 32); CP_COMMIT(); CP_WAIT1(); }
        else CP_WAIT0();
        __syncthreads();
        uint32_t b = sb + (ch & 1) * 40960;
        gemm3<4, 4, 2, false>(acc, b + aoff, b + 10240 + aoff,
                              b + 20480 + boff, b + 30720 + boff, 80, 80, lane);
        __syncthreads();
    }

#pragma unroll
    for (int mt = 0; mt < 4; mt++) {
#pragma unroll
        for (int nt = 0; nt < 4; nt++) {
            int n = (int)n0 + warp_n * 32 + nt * 8 + (lane & 3) * 2;
            float bv0 = bias[n], bv1 = bias[n + 1];
            long r0 = m0 + warp_m * 64 + mt * 16 + (lane >> 2);
            *(float2*)(outD + r0 * 1024 + n) =
                make_float2(acc[mt][nt][0] + bv0, acc[mt][nt][1] + bv1);
            *(float2*)(outD + (r0 + 8) * 1024 + n) =
                make_float2(acc[mt][nt][2] + bv0, acc[mt][nt][3] + bv1);
        }
    }
}

// ---------------- scores: masked scaled Q.K + per-tile softmax partials ------
__global__ __launch_bounds__(256) void scores_kernel(
    const bf16* __restrict__ Qhi, const bf16* __restrict__ Qlo,
    const bf16* __restrict__ Khi, const bf16* __restrict__ Klo,
    const int* __restrict__ mask, float* __restrict__ Wt,
    float* __restrict__ part)
{
    extern __shared__ char smem[];
    const uint32_t sb = smem_u32(smem);
    const int tid = threadIdx.x, lane = tid & 31, wid = tid >> 5;
    const int warp_m = wid >> 2, warp_n = wid & 3;
    const int kt = blockIdx.x, qt = blockIdx.y, bh = blockIdx.z;
    const int b_ = bh >> 4;

    const bf16* srcs[4] = {
        Qhi + ((long)bh * 2048 + qt * 128) * 64,
        Qlo + ((long)bh * 2048 + qt * 128) * 64,
        Khi + ((long)bh * 2048 + kt * 128) * 64,
        Klo + ((long)bh * 2048 + kt * 128) * 64};
#pragma unroll
    for (int t = 0; t < 4; t++) {
        uint32_t db = sb + t * 18432;
#pragma unroll
        for (int j = 0; j < 4; j++) {
            int idx = tid + j * 256;
            int r = idx >> 3, c = idx & 7;
            cpa16(db + r * 144 + c * 16, srcs[t] + (long)r * 64 + c * 8);
        }
    }
    CP_COMMIT(); CP_WAIT0();
    __syncthreads();

    float acc[4][4][4];
#pragma unroll
    for (int i = 0; i < 4; i++)
#pragma unroll
        for (int j = 0; j < 4; j++)
#pragma unroll
            for (int k = 0; k < 4; k++) acc[i][j][k] = 0.f;

    const int aoff = warp_m * 64 * 144, boff = warp_n * 32 * 144;
    gemm3<4, 4, 4, false>(acc, sb + aoff, sb + 18432 + aoff,
                          sb + 36864 + boff, sb + 55296 + boff, 144, 144, lane);

    // -------- epilogue: mask + scale, store, per-warp softmax partials -------
    float* base = Wt + ((long)bh * 2048 + qt * 128) * 2048 + kt * 128;
#pragma unroll
    for (int mt = 0; mt < 4; mt++) {
#pragma unroll
        for (int nt = 0; nt < 4; nt++) {
            int r0 = warp_m * 64 + mt * 16 + (lane >> 2);
            int c = warp_n * 32 + nt * 8 + (lane & 3) * 2;
            const long q0 = (long)qt * 128 + r0;
            const long kk = (long)kt * 128 + c;
            int2 mk0 = *(const int2*)(mask + ((long)b_ * 2048 + q0) * 2048 + kk);
            int2 mk1 = *(const int2*)(mask + ((long)b_ * 2048 + q0 + 8) * 2048 + kk);
            float v00 = mk0.x ? acc[mt][nt][0] * 0.125f : -1e30f;
            float v01 = mk0.y ? acc[mt][nt][1] * 0.125f : -1e30f;
            float v10 = mk1.x ? acc[mt][nt][2] * 0.125f : -1e30f;
            float v11 = mk1.y ? acc[mt][nt][3] * 0.125f : -1e30f;
            acc[mt][nt][0] = v00; acc[mt][nt][1] = v01;
            acc[mt][nt][2] = v10; acc[mt][nt][3] = v11;
            *(float2*)(base + (long)r0 * 2048 + c) = make_float2(v00, v01);
            *(float2*)(base + (long)(r0 + 8) * 2048 + c) = make_float2(v10, v11);
        }
    }

    __syncthreads();   // tiles no longer needed; reuse smem for stats
    float* smm = (float*)smem;            // [128][4]
    float* sms = (float*)(smem + 2048);   // [128][4]

#pragma unroll
    for (int mt = 0; mt < 4; mt++) {
#pragma unroll
        for (int hf = 0; hf < 2; hf++) {
            float m = -1e30f;
#pragma unroll
            for (int nt = 0; nt < 4; nt++)
                m = fmaxf(m, fmaxf(acc[mt][nt][hf*2], acc[mt][nt][hf*2+1]));
            m = fmaxf(m, __shfl_xor_sync(0xffffffffu, m, 1));
            m = fmaxf(m, __shfl_xor_sync(0xffffffffu, m, 2));
            float s = 0.f;
#pragma unroll
            for (int nt = 0; nt < 4; nt++)
                s += __expf(acc[mt][nt][hf*2] - m) + __expf(acc[mt][nt][hf*2+1] - m);
            s += __shfl_xor_sync(0xffffffffu, s, 1);
            s += __shfl_xor_sync(0xffffffffu, s, 2);
            if ((lane & 3) == 0) {
                int row = warp_m * 64 + mt * 16 + hf * 8 + (lane >> 2);
                smm[row * 4 + warp_n] = m;
                sms[row * 4 + warp_n] = s;
            }
        }
    }
    __syncthreads();
    if (tid < 128) {
        float M = smm[tid * 4];
        M = fmaxf(M, smm[tid * 4 + 1]);
        M = fmaxf(M, smm[tid * 4 + 2]);
        M = fmaxf(M, smm[tid * 4 + 3]);
        float Ssum = 0.f;
#pragma unroll
        for (int w = 0; w < 4; w++)
            Ssum += sms[tid * 4 + w] * __expf(smm[tid * 4 + w] - M);
        long idx = (((long)bh * 2048 + qt * 128 + tid) * 16 + kt) * 2;
        part[idx] = M; part[idx + 1] = Ssum;
    }
}

// ---------------- reduce partials -> (M, invS) per row ----------------
__global__ __launch_bounds__(256) void reduce_stats(
    const float* __restrict__ part, float* __restrict__ stats)
{
    long row = (long)blockIdx.x * 256 + threadIdx.x;   // 0..65535
    const float* p = part + row * 32;
    float M = -1e30f;
#pragma unroll
    for (int t = 0; t < 16; t++) M = fmaxf(M, p[t * 2]);
    float Ssum = 0.f;
#pragma unroll
    for (int t = 0; t < 16; t++) Ssum += p[t * 2 + 1] * __expf(p[t * 2] - M);
    stats[row * 2] = M;
    stats[row * 2 + 1] = 1.f / Ssum;
}

// ---------------- PV: exp + normalize inline, write weights + attn hi/lo ----
__global__ __launch_bounds__(256) void pv_kernel(
    float* __restrict__ Wt, const bf16* __restrict__ Vhi,
    const bf16* __restrict__ Vlo, const float* __restrict__ stats,
    bf16* __restrict__ Oh, bf16* __restrict__ Ol)
{
    extern __shared__ char smem[];
    __shared__ float st[128][2];
    const uint32_t sb = smem_u32(smem);
    const int tid = threadIdx.x, lane = tid & 31, wid = tid >> 5;
    const int warp_m = wid >> 1, warp_n = wid & 1;
    const int qt = blockIdx.x, bh = blockIdx.y;
    const uint32_t RAW0 = 0, RAW1 = 18432, VH0 = 36864, VH1 = 41472,
                   VL0 = 46080, VL1 = 50688, WH = 55296, WL = 65536;

    if (tid < 128) {
        long row = (long)bh * 2048 + qt * 128 + tid;
        st[tid][0] = stats[row * 2];
        st[tid][1] = stats[row * 2 + 1];
    }

    float* wrow = Wt + ((long)bh * 2048 + qt * 128) * 2048;
    const bf16* vhsrc = Vhi + (long)bh * 2048 * 64;
    const bf16* vlsrc = Vlo + (long)bh * 2048 * 64;

    auto load_chunk = [&](int buf, int ch) {
        uint32_t raw = sb + (buf ? RAW1 : RAW0);
        uint32_t vh = sb + (buf ? VH1 : VH0);
        uint32_t vl = sb + (buf ? VL1 : VL0);
        const float* wp = wrow + ch * 32;
#pragma unroll
        for (int j = 0; j < 4; j++) {
            int idx = tid + j * 256;
            int r = idx >> 3, c = idx & 7;
            cpa16(raw + r * 144 + c * 16, wp + (long)r * 2048 + c * 4);
        }
        {
            int r = tid >> 3, c = tid & 7;
            cpa16(vh + r * 144 + c * 16, vhsrc + (long)(ch * 32 + r) * 64 + c * 8);
            cpa16(vl + r * 144 + c * 16, vlsrc + (long)(ch * 32 + r) * 64 + c * 8);
        }
    };

    float acc[2][4][4];
#pragma unroll
    for (int i = 0; i < 2; i++)
#pragma unroll
        for (int j = 0; j < 4; j++)
#pragma unroll
            for (int k = 0; k < 4; k++) acc[i][j][k] = 0.f;

    load_chunk(0, 0);
    CP_COMMIT();
    const int crow = tid >> 1, chalf = tid & 1;
    const int aoff = warp_m * 32 * 80, boff = warp_n * 32 * 2;
    __syncthreads();   // st[] visible
    const float M = st[crow][0], invS = st[crow][1];

    for (int ch = 0; ch < 64; ch++) {
        if (ch < 63) { load_chunk((ch + 1) & 1, ch + 1); CP_COMMIT(); CP_WAIT1(); }
        else CP_WAIT0();
        __syncthreads();
        // convert raw fp32 -> p = exp(x-M)*invS; write weights; split hi/lo
        {
            const char* rp = smem + (ch & 1 ? RAW1 : RAW0) + crow * 144 + chalf * 64;
            float* wout = wrow + (long)crow * 2048 + ch * 32 + chalf * 16;
            uint32_t uh[8], ul[8];
#pragma unroll
            for (int i = 0; i < 4; i++) {
                float4 v = *(const float4*)(rp + i * 16);
                v.x = __expf(v.x - M) * invS;
                v.y = __expf(v.y - M) * invS;
                v.z = __expf(v.z - M) * invS;
                v.w = __expf(v.w - M) * invS;
                *(float4*)(wout + i * 4) = v;
                bf16 h0, l0, h1, l1;
                split1(v.x, h0, l0); split1(v.y, h1, l1);
                uh[i * 2] = pack2(h0, h1); ul[i * 2] = pack2(l0, l1);
                split1(v.z, h0, l0); split1(v.w, h1, l1);
                uh[i * 2 + 1] = pack2(h0, h1); ul[i * 2 + 1] = pack2(l0, l1);
            }
            char* wh = smem + WH + crow * 80 + chalf * 32;
            char* wl = smem + WL + crow * 80 + chalf * 32;
            *(uint4*)wh = make_uint4(uh[0], uh[1], uh[2], uh[3]);
            *(uint4*)(wh + 16) = make_uint4(uh[4], uh[5], uh[6], uh[7]);
            *(uint4*)wl = make_uint4(ul[0], ul[1], ul[2], ul[3]);
            *(uint4*)(wl + 16) = make_uint4(ul[4], ul[5], ul[6], ul[7]);
        }
        __syncthreads();
        uint32_t vh = sb + ((ch & 1) ? VH1 : VH0) + boff;
        uint32_t vl = sb + ((ch & 1) ? VL1 : VL0) + boff;
        gemm3<2, 4, 2, true>(acc, sb + WH + aoff, sb + WL + aoff, vh, vl, 80, 144, lane);
        __syncthreads();
    }

    const int b_ = bh >> 4, h = bh & 15;
#pragma unroll
    for (int mt = 0; mt < 2; mt++) {
#pragma unroll
        for (int nt = 0; nt < 4; nt++) {
            int s0 = qt * 128 + warp_m * 32 + mt * 16 + (lane >> 2);
            int dh = warp_n * 32 + nt * 8 + (lane & 3) * 2;
            long a0 = ((long)b_ * 2048 + s0) * 1024 + h * 64 + dh;
            long a1 = ((long)b_ * 2048 + s0 + 8) * 1024 + h * 64 + dh;
            bf16 hh0, ll0, hh1, ll1;
            split1(acc[mt][nt][0], hh0, ll0); split1(acc[mt][nt][1], hh1, ll1);
            *(uint32_t*)(Oh + a0) = pack2(hh0, hh1);
            *(uint32_t*)(Ol + a0) = pack2(ll0, ll1);
            split1(acc[mt][nt][2], hh0, ll0); split1(acc[mt][nt][3], hh1, ll1);
            *(uint32_t*)(Oh + a1) = pack2(hh0, hh1);
            *(uint32_t*)(Ol + a1) = pack2(ll0, ll1);
        }
    }
}

// ---------------- host launcher ----------------
extern "C" void kernel_launch(void* const* d_in, const int* in_sizes, int n_in,
                              void* d_out, int out_size)
{
    const float* q    = (const float*)d_in[0];
    const float* k    = (const float*)d_in[1];
    const float* v    = (const float*)d_in[2];
    const int*   mask = (const int*)d_in[3];
    const float* wq_w = (const float*)d_in[4];
    const float* wq_b = (const float*)d_in[5];
    const float* wk_w = (const float*)d_in[6];
    const float* wk_b = (const float*)d_in[7];
    const float* wv_w = (const float*)d_in[8];
    const float* wv_b = (const float*)d_in[9];
    const float* dw   = (const float*)d_in[10];
    const float* db   = (const float*)d_in[11];

    float* out = (float*)d_out;
    float* wts = out + OUT_ELEMS;

    bf16 *xqh, *xql, *xkh, *xkl, *xvh, *xvl;
    bf16 *wqh, *wql, *wkh, *wkl, *wvh, *wvl, *wdh, *wdl;
    bf16 *qph, *qpl, *kph, *kpl, *vph, *vpl, *ah, *al;
    float *part, *stats;
    cudaGetSymbolAddress((void**)&xqh, g_xq_hi); cudaGetSymbolAddress((void**)&xql, g_xq_lo);
    cudaGetSymbolAddress((void**)&xkh, g_xk_hi); cudaGetSymbolAddress((void**)&xkl, g_xk_lo);
    cudaGetSymbolAddress((void**)&xvh, g_xv_hi); cudaGetSymbolAddress((void**)&xvl, g_xv_lo);
    cudaGetSymbolAddress((void**)&wqh, g_wq_hi); cudaGetSymbolAddress((void**)&wql, g_wq_lo);
    cudaGetSymbolAddress((void**)&wkh, g_wk_hi); cudaGetSymbolAddress((void**)&wkl, g_wk_lo);
    cudaGetSymbolAddress((void**)&wvh, g_wv_hi); cudaGetSymbolAddress((void**)&wvl, g_wv_lo);
    cudaGetSymbolAddress((void**)&wdh, g_wd_hi); cudaGetSymbolAddress((void**)&wdl, g_wd_lo);
    cudaGetSymbolAddress((void**)&qph, g_qp_hi); cudaGetSymbolAddress((void**)&qpl, g_qp_lo);
    cudaGetSymbolAddress((void**)&kph, g_kp_hi); cudaGetSymbolAddress((void**)&kpl, g_kp_lo);
    cudaGetSymbolAddress((void**)&vph, g_vp_hi); cudaGetSymbolAddress((void**)&vpl, g_vp_lo);
    cudaGetSymbolAddress((void**)&ah,  g_ah);    cudaGetSymbolAddress((void**)&al,  g_al);
    cudaGetSymbolAddress((void**)&part, g_part); cudaGetSymbolAddress((void**)&stats, g_stats);

    cudaFuncSetAttribute(qkv_kernel,    cudaFuncAttributeMaxDynamicSharedMemorySize, 81920);
    cudaFuncSetAttribute(dense_kernel,  cudaFuncAttributeMaxDynamicSharedMemorySize, 81920);
    cudaFuncSetAttribute(scores_kernel, cudaFuncAttributeMaxDynamicSharedMemorySize, 73728);
    cudaFuncSetAttribute(pv_kernel,     cudaFuncAttributeMaxDynamicSharedMemorySize, 75776);

    split_kernel<<<4096, 256>>>(q, xqh, xql, 1048576);
    split_kernel<<<4096, 256>>>(k, xkh, xkl, 1048576);
    split_kernel<<<4096, 256>>>(v, xvh, xvl, 1048576);
    split_kernel<<<1024, 256>>>(wq_w, wqh, wql, 262144);
    split_kernel<<<1024, 256>>>(wk_w, wkh, wkl, 262144);
    split_kernel<<<1024, 256>>>(wv_w, wvh, wvl, 262144);
    split_kernel<<<1024, 256>>>(dw,   wdh, wdl, 262144);

    QKVArgs qa;
    qa.p[0] = {xqh, xql, wqh, wql, wq_b, qph, qpl};
    qa.p[1] = {xkh, xkl, wkh, wkl, wk_b, kph, kpl};
    qa.p[2] = {xvh, xvl, wvh, wvl, wv_b, vph, vpl};
    qkv_kernel<<<dim3(8, 32, 3), 256, 81920>>>(qa);

    scores_kernel<<<dim3(16, 16, 32), 256, 73728>>>(qph, qpl, kph, kpl, mask, wts, part);
    reduce_stats<<<256, 256>>>(part, stats);
    pv_kernel<<<dim3(16, 32), 256, 75776>>>(wts, vph, vpl, stats, ah, al);

    dense_kernel<<<dim3(8, 32), 256, 81920>>>(ah, al, wdh, wdl, db, out);
}

// round 6
// speedup vs baseline: 1.5984x; 1.5984x over previous
#include <cuda_runtime.h>
#include <cuda_bf16.h>
#include <stdint.h>
#include <math.h>

typedef __nv_bfloat16 bf16;

constexpr long OUT_ELEMS = 4194304L;   // B*S*D

// ---------------- scratch: device globals (no allocation) ----------------
__device__ __align__(256) bf16 g_xq_hi[4194304], g_xq_lo[4194304];
__device__ __align__(256) bf16 g_xk_hi[4194304], g_xk_lo[4194304];
__device__ __align__(256) bf16 g_xv_hi[4194304], g_xv_lo[4194304];
__device__ __align__(256) bf16 g_wq_hi[1048576], g_wq_lo[1048576];
__device__ __align__(256) bf16 g_wk_hi[1048576], g_wk_lo[1048576];
__device__ __align__(256) bf16 g_wv_hi[1048576], g_wv_lo[1048576];
__device__ __align__(256) bf16 g_wd_hi[1048576], g_wd_lo[1048576];
__device__ __align__(256) bf16 g_qp_hi[4194304], g_qp_lo[4194304];  // [bh][s][64]
__device__ __align__(256) bf16 g_kp_hi[4194304], g_kp_lo[4194304];
__device__ __align__(256) bf16 g_vp_hi[4194304], g_vp_lo[4194304];
__device__ __align__(256) bf16 g_ah[4194304], g_al[4194304];        // attn hi/lo [m][1024]

// ---------------- helpers ----------------
__device__ __forceinline__ uint32_t smem_u32(const void* p) {
    uint32_t a;
    asm("{ .reg .u64 t; cvta.to.shared.u64 t, %1; cvt.u32.u64 %0, t; }" : "=r"(a) : "l"(p));
    return a;
}
__device__ __forceinline__ void cpa16(uint32_t d, const void* g) {
    asm volatile("cp.async.cg.shared.global [%0], [%1], 16;" :: "r"(d), "l"(g));
}
#define CP_COMMIT() asm volatile("cp.async.commit_group;" ::: "memory")
#define CP_WAIT0()  asm volatile("cp.async.wait_group 0;" ::: "memory")
#define CP_WAIT1()  asm volatile("cp.async.wait_group 1;" ::: "memory")

__device__ __forceinline__ void ldm_x4(uint32_t& r0, uint32_t& r1, uint32_t& r2, uint32_t& r3, uint32_t a) {
    asm volatile("ldmatrix.sync.aligned.m8n8.x4.shared.b16 {%0,%1,%2,%3}, [%4];"
                 : "=r"(r0), "=r"(r1), "=r"(r2), "=r"(r3) : "r"(a));
}
__device__ __forceinline__ void ldm_x4t(uint32_t& r0, uint32_t& r1, uint32_t& r2, uint32_t& r3, uint32_t a) {
    asm volatile("ldmatrix.sync.aligned.m8n8.x4.trans.shared.b16 {%0,%1,%2,%3}, [%4];"
                 : "=r"(r0), "=r"(r1), "=r"(r2), "=r"(r3) : "r"(a));
}
__device__ __forceinline__ void mma16816(float* c, const uint32_t* a, const uint32_t* b) {
    asm volatile(
        "mma.sync.aligned.m16n8k16.row.col.f32.bf16.bf16.f32 "
        "{%0,%1,%2,%3}, {%4,%5,%6,%7}, {%8,%9}, {%0,%1,%2,%3};"
        : "+f"(c[0]), "+f"(c[1]), "+f"(c[2]), "+f"(c[3])
        : "r"(a[0]), "r"(a[1]), "r"(a[2]), "r"(a[3]), "r"(b[0]), "r"(b[1]));
}

__device__ __forceinline__ uint32_t pack2(bf16 a, bf16 b) {
    return (uint32_t)__bfloat16_as_ushort(a) | ((uint32_t)__bfloat16_as_ushort(b) << 16);
}
__device__ __forceinline__ void split1(float v, bf16& h, bf16& l) {
    h = __float2bfloat16_rn(v);
    l = __float2bfloat16_rn(v - __bfloat162float(h));
}

// --------------- warp-tile GEMM core (3-term compensated) ---------------
template<int MT, int NT, int NK, bool TRB>
__device__ __forceinline__ void gemm_pass(float (&acc)[MT][NT][4],
        uint32_t ab, uint32_t bb, int astr, int bstr, int lane)
{
    const int a_row = (lane & 7) + ((lane >> 3) & 1) * 8;
    const int a_k16 = (lane >> 4) * 16;
    const int b_row = (lane & 7) + (lane >> 4) * 8;
    const int b_k16 = ((lane >> 3) & 1) * 16;
    const int bt_row = (lane & 7) + ((lane >> 3) & 1) * 8;
    const int bt_col = (lane >> 4) * 8;
#pragma unroll
    for (int ks = 0; ks < NK; ks++) {
        uint32_t af[MT][4];
#pragma unroll
        for (int mt = 0; mt < MT; mt++)
            ldm_x4(af[mt][0], af[mt][1], af[mt][2], af[mt][3],
                   ab + (mt * 16 + a_row) * astr + ks * 32 + a_k16);
        uint32_t bfr[NT][2];
#pragma unroll
        for (int np = 0; np < NT / 2; np++) {
            uint32_t r0, r1, r2, r3;
            if (TRB)
                ldm_x4t(r0, r1, r2, r3, bb + (ks * 16 + bt_row) * bstr + (np * 16 + bt_col) * 2);
            else
                ldm_x4(r0, r1, r2, r3, bb + (np * 16 + b_row) * bstr + ks * 32 + b_k16);
            bfr[2*np][0] = r0; bfr[2*np][1] = r1;
            bfr[2*np+1][0] = r2; bfr[2*np+1][1] = r3;
        }
#pragma unroll
        for (int mt = 0; mt < MT; mt++)
#pragma unroll
            for (int nt = 0; nt < NT; nt++)
                mma16816(acc[mt][nt], af[mt], bfr[nt]);
    }
}

template<int MT, int NT, int NK, bool TRB>
__device__ __forceinline__ void gemm3(float (&acc)[MT][NT][4],
        uint32_t ahi, uint32_t alo, uint32_t bhi, uint32_t blo,
        int astr, int bstr, int lane)
{
    gemm_pass<MT, NT, NK, TRB>(acc, ahi, bhi, astr, bstr, lane);
    gemm_pass<MT, NT, NK, TRB>(acc, ahi, blo, astr, bstr, lane);
    gemm_pass<MT, NT, NK, TRB>(acc, alo, bhi, astr, bstr, lane);
}

// ---------------- splits: fp32 -> hi/lo bf16, z-indexed ----------------
struct SplitSet { const float* x; bf16 *hi, *lo; };
struct Split3Args { SplitSet s[3]; };
struct Split4Args { SplitSet s[4]; };

__global__ void split3_kernel(Split3Args args) {
    const SplitSet ss = args.s[blockIdx.z];
    for (long i = blockIdx.x * blockDim.x + threadIdx.x; i < 1048576; i += (long)gridDim.x * blockDim.x) {
        float4 v = *(const float4*)(ss.x + i * 4);
        bf16 h0, l0, h1, l1, h2, l2, h3, l3;
        split1(v.x, h0, l0); split1(v.y, h1, l1);
        split1(v.z, h2, l2); split1(v.w, h3, l3);
        *(uint2*)(ss.hi + i * 4) = make_uint2(pack2(h0, h1), pack2(h2, h3));
        *(uint2*)(ss.lo + i * 4) = make_uint2(pack2(l0, l1), pack2(l2, l3));
    }
}
__global__ void split4_kernel(Split4Args args) {
    const SplitSet ss = args.s[blockIdx.z];
    for (long i = blockIdx.x * blockDim.x + threadIdx.x; i < 262144; i += (long)gridDim.x * blockDim.x) {
        float4 v = *(const float4*)(ss.x + i * 4);
        bf16 h0, l0, h1, l1, h2, l2, h3, l3;
        split1(v.x, h0, l0); split1(v.y, h1, l1);
        split1(v.z, h2, l2); split1(v.w, h3, l3);
        *(uint2*)(ss.hi + i * 4) = make_uint2(pack2(h0, h1), pack2(h2, h3));
        *(uint2*)(ss.lo + i * 4) = make_uint2(pack2(l0, l1), pack2(l2, l3));
    }
}

// ---------------- QKV proj: 3 GEMMs in one launch (z selects) ----------------
struct ProjSet { const bf16 *Ah, *Al, *Bh, *Bl; const float* bias; bf16 *Ph, *Pl; };
struct QKVArgs { ProjSet p[3]; };

// Block 128x128, 8 warps (2x4), BK=32, double-buffered. Writes split-head hi/lo.
__global__ __launch_bounds__(256) void qkv_kernel(QKVArgs args)
{
    extern __shared__ char smem[];
    const uint32_t sb = smem_u32(smem);
    const ProjSet ps = args.p[blockIdx.z];
    const int tid = threadIdx.x, lane = tid & 31, wid = tid >> 5;
    const int warp_m = wid >> 2, warp_n = wid & 3;
    const long m0 = (long)blockIdx.y * 128, n0 = (long)blockIdx.x * 128;

    float acc[4][4][4];
#pragma unroll
    for (int i = 0; i < 4; i++)
#pragma unroll
        for (int j = 0; j < 4; j++)
#pragma unroll
            for (int k = 0; k < 4; k++) acc[i][j][k] = 0.f;

    const bf16* srcs[4] = {ps.Ah + m0 * 1024, ps.Al + m0 * 1024,
                           ps.Bh + n0 * 1024, ps.Bl + n0 * 1024};
    auto load_chunk = [&](int buf, int kb) {
        uint32_t base = sb + buf * 40960;
#pragma unroll
        for (int t = 0; t < 4; t++) {
            const bf16* s = srcs[t] + kb;
            uint32_t db = base + t * 10240;
#pragma unroll
            for (int j = 0; j < 2; j++) {
                int idx = tid + j * 256;
                int r = idx >> 2, c = idx & 3;
                cpa16(db + r * 80 + c * 16, s + (long)r * 1024 + c * 8);
            }
        }
    };

    load_chunk(0, 0);
    CP_COMMIT();
    const int aoff = warp_m * 64 * 80, boff = warp_n * 32 * 80;
    for (int ch = 0; ch < 32; ch++) {
        if (ch < 31) { load_chunk((ch + 1) & 1, (ch + 1) * 32); CP_COMMIT(); CP_WAIT1(); }
        else CP_WAIT0();
        __syncthreads();
        uint32_t b = sb + (ch & 1) * 40960;
        gemm3<4, 4, 2, false>(acc, b + aoff, b + 10240 + aoff,
                              b + 20480 + boff, b + 30720 + boff, 80, 80, lane);
        __syncthreads();
    }

#pragma unroll
    for (int mt = 0; mt < 4; mt++) {
#pragma unroll
        for (int nt = 0; nt < 4; nt++) {
            int n = (int)n0 + warp_n * 32 + nt * 8 + (lane & 3) * 2;
            float bv0 = ps.bias[n], bv1 = ps.bias[n + 1];
            long r0 = m0 + warp_m * 64 + mt * 16 + (lane >> 2);
            long r1 = r0 + 8;
            float v00 = acc[mt][nt][0] + bv0, v01 = acc[mt][nt][1] + bv1;
            float v10 = acc[mt][nt][2] + bv0, v11 = acc[mt][nt][3] + bv1;
            int h = n >> 6, dh = n & 63;
            {
                int b_ = (int)(r0 >> 11), s_ = (int)(r0 & 2047);
                long a = ((long)(b_ * 16 + h) * 2048 + s_) * 64 + dh;
                bf16 hh0, ll0, hh1, ll1;
                split1(v00, hh0, ll0); split1(v01, hh1, ll1);
                *(uint32_t*)(ps.Ph + a) = pack2(hh0, hh1);
                *(uint32_t*)(ps.Pl + a) = pack2(ll0, ll1);
            }
            {
                int b_ = (int)(r1 >> 11), s_ = (int)(r1 & 2047);
                long a = ((long)(b_ * 16 + h) * 2048 + s_) * 64 + dh;
                bf16 hh0, ll0, hh1, ll1;
                split1(v10, hh0, ll0); split1(v11, hh1, ll1);
                *(uint32_t*)(ps.Ph + a) = pack2(hh0, hh1);
                *(uint32_t*)(ps.Pl + a) = pack2(ll0, ll1);
            }
        }
    }
}

// ---------------- scores: Wt[bh,q,k] = 0.125 * Q . K (raw, no mask) ----------
__global__ __launch_bounds__(256) void scores_kernel(
    const bf16* __restrict__ Qhi, const bf16* __restrict__ Qlo,
    const bf16* __restrict__ Khi, const bf16* __restrict__ Klo,
    float* __restrict__ Wt)
{
    extern __shared__ char smem[];
    const uint32_t sb = smem_u32(smem);
    const int tid = threadIdx.x, lane = tid & 31, wid = tid >> 5;
    const int warp_m = wid >> 2, warp_n = wid & 3;
    const int kt = blockIdx.x, qt = blockIdx.y, bh = blockIdx.z;

    const bf16* srcs[4] = {
        Qhi + ((long)bh * 2048 + qt * 128) * 64,
        Qlo + ((long)bh * 2048 + qt * 128) * 64,
        Khi + ((long)bh * 2048 + kt * 128) * 64,
        Klo + ((long)bh * 2048 + kt * 128) * 64};
#pragma unroll
    for (int t = 0; t < 4; t++) {
        uint32_t db = sb + t * 18432;
#pragma unroll
        for (int j = 0; j < 4; j++) {
            int idx = tid + j * 256;
            int r = idx >> 3, c = idx & 7;
            cpa16(db + r * 144 + c * 16, srcs[t] + (long)r * 64 + c * 8);
        }
    }
    CP_COMMIT(); CP_WAIT0();
    __syncthreads();

    float acc[4][4][4];
#pragma unroll
    for (int i = 0; i < 4; i++)
#pragma unroll
        for (int j = 0; j < 4; j++)
#pragma unroll
            for (int k = 0; k < 4; k++) acc[i][j][k] = 0.f;

    const int aoff = warp_m * 64 * 144, boff = warp_n * 32 * 144;
    gemm3<4, 4, 4, false>(acc, sb + aoff, sb + 18432 + aoff,
                          sb + 36864 + boff, sb + 55296 + boff, 144, 144, lane);

    float* base = Wt + ((long)bh * 2048 + qt * 128) * 2048 + kt * 128;
#pragma unroll
    for (int mt = 0; mt < 4; mt++) {
#pragma unroll
        for (int nt = 0; nt < 4; nt++) {
            int r0 = warp_m * 64 + mt * 16 + (lane >> 2);
            int c = warp_n * 32 + nt * 8 + (lane & 3) * 2;
            *(float2*)(base + (long)r0 * 2048 + c) =
                make_float2(acc[mt][nt][0] * 0.125f, acc[mt][nt][1] * 0.125f);
            *(float2*)(base + (long)(r0 + 8) * 2048 + c) =
                make_float2(acc[mt][nt][2] * 0.125f, acc[mt][nt][3] * 0.125f);
        }
    }
}

// ---------------- softmax (in place, mask at read; vectorized) ----------------
__global__ __launch_bounds__(256) void softmax_kernel(
    float* __restrict__ Wt, const int* __restrict__ mask)
{
    const long row = blockIdx.x;
    const int bh = (int)(row >> 11), q = (int)(row & 2047), b_ = bh >> 4;
    float* p = Wt + row * 2048L;
    const int* mrow = mask + ((long)b_ * 2048 + q) * 2048;
    const int tid = threadIdx.x;

    float4 v[2];
    float mx = -INFINITY;
#pragma unroll
    for (int t = 0; t < 2; t++) {
        const int idx = (t * 256 + tid) * 4;
        v[t] = *(const float4*)(p + idx);
        int4 m4 = *(const int4*)(mrow + idx);
        if (m4.x == 0) v[t].x = -INFINITY;
        if (m4.y == 0) v[t].y = -INFINITY;
        if (m4.z == 0) v[t].z = -INFINITY;
        if (m4.w == 0) v[t].w = -INFINITY;
        mx = fmaxf(mx, fmaxf(fmaxf(v[t].x, v[t].y), fmaxf(v[t].z, v[t].w)));
    }

    __shared__ float red[8];
#pragma unroll
    for (int o = 16; o > 0; o >>= 1) mx = fmaxf(mx, __shfl_xor_sync(0xffffffffu, mx, o));
    if ((tid & 31) == 0) red[tid >> 5] = mx;
    __syncthreads();
    mx = -INFINITY;
#pragma unroll
    for (int i = 0; i < 8; i++) mx = fmaxf(mx, red[i]);
    __syncthreads();
    float s = 0.f;
#pragma unroll
    for (int t = 0; t < 2; t++) {
        v[t].x = __expf(v[t].x - mx); v[t].y = __expf(v[t].y - mx);
        v[t].z = __expf(v[t].z - mx); v[t].w = __expf(v[t].w - mx);
        s += (v[t].x + v[t].y) + (v[t].z + v[t].w);
    }
#pragma unroll
    for (int o = 16; o > 0; o >>= 1) s += __shfl_xor_sync(0xffffffffu, s, o);
    if ((tid & 31) == 0) red[tid >> 5] = s;
    __syncthreads();
    s = 0.f;
#pragma unroll
    for (int i = 0; i < 8; i++) s += red[i];
    const float inv = 1.f / s;
#pragma unroll
    for (int t = 0; t < 2; t++) {
        const int idx = (t * 256 + tid) * 4;
        *(float4*)(p + idx) = make_float4(v[t].x * inv, v[t].y * inv,
                                          v[t].z * inv, v[t].w * inv);
    }
}

// ---------------- PV: O = W @ V (normalized W fp32 -> split in-kernel) -------
// Writes attn directly as bf16 hi/lo [m][1024].
__global__ __launch_bounds__(256) void pv_kernel(
    const float* __restrict__ Wt, const bf16* __restrict__ Vhi,
    const bf16* __restrict__ Vlo, bf16* __restrict__ Oh, bf16* __restrict__ Ol)
{
    extern __shared__ char smem[];
    const uint32_t sb = smem_u32(smem);
    const int tid = threadIdx.x, lane = tid & 31, wid = tid >> 5;
    const int warp_m = wid >> 1, warp_n = wid & 1;
    const int qt = blockIdx.x, bh = blockIdx.y;
    const uint32_t RAW0 = 0, RAW1 = 18432, VH0 = 36864, VH1 = 41472,
                   VL0 = 46080, VL1 = 50688, WH = 55296, WL = 65536;

    const float* wsrc = Wt + ((long)bh * 2048 + qt * 128) * 2048;
    const bf16* vhsrc = Vhi + (long)bh * 2048 * 64;
    const bf16* vlsrc = Vlo + (long)bh * 2048 * 64;

    auto load_chunk = [&](int buf, int ch) {
        uint32_t raw = sb + (buf ? RAW1 : RAW0);
        uint32_t vh = sb + (buf ? VH1 : VH0);
        uint32_t vl = sb + (buf ? VL1 : VL0);
        const float* wp = wsrc + ch * 32;
#pragma unroll
        for (int j = 0; j < 4; j++) {
            int idx = tid + j * 256;
            int r = idx >> 3, c = idx & 7;
            cpa16(raw + r * 144 + c * 16, wp + (long)r * 2048 + c * 4);
        }
        {
            int r = tid >> 3, c = tid & 7;
            cpa16(vh + r * 144 + c * 16, vhsrc + (long)(ch * 32 + r) * 64 + c * 8);
            cpa16(vl + r * 144 + c * 16, vlsrc + (long)(ch * 32 + r) * 64 + c * 8);
        }
    };

    float acc[2][4][4];
#pragma unroll
    for (int i = 0; i < 2; i++)
#pragma unroll
        for (int j = 0; j < 4; j++)
#pragma unroll
            for (int k = 0; k < 4; k++) acc[i][j][k] = 0.f;

    load_chunk(0, 0);
    CP_COMMIT();
    const int crow = tid >> 1, chalf = tid & 1;
    const int aoff = warp_m * 32 * 80, boff = warp_n * 32 * 2;
    for (int ch = 0; ch < 64; ch++) {
        if (ch < 63) { load_chunk((ch + 1) & 1, ch + 1); CP_COMMIT(); CP_WAIT1(); }
        else CP_WAIT0();
        __syncthreads();
        // convert raw fp32 -> WH/WL padded bf16
        {
            const char* rp = smem + (ch & 1 ? RAW1 : RAW0) + crow * 144 + chalf * 64;
            uint32_t uh[8], ul[8];
#pragma unroll
            for (int i = 0; i < 4; i++) {
                float4 v = *(const float4*)(rp + i * 16);
                bf16 h0, l0, h1, l1;
                split1(v.x, h0, l0); split1(v.y, h1, l1);
                uh[i * 2] = pack2(h0, h1); ul[i * 2] = pack2(l0, l1);
                split1(v.z, h0, l0); split1(v.w, h1, l1);
                uh[i * 2 + 1] = pack2(h0, h1); ul[i * 2 + 1] = pack2(l0, l1);
            }
            char* wh = smem + WH + crow * 80 + chalf * 32;
            char* wl = smem + WL + crow * 80 + chalf * 32;
            *(uint4*)wh = make_uint4(uh[0], uh[1], uh[2], uh[3]);
            *(uint4*)(wh + 16) = make_uint4(uh[4], uh[5], uh[6], uh[7]);
            *(uint4*)wl = make_uint4(ul[0], ul[1], ul[2], ul[3]);
            *(uint4*)(wl + 16) = make_uint4(ul[4], ul[5], ul[6], ul[7]);
        }
        __syncthreads();
        uint32_t vh = sb + ((ch & 1) ? VH1 : VH0) + boff;
        uint32_t vl = sb + ((ch & 1) ? VL1 : VL0) + boff;
        gemm3<2, 4, 2, true>(acc, sb + WH + aoff, sb + WL + aoff, vh, vl, 80, 144, lane);
        __syncthreads();
    }

    const int b_ = bh >> 4, h = bh & 15;
#pragma unroll
    for (int mt = 0; mt < 2; mt++) {
#pragma unroll
        for (int nt = 0; nt < 4; nt++) {
            int s0 = qt * 128 + warp_m * 32 + mt * 16 + (lane >> 2);
            int dh = warp_n * 32 + nt * 8 + (lane & 3) * 2;
            long a0 = ((long)b_ * 2048 + s0) * 1024 + h * 64 + dh;
            long a1 = ((long)b_ * 2048 + s0 + 8) * 1024 + h * 64 + dh;
            bf16 hh0, ll0, hh1, ll1;
            split1(acc[mt][nt][0], hh0, ll0); split1(acc[mt][nt][1], hh1, ll1);
            *(uint32_t*)(Oh + a0) = pack2(hh0, hh1);
            *(uint32_t*)(Ol + a0) = pack2(ll0, ll1);
            split1(acc[mt][nt][2], hh0, ll0); split1(acc[mt][nt][3], hh1, ll1);
            *(uint32_t*)(Oh + a1) = pack2(hh0, hh1);
            *(uint32_t*)(Ol + a1) = pack2(ll0, ll1);
        }
    }
}

// ---------------- dense: out = A @ W^T + b (fp32 out) ----------------
__global__ __launch_bounds__(256) void dense_kernel(
    const bf16* __restrict__ Ahi, const bf16* __restrict__ Alo,
    const bf16* __restrict__ Bhi, const bf16* __restrict__ Blo,
    const float* __restrict__ bias, float* __restrict__ outD)
{
    extern __shared__ char smem[];
    const uint32_t sb = smem_u32(smem);
    const int tid = threadIdx.x, lane = tid & 31, wid = tid >> 5;
    const int warp_m = wid >> 2, warp_n = wid & 3;
    const long m0 = (long)blockIdx.y * 128, n0 = (long)blockIdx.x * 128;

    float acc[4][4][4];
#pragma unroll
    for (int i = 0; i < 4; i++)
#pragma unroll
        for (int j = 0; j < 4; j++)
#pragma unroll
            for (int k = 0; k < 4; k++) acc[i][j][k] = 0.f;

    const bf16* srcs[4] = {Ahi + m0 * 1024, Alo + m0 * 1024,
                           Bhi + n0 * 1024, Blo + n0 * 1024};
    auto load_chunk = [&](int buf, int kb) {
        uint32_t base = sb + buf * 40960;
#pragma unroll
        for (int t = 0; t < 4; t++) {
            const bf16* s = srcs[t] + kb;
            uint32_t db = base + t * 10240;
#pragma unroll
            for (int j = 0; j < 2; j++) {
                int idx = tid + j * 256;
                int r = idx >> 2, c = idx & 3;
                cpa16(db + r * 80 + c * 16, s + (long)r * 1024 + c * 8);
            }
        }
    };

    load_chunk(0, 0);
    CP_COMMIT();
    const int aoff = warp_m * 64 * 80, boff = warp_n * 32 * 80;
    for (int ch = 0; ch < 32; ch++) {
        if (ch < 31) { load_chunk((ch + 1) & 1, (ch + 1) * 32); CP_COMMIT(); CP_WAIT1(); }
        else CP_WAIT0();
        __syncthreads();
        uint32_t b = sb + (ch & 1) * 40960;
        gemm3<4, 4, 2, false>(acc, b + aoff, b + 10240 + aoff,
                              b + 20480 + boff, b + 30720 + boff, 80, 80, lane);
        __syncthreads();
    }

#pragma unroll
    for (int mt = 0; mt < 4; mt++) {
#pragma unroll
        for (int nt = 0; nt < 4; nt++) {
            int n = (int)n0 + warp_n * 32 + nt * 8 + (lane & 3) * 2;
            float bv0 = bias[n], bv1 = bias[n + 1];
            long r0 = m0 + warp_m * 64 + mt * 16 + (lane >> 2);
            *(float2*)(outD + r0 * 1024 + n) =
                make_float2(acc[mt][nt][0] + bv0, acc[mt][nt][1] + bv1);
            *(float2*)(outD + (r0 + 8) * 1024 + n) =
                make_float2(acc[mt][nt][2] + bv0, acc[mt][nt][3] + bv1);
        }
    }
}

// ---------------- host launcher ----------------
extern "C" void kernel_launch(void* const* d_in, const int* in_sizes, int n_in,
                              void* d_out, int out_size)
{
    const float* q    = (const float*)d_in[0];
    const float* k    = (const float*)d_in[1];
    const float* v    = (const float*)d_in[2];
    const int*   mask = (const int*)d_in[3];
    const float* wq_w = (const float*)d_in[4];
    const float* wq_b = (const float*)d_in[5];
    const float* wk_w = (const float*)d_in[6];
    const float* wk_b = (const float*)d_in[7];
    const float* wv_w = (const float*)d_in[8];
    const float* wv_b = (const float*)d_in[9];
    const float* dw   = (const float*)d_in[10];
    const float* db   = (const float*)d_in[11];

    float* out = (float*)d_out;
    float* wts = out + OUT_ELEMS;

    bf16 *xqh, *xql, *xkh, *xkl, *xvh, *xvl;
    bf16 *wqh, *wql, *wkh, *wkl, *wvh, *wvl, *wdh, *wdl;
    bf16 *qph, *qpl, *kph, *kpl, *vph, *vpl, *ah, *al;
    cudaGetSymbolAddress((void**)&xqh, g_xq_hi); cudaGetSymbolAddress((void**)&xql, g_xq_lo);
    cudaGetSymbolAddress((void**)&xkh, g_xk_hi); cudaGetSymbolAddress((void**)&xkl, g_xk_lo);
    cudaGetSymbolAddress((void**)&xvh, g_xv_hi); cudaGetSymbolAddress((void**)&xvl, g_xv_lo);
    cudaGetSymbolAddress((void**)&wqh, g_wq_hi); cudaGetSymbolAddress((void**)&wql, g_wq_lo);
    cudaGetSymbolAddress((void**)&wkh, g_wk_hi); cudaGetSymbolAddress((void**)&wkl, g_wk_lo);
    cudaGetSymbolAddress((void**)&wvh, g_wv_hi); cudaGetSymbolAddress((void**)&wvl, g_wv_lo);
    cudaGetSymbolAddress((void**)&wdh, g_wd_hi); cudaGetSymbolAddress((void**)&wdl, g_wd_lo);
    cudaGetSymbolAddress((void**)&qph, g_qp_hi); cudaGetSymbolAddress((void**)&qpl, g_qp_lo);
    cudaGetSymbolAddress((void**)&kph, g_kp_hi); cudaGetSymbolAddress((void**)&kpl, g_kp_lo);
    cudaGetSymbolAddress((void**)&vph, g_vp_hi); cudaGetSymbolAddress((void**)&vpl, g_vp_lo);
    cudaGetSymbolAddress((void**)&ah,  g_ah);    cudaGetSymbolAddress((void**)&al,  g_al);

    cudaFuncSetAttribute(qkv_kernel,    cudaFuncAttributeMaxDynamicSharedMemorySize, 81920);
    cudaFuncSetAttribute(dense_kernel,  cudaFuncAttributeMaxDynamicSharedMemorySize, 81920);
    cudaFuncSetAttribute(scores_kernel, cudaFuncAttributeMaxDynamicSharedMemorySize, 73728);
    cudaFuncSetAttribute(pv_kernel,     cudaFuncAttributeMaxDynamicSharedMemorySize, 75776);

    // launch 0: input splits
    Split3Args s3;
    s3.s[0] = {q, xqh, xql}; s3.s[1] = {k, xkh, xkl}; s3.s[2] = {v, xvh, xvl};
    split3_kernel<<<dim3(2048, 1, 3), 256>>>(s3);
    // launch 1: weight splits
    Split4Args s4;
    s4.s[0] = {wq_w, wqh, wql}; s4.s[1] = {wk_w, wkh, wkl};
    s4.s[2] = {wv_w, wvh, wvl}; s4.s[3] = {dw, wdh, wdl};
    split4_kernel<<<dim3(512, 1, 4), 256>>>(s4);

    // launch 2: QKV projections
    QKVArgs qa;
    qa.p[0] = {xqh, xql, wqh, wql, wq_b, qph, qpl};
    qa.p[1] = {xkh, xkl, wkh, wkl, wk_b, kph, kpl};
    qa.p[2] = {xvh, xvl, wvh, wvl, wv_b, vph, vpl};
    qkv_kernel<<<dim3(8, 32, 3), 256, 81920>>>(qa);

    // launch 3: scores
    scores_kernel<<<dim3(16, 16, 32), 256, 73728>>>(qph, qpl, kph, kpl, wts);
    // launch 4: softmax
    softmax_kernel<<<65536, 256>>>(wts, mask);
    // launch 5: PV (ncu -s 5 -c 1 captures this one)
    pv_kernel<<<dim3(16, 32), 256, 75776>>>(wts, vph, vpl, ah, al);
    // launch 6: dense
    dense_kernel<<<dim3(8, 32), 256, 81920>>>(ah, al, wdh, wdl, db, out);
}

// round 7
// speedup vs baseline: 1.6507x; 1.0327x over previous
#include <cuda_runtime.h>
#include <cuda_bf16.h>
#include <stdint.h>
#include <math.h>

typedef __nv_bfloat16 bf16;

constexpr long OUT_ELEMS = 4194304L;   // B*S*D

// ---------------- scratch: device globals (no allocation) ----------------
__device__ __align__(256) bf16 g_xq_hi[4194304], g_xq_lo[4194304];
__device__ __align__(256) bf16 g_xk_hi[4194304], g_xk_lo[4194304];
__device__ __align__(256) bf16 g_xv_hi[4194304], g_xv_lo[4194304];
__device__ __align__(256) bf16 g_wq_hi[1048576], g_wq_lo[1048576];
__device__ __align__(256) bf16 g_wk_hi[1048576], g_wk_lo[1048576];
__device__ __align__(256) bf16 g_wv_hi[1048576], g_wv_lo[1048576];
__device__ __align__(256) bf16 g_wd_hi[1048576], g_wd_lo[1048576];
__device__ __align__(256) bf16 g_qp_hi[4194304], g_qp_lo[4194304];  // [bh][s][64]
__device__ __align__(256) bf16 g_kp_hi[4194304], g_kp_lo[4194304];
__device__ __align__(256) bf16 g_vp_hi[4194304], g_vp_lo[4194304];
__device__ __align__(256) bf16 g_ah[4194304], g_al[4194304];        // attn hi/lo [m][1024]

// ---------------- helpers ----------------
__device__ __forceinline__ uint32_t smem_u32(const void* p) {
    uint32_t a;
    asm("{ .reg .u64 t; cvta.to.shared.u64 t, %1; cvt.u32.u64 %0, t; }" : "=r"(a) : "l"(p));
    return a;
}
__device__ __forceinline__ void cpa16(uint32_t d, const void* g) {
    asm volatile("cp.async.cg.shared.global [%0], [%1], 16;" :: "r"(d), "l"(g));
}
#define CP_COMMIT() asm volatile("cp.async.commit_group;" ::: "memory")
#define CP_WAIT0()  asm volatile("cp.async.wait_group 0;" ::: "memory")
#define CP_WAIT1()  asm volatile("cp.async.wait_group 1;" ::: "memory")

__device__ __forceinline__ void ldm_x4(uint32_t& r0, uint32_t& r1, uint32_t& r2, uint32_t& r3, uint32_t a) {
    asm volatile("ldmatrix.sync.aligned.m8n8.x4.shared.b16 {%0,%1,%2,%3}, [%4];"
                 : "=r"(r0), "=r"(r1), "=r"(r2), "=r"(r3) : "r"(a));
}
__device__ __forceinline__ void ldm_x4t(uint32_t& r0, uint32_t& r1, uint32_t& r2, uint32_t& r3, uint32_t a) {
    asm volatile("ldmatrix.sync.aligned.m8n8.x4.trans.shared.b16 {%0,%1,%2,%3}, [%4];"
                 : "=r"(r0), "=r"(r1), "=r"(r2), "=r"(r3) : "r"(a));
}
__device__ __forceinline__ void mma16816(float* c, const uint32_t* a, const uint32_t* b) {
    asm volatile(
        "mma.sync.aligned.m16n8k16.row.col.f32.bf16.bf16.f32 "
        "{%0,%1,%2,%3}, {%4,%5,%6,%7}, {%8,%9}, {%0,%1,%2,%3};"
        : "+f"(c[0]), "+f"(c[1]), "+f"(c[2]), "+f"(c[3])
        : "r"(a[0]), "r"(a[1]), "r"(a[2]), "r"(a[3]), "r"(b[0]), "r"(b[1]));
}

__device__ __forceinline__ uint32_t pack2(bf16 a, bf16 b) {
    return (uint32_t)__bfloat16_as_ushort(a) | ((uint32_t)__bfloat16_as_ushort(b) << 16);
}
__device__ __forceinline__ void split1(float v, bf16& h, bf16& l) {
    h = __float2bfloat16_rn(v);
    l = __float2bfloat16_rn(v - __bfloat162float(h));
}

// --------------- warp-tile GEMM core (3-term compensated) ---------------
template<int MT, int NT, int NK, bool TRB>
__device__ __forceinline__ void gemm_pass(float (&acc)[MT][NT][4],
        uint32_t ab, uint32_t bb, int astr, int bstr, int lane)
{
    const int a_row = (lane & 7) + ((lane >> 3) & 1) * 8;
    const int a_k16 = (lane >> 4) * 16;
    const int b_row = (lane & 7) + (lane >> 4) * 8;
    const int b_k16 = ((lane >> 3) & 1) * 16;
    const int bt_row = (lane & 7) + ((lane >> 3) & 1) * 8;
    const int bt_col = (lane >> 4) * 8;
#pragma unroll
    for (int ks = 0; ks < NK; ks++) {
        uint32_t af[MT][4];
#pragma unroll
        for (int mt = 0; mt < MT; mt++)
            ldm_x4(af[mt][0], af[mt][1], af[mt][2], af[mt][3],
                   ab + (mt * 16 + a_row) * astr + ks * 32 + a_k16);
        uint32_t bfr[NT][2];
#pragma unroll
        for (int np = 0; np < NT / 2; np++) {
            uint32_t r0, r1, r2, r3;
            if (TRB)
                ldm_x4t(r0, r1, r2, r3, bb + (ks * 16 + bt_row) * bstr + (np * 16 + bt_col) * 2);
            else
                ldm_x4(r0, r1, r2, r3, bb + (np * 16 + b_row) * bstr + ks * 32 + b_k16);
            bfr[2*np][0] = r0; bfr[2*np][1] = r1;
            bfr[2*np+1][0] = r2; bfr[2*np+1][1] = r3;
        }
#pragma unroll
        for (int mt = 0; mt < MT; mt++)
#pragma unroll
            for (int nt = 0; nt < NT; nt++)
                mma16816(acc[mt][nt], af[mt], bfr[nt]);
    }
}

template<int MT, int NT, int NK, bool TRB>
__device__ __forceinline__ void gemm3(float (&acc)[MT][NT][4],
        uint32_t ahi, uint32_t alo, uint32_t bhi, uint32_t blo,
        int astr, int bstr, int lane)
{
    gemm_pass<MT, NT, NK, TRB>(acc, ahi, bhi, astr, bstr, lane);
    gemm_pass<MT, NT, NK, TRB>(acc, ahi, blo, astr, bstr, lane);
    gemm_pass<MT, NT, NK, TRB>(acc, alo, bhi, astr, bstr, lane);
}

// ---------------- splits: fp32 -> hi/lo bf16, z-indexed ----------------
struct SplitSet { const float* x; bf16 *hi, *lo; };
struct Split3Args { SplitSet s[3]; };
struct Split4Args { SplitSet s[4]; };

__global__ void split3_kernel(Split3Args args) {
    const SplitSet ss = args.s[blockIdx.z];
    for (long i = blockIdx.x * blockDim.x + threadIdx.x; i < 1048576; i += (long)gridDim.x * blockDim.x) {
        float4 v = *(const float4*)(ss.x + i * 4);
        bf16 h0, l0, h1, l1, h2, l2, h3, l3;
        split1(v.x, h0, l0); split1(v.y, h1, l1);
        split1(v.z, h2, l2); split1(v.w, h3, l3);
        *(uint2*)(ss.hi + i * 4) = make_uint2(pack2(h0, h1), pack2(h2, h3));
        *(uint2*)(ss.lo + i * 4) = make_uint2(pack2(l0, l1), pack2(l2, l3));
    }
}
__global__ void split4_kernel(Split4Args args) {
    const SplitSet ss = args.s[blockIdx.z];
    for (long i = blockIdx.x * blockDim.x + threadIdx.x; i < 262144; i += (long)gridDim.x * blockDim.x) {
        float4 v = *(const float4*)(ss.x + i * 4);
        bf16 h0, l0, h1, l1, h2, l2, h3, l3;
        split1(v.x, h0, l0); split1(v.y, h1, l1);
        split1(v.z, h2, l2); split1(v.w, h3, l3);
        *(uint2*)(ss.hi + i * 4) = make_uint2(pack2(h0, h1), pack2(h2, h3));
        *(uint2*)(ss.lo + i * 4) = make_uint2(pack2(l0, l1), pack2(l2, l3));
    }
}

// ---------------- QKV proj: 3 GEMMs in one launch (z selects) ----------------
struct ProjSet { const bf16 *Ah, *Al, *Bh, *Bl; const float* bias; bf16 *Ph, *Pl; };
struct QKVArgs { ProjSet p[3]; };

// Block 128x128, 8 warps (2x4), BK=32, double-buffered. Writes split-head hi/lo.
__global__ __launch_bounds__(256) void qkv_kernel(QKVArgs args)
{
    extern __shared__ char smem[];
    const uint32_t sb = smem_u32(smem);
    const ProjSet ps = args.p[blockIdx.z];
    const int tid = threadIdx.x, lane = tid & 31, wid = tid >> 5;
    const int warp_m = wid >> 2, warp_n = wid & 3;
    const long m0 = (long)blockIdx.y * 128, n0 = (long)blockIdx.x * 128;

    float acc[4][4][4];
#pragma unroll
    for (int i = 0; i < 4; i++)
#pragma unroll
        for (int j = 0; j < 4; j++)
#pragma unroll
            for (int k = 0; k < 4; k++) acc[i][j][k] = 0.f;

    const bf16* srcs[4] = {ps.Ah + m0 * 1024, ps.Al + m0 * 1024,
                           ps.Bh + n0 * 1024, ps.Bl + n0 * 1024};
    auto load_chunk = [&](int buf, int kb) {
        uint32_t base = sb + buf * 40960;
#pragma unroll
        for (int t = 0; t < 4; t++) {
            const bf16* s = srcs[t] + kb;
            uint32_t db = base + t * 10240;
#pragma unroll
            for (int j = 0; j < 2; j++) {
                int idx = tid + j * 256;
                int r = idx >> 2, c = idx & 3;
                cpa16(db + r * 80 + c * 16, s + (long)r * 1024 + c * 8);
            }
        }
    };

    load_chunk(0, 0);
    CP_COMMIT();
    const int aoff = warp_m * 64 * 80, boff = warp_n * 32 * 80;
    for (int ch = 0; ch < 32; ch++) {
        if (ch < 31) { load_chunk((ch + 1) & 1, (ch + 1) * 32); CP_COMMIT(); CP_WAIT1(); }
        else CP_WAIT0();
        __syncthreads();
        uint32_t b = sb + (ch & 1) * 40960;
        gemm3<4, 4, 2, false>(acc, b + aoff, b + 10240 + aoff,
                              b + 20480 + boff, b + 30720 + boff, 80, 80, lane);
        __syncthreads();
    }

#pragma unroll
    for (int mt = 0; mt < 4; mt++) {
#pragma unroll
        for (int nt = 0; nt < 4; nt++) {
            int n = (int)n0 + warp_n * 32 + nt * 8 + (lane & 3) * 2;
            float bv0 = ps.bias[n], bv1 = ps.bias[n + 1];
            long r0 = m0 + warp_m * 64 + mt * 16 + (lane >> 2);
            long r1 = r0 + 8;
            float v00 = acc[mt][nt][0] + bv0, v01 = acc[mt][nt][1] + bv1;
            float v10 = acc[mt][nt][2] + bv0, v11 = acc[mt][nt][3] + bv1;
            int h = n >> 6, dh = n & 63;
            {
                int b_ = (int)(r0 >> 11), s_ = (int)(r0 & 2047);
                long a = ((long)(b_ * 16 + h) * 2048 + s_) * 64 + dh;
                bf16 hh0, ll0, hh1, ll1;
                split1(v00, hh0, ll0); split1(v01, hh1, ll1);
                *(uint32_t*)(ps.Ph + a) = pack2(hh0, hh1);
                *(uint32_t*)(ps.Pl + a) = pack2(ll0, ll1);
            }
            {
                int b_ = (int)(r1 >> 11), s_ = (int)(r1 & 2047);
                long a = ((long)(b_ * 16 + h) * 2048 + s_) * 64 + dh;
                bf16 hh0, ll0, hh1, ll1;
                split1(v10, hh0, ll0); split1(v11, hh1, ll1);
                *(uint32_t*)(ps.Ph + a) = pack2(hh0, hh1);
                *(uint32_t*)(ps.Pl + a) = pack2(ll0, ll1);
            }
        }
    }
}

// ---------------- scores: K-streaming. Wt[bh,q,k] = 0.125 * Q.K -------------
// Grid (qt=16, bh=32). Q tile resident; stream 16 K tiles double-buffered.
// smem: QH 0, QL 18432, K bufs at 36864 + b*36864 (KH, KL each 18432).
__global__ __launch_bounds__(256) void scores_kernel(
    const bf16* __restrict__ Qhi, const bf16* __restrict__ Qlo,
    const bf16* __restrict__ Khi, const bf16* __restrict__ Klo,
    float* __restrict__ Wt)
{
    extern __shared__ char smem[];
    const uint32_t sb = smem_u32(smem);
    const int tid = threadIdx.x, lane = tid & 31, wid = tid >> 5;
    const int warp_m = wid >> 2, warp_n = wid & 3;
    const int qt = blockIdx.x, bh = blockIdx.y;

    const bf16* qh = Qhi + ((long)bh * 2048 + qt * 128) * 64;
    const bf16* ql = Qlo + ((long)bh * 2048 + qt * 128) * 64;
    const bf16* kh0 = Khi + (long)bh * 2048 * 64;
    const bf16* kl0 = Klo + (long)bh * 2048 * 64;

    auto load_tile = [&](uint32_t dst, const bf16* src) {
#pragma unroll
        for (int j = 0; j < 4; j++) {
            int idx = tid + j * 256;
            int r = idx >> 3, c = idx & 7;
            cpa16(dst + r * 144 + c * 16, src + (long)r * 64 + c * 8);
        }
    };

    // Q tiles + first K tile in one group
    load_tile(sb, qh);
    load_tile(sb + 18432, ql);
    load_tile(sb + 36864, kh0);
    load_tile(sb + 55296, kl0);
    CP_COMMIT();

    const int aoff = warp_m * 64 * 144, boff = warp_n * 32 * 144;
    float* wbase = Wt + ((long)bh * 2048 + qt * 128) * 2048;

    for (int kt = 0; kt < 16; kt++) {
        if (kt < 15) {
            uint32_t kb = sb + 36864 + ((kt + 1) & 1) * 36864;
            load_tile(kb, kh0 + (long)(kt + 1) * 128 * 64);
            load_tile(kb + 18432, kl0 + (long)(kt + 1) * 128 * 64);
            CP_COMMIT(); CP_WAIT1();
        } else CP_WAIT0();
        __syncthreads();

        float acc[4][4][4];
#pragma unroll
        for (int i = 0; i < 4; i++)
#pragma unroll
            for (int j = 0; j < 4; j++)
#pragma unroll
                for (int k = 0; k < 4; k++) acc[i][j][k] = 0.f;

        uint32_t kbuf = sb + 36864 + (kt & 1) * 36864;
        gemm3<4, 4, 4, false>(acc, sb + aoff, sb + 18432 + aoff,
                              kbuf + boff, kbuf + 18432 + boff, 144, 144, lane);

        float* base = wbase + kt * 128;
#pragma unroll
        for (int mt = 0; mt < 4; mt++) {
#pragma unroll
            for (int nt = 0; nt < 4; nt++) {
                int r0 = warp_m * 64 + mt * 16 + (lane >> 2);
                int c = warp_n * 32 + nt * 8 + (lane & 3) * 2;
                *(float2*)(base + (long)r0 * 2048 + c) =
                    make_float2(acc[mt][nt][0] * 0.125f, acc[mt][nt][1] * 0.125f);
                *(float2*)(base + (long)(r0 + 8) * 2048 + c) =
                    make_float2(acc[mt][nt][2] * 0.125f, acc[mt][nt][3] * 0.125f);
            }
        }
        __syncthreads();
    }
}

// ---------------- softmax (in place, mask at read; vectorized) ----------------
__global__ __launch_bounds__(256) void softmax_kernel(
    float* __restrict__ Wt, const int* __restrict__ mask)
{
    const long row = blockIdx.x;
    const int bh = (int)(row >> 11), q = (int)(row & 2047), b_ = bh >> 4;
    float* p = Wt + row * 2048L;
    const int* mrow = mask + ((long)b_ * 2048 + q) * 2048;
    const int tid = threadIdx.x;

    float4 v[2];
    float mx = -INFINITY;
#pragma unroll
    for (int t = 0; t < 2; t++) {
        const int idx = (t * 256 + tid) * 4;
        v[t] = *(const float4*)(p + idx);
        int4 m4 = *(const int4*)(mrow + idx);
        if (m4.x == 0) v[t].x = -INFINITY;
        if (m4.y == 0) v[t].y = -INFINITY;
        if (m4.z == 0) v[t].z = -INFINITY;
        if (m4.w == 0) v[t].w = -INFINITY;
        mx = fmaxf(mx, fmaxf(fmaxf(v[t].x, v[t].y), fmaxf(v[t].z, v[t].w)));
    }

    __shared__ float red[8];
#pragma unroll
    for (int o = 16; o > 0; o >>= 1) mx = fmaxf(mx, __shfl_xor_sync(0xffffffffu, mx, o));
    if ((tid & 31) == 0) red[tid >> 5] = mx;
    __syncthreads();
    mx = -INFINITY;
#pragma unroll
    for (int i = 0; i < 8; i++) mx = fmaxf(mx, red[i]);
    __syncthreads();
    float s = 0.f;
#pragma unroll
    for (int t = 0; t < 2; t++) {
        v[t].x = __expf(v[t].x - mx); v[t].y = __expf(v[t].y - mx);
        v[t].z = __expf(v[t].z - mx); v[t].w = __expf(v[t].w - mx);
        s += (v[t].x + v[t].y) + (v[t].z + v[t].w);
    }
#pragma unroll
    for (int o = 16; o > 0; o >>= 1) s += __shfl_xor_sync(0xffffffffu, s, o);
    if ((tid & 31) == 0) red[tid >> 5] = s;
    __syncthreads();
    s = 0.f;
#pragma unroll
    for (int i = 0; i < 8; i++) s += red[i];
    const float inv = 1.f / s;
#pragma unroll
    for (int t = 0; t < 2; t++) {
        const int idx = (t * 256 + tid) * 4;
        *(float4*)(p + idx) = make_float4(v[t].x * inv, v[t].y * inv,
                                          v[t].z * inv, v[t].w * inv);
    }
}

// ---------------- PV: O = W @ V (normalized W fp32 -> split in-kernel) -------
// Writes attn directly as bf16 hi/lo [m][1024].
__global__ __launch_bounds__(256) void pv_kernel(
    const float* __restrict__ Wt, const bf16* __restrict__ Vhi,
    const bf16* __restrict__ Vlo, bf16* __restrict__ Oh, bf16* __restrict__ Ol)
{
    extern __shared__ char smem[];
    const uint32_t sb = smem_u32(smem);
    const int tid = threadIdx.x, lane = tid & 31, wid = tid >> 5;
    const int warp_m = wid >> 1, warp_n = wid & 1;
    const int qt = blockIdx.x, bh = blockIdx.y;
    const uint32_t RAW0 = 0, RAW1 = 18432, VH0 = 36864, VH1 = 41472,
                   VL0 = 46080, VL1 = 50688, WH = 55296, WL = 65536;

    const float* wsrc = Wt + ((long)bh * 2048 + qt * 128) * 2048;
    const bf16* vhsrc = Vhi + (long)bh * 2048 * 64;
    const bf16* vlsrc = Vlo + (long)bh * 2048 * 64;

    auto load_chunk = [&](int buf, int ch) {
        uint32_t raw = sb + (buf ? RAW1 : RAW0);
        uint32_t vh = sb + (buf ? VH1 : VH0);
        uint32_t vl = sb + (buf ? VL1 : VL0);
        const float* wp = wsrc + ch * 32;
#pragma unroll
        for (int j = 0; j < 4; j++) {
            int idx = tid + j * 256;
            int r = idx >> 3, c = idx & 7;
            cpa16(raw + r * 144 + c * 16, wp + (long)r * 2048 + c * 4);
        }
        {
            int r = tid >> 3, c = tid & 7;
            cpa16(vh + r * 144 + c * 16, vhsrc + (long)(ch * 32 + r) * 64 + c * 8);
            cpa16(vl + r * 144 + c * 16, vlsrc + (long)(ch * 32 + r) * 64 + c * 8);
        }
    };

    float acc[2][4][4];
#pragma unroll
    for (int i = 0; i < 2; i++)
#pragma unroll
        for (int j = 0; j < 4; j++)
#pragma unroll
            for (int k = 0; k < 4; k++) acc[i][j][k] = 0.f;

    load_chunk(0, 0);
    CP_COMMIT();
    const int crow = tid >> 1, chalf = tid & 1;
    const int aoff = warp_m * 32 * 80, boff = warp_n * 32 * 2;
    for (int ch = 0; ch < 64; ch++) {
        if (ch < 63) { load_chunk((ch + 1) & 1, ch + 1); CP_COMMIT(); CP_WAIT1(); }
        else CP_WAIT0();
        __syncthreads();
        // convert raw fp32 -> WH/WL padded bf16
        {
            const char* rp = smem + (ch & 1 ? RAW1 : RAW0) + crow * 144 + chalf * 64;
            uint32_t uh[8], ul[8];
#pragma unroll
            for (int i = 0; i < 4; i++) {
                float4 v = *(const float4*)(rp + i * 16);
                bf16 h0, l0, h1, l1;
                split1(v.x, h0, l0); split1(v.y, h1, l1);
                uh[i * 2] = pack2(h0, h1); ul[i * 2] = pack2(l0, l1);
                split1(v.z, h0, l0); split1(v.w, h1, l1);
                uh[i * 2 + 1] = pack2(h0, h1); ul[i * 2 + 1] = pack2(l0, l1);
            }
            char* wh = smem + WH + crow * 80 + chalf * 32;
            char* wl = smem + WL + crow * 80 + chalf * 32;
            *(uint4*)wh = make_uint4(uh[0], uh[1], uh[2], uh[3]);
            *(uint4*)(wh + 16) = make_uint4(uh[4], uh[5], uh[6], uh[7]);
            *(uint4*)wl = make_uint4(ul[0], ul[1], ul[2], ul[3]);
            *(uint4*)(wl + 16) = make_uint4(ul[4], ul[5], ul[6], ul[7]);
        }
        __syncthreads();
        uint32_t vh = sb + ((ch & 1) ? VH1 : VH0) + boff;
        uint32_t vl = sb + ((ch & 1) ? VL1 : VL0) + boff;
        gemm3<2, 4, 2, true>(acc, sb + WH + aoff, sb + WL + aoff, vh, vl, 80, 144, lane);
        __syncthreads();
    }

    const int b_ = bh >> 4, h = bh & 15;
#pragma unroll
    for (int mt = 0; mt < 2; mt++) {
#pragma unroll
        for (int nt = 0; nt < 4; nt++) {
            int s0 = qt * 128 + warp_m * 32 + mt * 16 + (lane >> 2);
            int dh = warp_n * 32 + nt * 8 + (lane & 3) * 2;
            long a0 = ((long)b_ * 2048 + s0) * 1024 + h * 64 + dh;
            long a1 = ((long)b_ * 2048 + s0 + 8) * 1024 + h * 64 + dh;
            bf16 hh0, ll0, hh1, ll1;
            split1(acc[mt][nt][0], hh0, ll0); split1(acc[mt][nt][1], hh1, ll1);
            *(uint32_t*)(Oh + a0) = pack2(hh0, hh1);
            *(uint32_t*)(Ol + a0) = pack2(ll0, ll1);
            split1(acc[mt][nt][2], hh0, ll0); split1(acc[mt][nt][3], hh1, ll1);
            *(uint32_t*)(Oh + a1) = pack2(hh0, hh1);
            *(uint32_t*)(Ol + a1) = pack2(ll0, ll1);
        }
    }
}

// ---------------- dense: out = A @ W^T + b (fp32 out) ----------------
__global__ __launch_bounds__(256) void dense_kernel(
    const bf16* __restrict__ Ahi, const bf16* __restrict__ Alo,
    const bf16* __restrict__ Bhi, const bf16* __restrict__ Blo,
    const float* __restrict__ bias, float* __restrict__ outD)
{
    extern __shared__ char smem[];
    const uint32_t sb = smem_u32(smem);
    const int tid = threadIdx.x, lane = tid & 31, wid = tid >> 5;
    const int warp_m = wid >> 2, warp_n = wid & 3;
    const long m0 = (long)blockIdx.y * 128, n0 = (long)blockIdx.x * 128;

    float acc[4][4][4];
#pragma unroll
    for (int i = 0; i < 4; i++)
#pragma unroll
        for (int j = 0; j < 4; j++)
#pragma unroll
            for (int k = 0; k < 4; k++) acc[i][j][k] = 0.f;

    const bf16* srcs[4] = {Ahi + m0 * 1024, Alo + m0 * 1024,
                           Bhi + n0 * 1024, Blo + n0 * 1024};
    auto load_chunk = [&](int buf, int kb) {
        uint32_t base = sb + buf * 40960;
#pragma unroll
        for (int t = 0; t < 4; t++) {
            const bf16* s = srcs[t] + kb;
            uint32_t db = base + t * 10240;
#pragma unroll
            for (int j = 0; j < 2; j++) {
                int idx = tid + j * 256;
                int r = idx >> 2, c = idx & 3;
                cpa16(db + r * 80 + c * 16, s + (long)r * 1024 + c * 8);
            }
        }
    };

    load_chunk(0, 0);
    CP_COMMIT();
    const int aoff = warp_m * 64 * 80, boff = warp_n * 32 * 80;
    for (int ch = 0; ch < 32; ch++) {
        if (ch < 31) { load_chunk((ch + 1) & 1, (ch + 1) * 32); CP_COMMIT(); CP_WAIT1(); }
        else CP_WAIT0();
        __syncthreads();
        uint32_t b = sb + (ch & 1) * 40960;
        gemm3<4, 4, 2, false>(acc, b + aoff, b + 10240 + aoff,
                              b + 20480 + boff, b + 30720 + boff, 80, 80, lane);
        __syncthreads();
    }

#pragma unroll
    for (int mt = 0; mt < 4; mt++) {
#pragma unroll
        for (int nt = 0; nt < 4; nt++) {
            int n = (int)n0 + warp_n * 32 + nt * 8 + (lane & 3) * 2;
            float bv0 = bias[n], bv1 = bias[n + 1];
            long r0 = m0 + warp_m * 64 + mt * 16 + (lane >> 2);
            *(float2*)(outD + r0 * 1024 + n) =
                make_float2(acc[mt][nt][0] + bv0, acc[mt][nt][1] + bv1);
            *(float2*)(outD + (r0 + 8) * 1024 + n) =
                make_float2(acc[mt][nt][2] + bv0, acc[mt][nt][3] + bv1);
        }
    }
}

// ---------------- host launcher ----------------
extern "C" void kernel_launch(void* const* d_in, const int* in_sizes, int n_in,
                              void* d_out, int out_size)
{
    const float* q    = (const float*)d_in[0];
    const float* k    = (const float*)d_in[1];
    const float* v    = (const float*)d_in[2];
    const int*   mask = (const int*)d_in[3];
    const float* wq_w = (const float*)d_in[4];
    const float* wq_b = (const float*)d_in[5];
    const float* wk_w = (const float*)d_in[6];
    const float* wk_b = (const float*)d_in[7];
    const float* wv_w = (const float*)d_in[8];
    const float* wv_b = (const float*)d_in[9];
    const float* dw   = (const float*)d_in[10];
    const float* db   = (const float*)d_in[11];

    float* out = (float*)d_out;
    float* wts = out + OUT_ELEMS;

    bf16 *xqh, *xql, *xkh, *xkl, *xvh, *xvl;
    bf16 *wqh, *wql, *wkh, *wkl, *wvh, *wvl, *wdh, *wdl;
    bf16 *qph, *qpl, *kph, *kpl, *vph, *vpl, *ah, *al;
    cudaGetSymbolAddress((void**)&xqh, g_xq_hi); cudaGetSymbolAddress((void**)&xql, g_xq_lo);
    cudaGetSymbolAddress((void**)&xkh, g_xk_hi); cudaGetSymbolAddress((void**)&xkl, g_xk_lo);
    cudaGetSymbolAddress((void**)&xvh, g_xv_hi); cudaGetSymbolAddress((void**)&xvl, g_xv_lo);
    cudaGetSymbolAddress((void**)&wqh, g_wq_hi); cudaGetSymbolAddress((void**)&wql, g_wq_lo);
    cudaGetSymbolAddress((void**)&wkh, g_wk_hi); cudaGetSymbolAddress((void**)&wkl, g_wk_lo);
    cudaGetSymbolAddress((void**)&wvh, g_wv_hi); cudaGetSymbolAddress((void**)&wvl, g_wv_lo);
    cudaGetSymbolAddress((void**)&wdh, g_wd_hi); cudaGetSymbolAddress((void**)&wdl, g_wd_lo);
    cudaGetSymbolAddress((void**)&qph, g_qp_hi); cudaGetSymbolAddress((void**)&qpl, g_qp_lo);
    cudaGetSymbolAddress((void**)&kph, g_kp_hi); cudaGetSymbolAddress((void**)&kpl, g_kp_lo);
    cudaGetSymbolAddress((void**)&vph, g_vp_hi); cudaGetSymbolAddress((void**)&vpl, g_vp_lo);
    cudaGetSymbolAddress((void**)&ah,  g_ah);    cudaGetSymbolAddress((void**)&al,  g_al);

    cudaFuncSetAttribute(qkv_kernel,    cudaFuncAttributeMaxDynamicSharedMemorySize, 81920);
    cudaFuncSetAttribute(dense_kernel,  cudaFuncAttributeMaxDynamicSharedMemorySize, 81920);
    cudaFuncSetAttribute(scores_kernel, cudaFuncAttributeMaxDynamicSharedMemorySize, 110592);
    cudaFuncSetAttribute(pv_kernel,     cudaFuncAttributeMaxDynamicSharedMemorySize, 75776);

    // launch 0: input splits
    Split3Args s3;
    s3.s[0] = {q, xqh, xql}; s3.s[1] = {k, xkh, xkl}; s3.s[2] = {v, xvh, xvl};
    split3_kernel<<<dim3(2048, 1, 3), 256>>>(s3);
    // launch 1: weight splits
    Split4Args s4;
    s4.s[0] = {wq_w, wqh, wql}; s4.s[1] = {wk_w, wkh, wkl};
    s4.s[2] = {wv_w, wvh, wvl}; s4.s[3] = {dw, wdh, wdl};
    split4_kernel<<<dim3(512, 1, 4), 256>>>(s4);

    // launch 2: QKV projections
    QKVArgs qa;
    qa.p[0] = {xqh, xql, wqh, wql, wq_b, qph, qpl};
    qa.p[1] = {xkh, xkl, wkh, wkl, wk_b, kph, kpl};
    qa.p[2] = {xvh, xvl, wvh, wvl, wv_b, vph, vpl};
    qkv_kernel<<<dim3(8, 32, 3), 256, 81920>>>(qa);

    // launch 3: scores (K-streaming)
    scores_kernel<<<dim3(16, 32), 256, 110592>>>(qph, qpl, kph, kpl, wts);
    // launch 4: softmax
    softmax_kernel<<<65536, 256>>>(wts, mask);
    // launch 5: PV (ncu -s 5 -c 1 captures this one)
    pv_kernel<<<dim3(16, 32), 256, 75776>>>(wts, vph, vpl, ah, al);
    // launch 6: dense
    dense_kernel<<<dim3(8, 32), 256, 81920>>>(ah, al, wdh, wdl, db, out);
}

// round 12
// speedup vs baseline: 1.6569x; 1.0038x over previous
#include <cuda_runtime.h>
#include <cuda_bf16.h>
#include <stdint.h>
#include <math.h>

typedef __nv_bfloat16 bf16;

constexpr long OUT_ELEMS = 4194304L;   // B*S*D

// ---------------- scratch: device globals (no allocation) ----------------
__device__ __align__(256) bf16 g_xq_hi[4194304], g_xq_lo[4194304];
__device__ __align__(256) bf16 g_xk_hi[4194304], g_xk_lo[4194304];
__device__ __align__(256) bf16 g_xv_hi[4194304], g_xv_lo[4194304];
__device__ __align__(256) bf16 g_wq_hi[1048576], g_wq_lo[1048576];
__device__ __align__(256) bf16 g_wk_hi[1048576], g_wk_lo[1048576];
__device__ __align__(256) bf16 g_wv_hi[1048576], g_wv_lo[1048576];
__device__ __align__(256) bf16 g_wd_hi[1048576], g_wd_lo[1048576];
__device__ __align__(256) bf16 g_qp_hi[4194304], g_qp_lo[4194304];  // [bh][s][64]
__device__ __align__(256) bf16 g_kp_hi[4194304], g_kp_lo[4194304];
__device__ __align__(256) bf16 g_vp_hi[4194304], g_vp_lo[4194304];
__device__ __align__(256) bf16 g_ah[4194304], g_al[4194304];        // attn hi/lo [m][1024]

// ---------------- helpers ----------------
__device__ __forceinline__ uint32_t smem_u32(const void* p) {
    uint32_t a;
    asm("{ .reg .u64 t; cvta.to.shared.u64 t, %1; cvt.u32.u64 %0, t; }" : "=r"(a) : "l"(p));
    return a;
}
__device__ __forceinline__ void cpa16(uint32_t d, const void* g) {
    asm volatile("cp.async.cg.shared.global [%0], [%1], 16;" :: "r"(d), "l"(g));
}
#define CP_COMMIT() asm volatile("cp.async.commit_group;" ::: "memory")
#define CP_WAIT0()  asm volatile("cp.async.wait_group 0;" ::: "memory")
#define CP_WAIT1()  asm volatile("cp.async.wait_group 1;" ::: "memory")

__device__ __forceinline__ void ldm_x4(uint32_t& r0, uint32_t& r1, uint32_t& r2, uint32_t& r3, uint32_t a) {
    asm volatile("ldmatrix.sync.aligned.m8n8.x4.shared.b16 {%0,%1,%2,%3}, [%4];"
                 : "=r"(r0), "=r"(r1), "=r"(r2), "=r"(r3) : "r"(a));
}
__device__ __forceinline__ void ldm_x4t(uint32_t& r0, uint32_t& r1, uint32_t& r2, uint32_t& r3, uint32_t a) {
    asm volatile("ldmatrix.sync.aligned.m8n8.x4.trans.shared.b16 {%0,%1,%2,%3}, [%4];"
                 : "=r"(r0), "=r"(r1), "=r"(r2), "=r"(r3) : "r"(a));
}
__device__ __forceinline__ void mma16816(float* c, const uint32_t* a, const uint32_t* b) {
    asm volatile(
        "mma.sync.aligned.m16n8k16.row.col.f32.bf16.bf16.f32 "
        "{%0,%1,%2,%3}, {%4,%5,%6,%7}, {%8,%9}, {%0,%1,%2,%3};"
        : "+f"(c[0]), "+f"(c[1]), "+f"(c[2]), "+f"(c[3])
        : "r"(a[0]), "r"(a[1]), "r"(a[2]), "r"(a[3]), "r"(b[0]), "r"(b[1]));
}

__device__ __forceinline__ uint32_t pack2(bf16 a, bf16 b) {
    return (uint32_t)__bfloat16_as_ushort(a) | ((uint32_t)__bfloat16_as_ushort(b) << 16);
}
__device__ __forceinline__ void split1(float v, bf16& h, bf16& l) {
    h = __float2bfloat16_rn(v);
    l = __float2bfloat16_rn(v - __bfloat162float(h));
}

// --------------- warp-tile GEMM core (3-term compensated) ---------------
template<int MT, int NT, int NK, bool TRB>
__device__ __forceinline__ void gemm_pass(float (&acc)[MT][NT][4],
        uint32_t ab, uint32_t bb, int astr, int bstr, int lane)
{
    const int a_row = (lane & 7) + ((lane >> 3) & 1) * 8;
    const int a_k16 = (lane >> 4) * 16;
    const int b_row = (lane & 7) + (lane >> 4) * 8;
    const int b_k16 = ((lane >> 3) & 1) * 16;
    const int bt_row = (lane & 7) + ((lane >> 3) & 1) * 8;
    const int bt_col = (lane >> 4) * 8;
#pragma unroll
    for (int ks = 0; ks < NK; ks++) {
        uint32_t af[MT][4];
#pragma unroll
        for (int mt = 0; mt < MT; mt++)
            ldm_x4(af[mt][0], af[mt][1], af[mt][2], af[mt][3],
                   ab + (mt * 16 + a_row) * astr + ks * 32 + a_k16);
        uint32_t bfr[NT][2];
#pragma unroll
        for (int np = 0; np < NT / 2; np++) {
            uint32_t r0, r1, r2, r3;
            if (TRB)
                ldm_x4t(r0, r1, r2, r3, bb + (ks * 16 + bt_row) * bstr + (np * 16 + bt_col) * 2);
            else
                ldm_x4(r0, r1, r2, r3, bb + (np * 16 + b_row) * bstr + ks * 32 + b_k16);
            bfr[2*np][0] = r0; bfr[2*np][1] = r1;
            bfr[2*np+1][0] = r2; bfr[2*np+1][1] = r3;
        }
#pragma unroll
        for (int mt = 0; mt < MT; mt++)
#pragma unroll
            for (int nt = 0; nt < NT; nt++)
                mma16816(acc[mt][nt], af[mt], bfr[nt]);
    }
}

template<int MT, int NT, int NK, bool TRB>
__device__ __forceinline__ void gemm3(float (&acc)[MT][NT][4],
        uint32_t ahi, uint32_t alo, uint32_t bhi, uint32_t blo,
        int astr, int bstr, int lane)
{
    gemm_pass<MT, NT, NK, TRB>(acc, ahi, bhi, astr, bstr, lane);
    gemm_pass<MT, NT, NK, TRB>(acc, ahi, blo, astr, bstr, lane);
    gemm_pass<MT, NT, NK, TRB>(acc, alo, bhi, astr, bstr, lane);
}

// ---------------- splits: fp32 -> hi/lo bf16, z-indexed ----------------
struct SplitSet { const float* x; bf16 *hi, *lo; };
struct Split3Args { SplitSet s[3]; };
struct Split4Args { SplitSet s[4]; };

__global__ void split3_kernel(Split3Args args) {
    const SplitSet ss = args.s[blockIdx.z];
    for (long i = blockIdx.x * blockDim.x + threadIdx.x; i < 1048576; i += (long)gridDim.x * blockDim.x) {
        float4 v = *(const float4*)(ss.x + i * 4);
        bf16 h0, l0, h1, l1, h2, l2, h3, l3;
        split1(v.x, h0, l0); split1(v.y, h1, l1);
        split1(v.z, h2, l2); split1(v.w, h3, l3);
        *(uint2*)(ss.hi + i * 4) = make_uint2(pack2(h0, h1), pack2(h2, h3));
        *(uint2*)(ss.lo + i * 4) = make_uint2(pack2(l0, l1), pack2(l2, l3));
    }
}
__global__ void split4_kernel(Split4Args args) {
    const SplitSet ss = args.s[blockIdx.z];
    for (long i = blockIdx.x * blockDim.x + threadIdx.x; i < 262144; i += (long)gridDim.x * blockDim.x) {
        float4 v = *(const float4*)(ss.x + i * 4);
        bf16 h0, l0, h1, l1, h2, l2, h3, l3;
        split1(v.x, h0, l0); split1(v.y, h1, l1);
        split1(v.z, h2, l2); split1(v.w, h3, l3);
        *(uint2*)(ss.hi + i * 4) = make_uint2(pack2(h0, h1), pack2(h2, h3));
        *(uint2*)(ss.lo + i * 4) = make_uint2(pack2(l0, l1), pack2(l2, l3));
    }
}

// ---------------- QKV proj: 3 GEMMs in one launch (z selects) ----------------
struct ProjSet { const bf16 *Ah, *Al, *Bh, *Bl; const float* bias; bf16 *Ph, *Pl; };
struct QKVArgs { ProjSet p[3]; };

// Block 128x128, 8 warps (2x4), BK=32, double-buffered. Writes split-head hi/lo.
__global__ __launch_bounds__(256) void qkv_kernel(QKVArgs args)
{
    extern __shared__ char smem[];
    const uint32_t sb = smem_u32(smem);
    const ProjSet ps = args.p[blockIdx.z];
    const int tid = threadIdx.x, lane = tid & 31, wid = tid >> 5;
    const int warp_m = wid >> 2, warp_n = wid & 3;
    const long m0 = (long)blockIdx.y * 128, n0 = (long)blockIdx.x * 128;

    float acc[4][4][4];
#pragma unroll
    for (int i = 0; i < 4; i++)
#pragma unroll
        for (int j = 0; j < 4; j++)
#pragma unroll
            for (int k = 0; k < 4; k++) acc[i][j][k] = 0.f;

    const bf16* srcs[4] = {ps.Ah + m0 * 1024, ps.Al + m0 * 1024,
                           ps.Bh + n0 * 1024, ps.Bl + n0 * 1024};
    auto load_chunk = [&](int buf, int kb) {
        uint32_t base = sb + buf * 40960;
#pragma unroll
        for (int t = 0; t < 4; t++) {
            const bf16* s = srcs[t] + kb;
            uint32_t db = base + t * 10240;
#pragma unroll
            for (int j = 0; j < 2; j++) {
                int idx = tid + j * 256;
                int r = idx >> 2, c = idx & 3;
                cpa16(db + r * 80 + c * 16, s + (long)r * 1024 + c * 8);
            }
        }
    };

    load_chunk(0, 0);
    CP_COMMIT();
    const int aoff = warp_m * 64 * 80, boff = warp_n * 32 * 80;
    for (int ch = 0; ch < 32; ch++) {
        if (ch < 31) { load_chunk((ch + 1) & 1, (ch + 1) * 32); CP_COMMIT(); CP_WAIT1(); }
        else CP_WAIT0();
        __syncthreads();
        uint32_t b = sb + (ch & 1) * 40960;
        gemm3<4, 4, 2, false>(acc, b + aoff, b + 10240 + aoff,
                              b + 20480 + boff, b + 30720 + boff, 80, 80, lane);
        __syncthreads();
    }

#pragma unroll
    for (int mt = 0; mt < 4; mt++) {
#pragma unroll
        for (int nt = 0; nt < 4; nt++) {
            int n = (int)n0 + warp_n * 32 + nt * 8 + (lane & 3) * 2;
            float bv0 = ps.bias[n], bv1 = ps.bias[n + 1];
            long r0 = m0 + warp_m * 64 + mt * 16 + (lane >> 2);
            long r1 = r0 + 8;
            float v00 = acc[mt][nt][0] + bv0, v01 = acc[mt][nt][1] + bv1;
            float v10 = acc[mt][nt][2] + bv0, v11 = acc[mt][nt][3] + bv1;
            int h = n >> 6, dh = n & 63;
            {
                int b_ = (int)(r0 >> 11), s_ = (int)(r0 & 2047);
                long a = ((long)(b_ * 16 + h) * 2048 + s_) * 64 + dh;
                bf16 hh0, ll0, hh1, ll1;
                split1(v00, hh0, ll0); split1(v01, hh1, ll1);
                *(uint32_t*)(ps.Ph + a) = pack2(hh0, hh1);
                *(uint32_t*)(ps.Pl + a) = pack2(ll0, ll1);
            }
            {
                int b_ = (int)(r1 >> 11), s_ = (int)(r1 & 2047);
                long a = ((long)(b_ * 16 + h) * 2048 + s_) * 64 + dh;
                bf16 hh0, ll0, hh1, ll1;
                split1(v10, hh0, ll0); split1(v11, hh1, ll1);
                *(uint32_t*)(ps.Ph + a) = pack2(hh0, hh1);
                *(uint32_t*)(ps.Pl + a) = pack2(ll0, ll1);
            }
        }
    }
}

// ---------------- scores: K-streaming, 64q x 128k tiles, 2 CTAs/SM ----------
// Grid (qt=32, bh=32). Q tile resident; stream 16 K tiles double-buffered.
// smem: QH 0 (9216), QL 9216, Kbuf{0,1} at 18432 + b*36864 (KH, KL 18432 each).
__global__ __launch_bounds__(256, 2) void scores_kernel(
    const bf16* __restrict__ Qhi, const bf16* __restrict__ Qlo,
    const bf16* __restrict__ Khi, const bf16* __restrict__ Klo,
    float* __restrict__ Wt)
{
    extern __shared__ char smem[];
    const uint32_t sb = smem_u32(smem);
    const int tid = threadIdx.x, lane = tid & 31, wid = tid >> 5;
    const int warp_m = wid >> 2, warp_n = wid & 3;    // 2 x 4 warps, warp tile 32x32
    const int qt = blockIdx.x, bh = blockIdx.y;

    const bf16* qh = Qhi + ((long)bh * 2048 + qt * 64) * 64;
    const bf16* ql = Qlo + ((long)bh * 2048 + qt * 64) * 64;
    const bf16* kh0 = Khi + (long)bh * 2048 * 64;
    const bf16* kl0 = Klo + (long)bh * 2048 * 64;

    auto load_q = [&](uint32_t dst, const bf16* src) {
#pragma unroll
        for (int j = 0; j < 2; j++) {
            int idx = tid + j * 256;
            int r = idx >> 3, c = idx & 7;
            cpa16(dst + r * 144 + c * 16, src + (long)r * 64 + c * 8);
        }
    };
    auto load_k = [&](uint32_t dst, const bf16* src) {
#pragma unroll
        for (int j = 0; j < 4; j++) {
            int idx = tid + j * 256;
            int r = idx >> 3, c = idx & 7;
            cpa16(dst + r * 144 + c * 16, src + (long)r * 64 + c * 8);
        }
    };

    load_q(sb, qh);
    load_q(sb + 9216, ql);
    load_k(sb + 18432, kh0);
    load_k(sb + 36864, kl0);
    CP_COMMIT();

    const int aoff = warp_m * 32 * 144, boff = warp_n * 32 * 144;
    float* wbase = Wt + ((long)bh * 2048 + qt * 64) * 2048;

    for (int kt = 0; kt < 16; kt++) {
        if (kt < 15) {
            uint32_t kb = sb + 18432 + ((kt + 1) & 1) * 36864;
            load_k(kb, kh0 + (long)(kt + 1) * 128 * 64);
            load_k(kb + 18432, kl0 + (long)(kt + 1) * 128 * 64);
            CP_COMMIT(); CP_WAIT1();
        } else CP_WAIT0();
        __syncthreads();

        float acc[2][4][4];
#pragma unroll
        for (int i = 0; i < 2; i++)
#pragma unroll
            for (int j = 0; j < 4; j++)
#pragma unroll
                for (int k = 0; k < 4; k++) acc[i][j][k] = 0.f;

        uint32_t kbuf = sb + 18432 + (kt & 1) * 36864;
        gemm3<2, 4, 4, false>(acc, sb + aoff, sb + 9216 + aoff,
                              kbuf + boff, kbuf + 18432 + boff, 144, 144, lane);

        float* base = wbase + kt * 128;
#pragma unroll
        for (int mt = 0; mt < 2; mt++) {
#pragma unroll
            for (int nt = 0; nt < 4; nt++) {
                int r0 = warp_m * 32 + mt * 16 + (lane >> 2);
                int c = warp_n * 32 + nt * 8 + (lane & 3) * 2;
                *(float2*)(base + (long)r0 * 2048 + c) =
                    make_float2(acc[mt][nt][0] * 0.125f, acc[mt][nt][1] * 0.125f);
                *(float2*)(base + (long)(r0 + 8) * 2048 + c) =
                    make_float2(acc[mt][nt][2] * 0.125f, acc[mt][nt][3] * 0.125f);
            }
        }
        __syncthreads();
    }
}

// ---------------- softmax (in place, mask at read; vectorized) ----------------
__global__ __launch_bounds__(256) void softmax_kernel(
    float* __restrict__ Wt, const int* __restrict__ mask)
{
    const long row = blockIdx.x;
    const int bh = (int)(row >> 11), q = (int)(row & 2047), b_ = bh >> 4;
    float* p = Wt + row * 2048L;
    const int* mrow = mask + ((long)b_ * 2048 + q) * 2048;
    const int tid = threadIdx.x;

    float4 v[2];
    float mx = -INFINITY;
#pragma unroll
    for (int t = 0; t < 2; t++) {
        const int idx = (t * 256 + tid) * 4;
        v[t] = *(const float4*)(p + idx);
        int4 m4 = *(const int4*)(mrow + idx);
        if (m4.x == 0) v[t].x = -INFINITY;
        if (m4.y == 0) v[t].y = -INFINITY;
        if (m4.z == 0) v[t].z = -INFINITY;
        if (m4.w == 0) v[t].w = -INFINITY;
        mx = fmaxf(mx, fmaxf(fmaxf(v[t].x, v[t].y), fmaxf(v[t].z, v[t].w)));
    }

    __shared__ float red[8];
#pragma unroll
    for (int o = 16; o > 0; o >>= 1) mx = fmaxf(mx, __shfl_xor_sync(0xffffffffu, mx, o));
    if ((tid & 31) == 0) red[tid >> 5] = mx;
    __syncthreads();
    mx = -INFINITY;
#pragma unroll
    for (int i = 0; i < 8; i++) mx = fmaxf(mx, red[i]);
    __syncthreads();
    float s = 0.f;
#pragma unroll
    for (int t = 0; t < 2; t++) {
        v[t].x = __expf(v[t].x - mx); v[t].y = __expf(v[t].y - mx);
        v[t].z = __expf(v[t].z - mx); v[t].w = __expf(v[t].w - mx);
        s += (v[t].x + v[t].y) + (v[t].z + v[t].w);
    }
#pragma unroll
    for (int o = 16; o > 0; o >>= 1) s += __shfl_xor_sync(0xffffffffu, s, o);
    if ((tid & 31) == 0) red[tid >> 5] = s;
    __syncthreads();
    s = 0.f;
#pragma unroll
    for (int i = 0; i < 8; i++) s += red[i];
    const float inv = 1.f / s;
#pragma unroll
    for (int t = 0; t < 2; t++) {
        const int idx = (t * 256 + tid) * 4;
        *(float4*)(p + idx) = make_float4(v[t].x * inv, v[t].y * inv,
                                          v[t].z * inv, v[t].w * inv);
    }
}

// ---------------- PV: 64q x 64dh tiles, 2 CTAs/SM --------------------------
// W fp32 -> split in-kernel; V bf16 [s][64] via ldmatrix.trans.
// smem: RAW0 0, RAW1 9216, VH0 18432, VH1 23040, VL0 27648, VL1 32256,
//       WH 36864, WL 41984 (total 47104).
__global__ __launch_bounds__(256, 2) void pv_kernel(
    const float* __restrict__ Wt, const bf16* __restrict__ Vhi,
    const bf16* __restrict__ Vlo, bf16* __restrict__ Oh, bf16* __restrict__ Ol)
{
    extern __shared__ char smem[];
    const uint32_t sb = smem_u32(smem);
    const int tid = threadIdx.x, lane = tid & 31, wid = tid >> 5;
    const int warp_m = wid >> 1, warp_n = wid & 1;    // 4 x 2 warps, warp tile 16x32
    const int qt = blockIdx.x, bh = blockIdx.y;
    const uint32_t RAW0 = 0, RAW1 = 9216, VH0 = 18432, VH1 = 23040,
                   VL0 = 27648, VL1 = 32256, WH = 36864, WL = 41984;

    const float* wsrc = Wt + ((long)bh * 2048 + qt * 64) * 2048;
    const bf16* vhsrc = Vhi + (long)bh * 2048 * 64;
    const bf16* vlsrc = Vlo + (long)bh * 2048 * 64;

    auto load_chunk = [&](int buf, int ch) {
        uint32_t raw = sb + (buf ? RAW1 : RAW0);
        uint32_t vh = sb + (buf ? VH1 : VH0);
        uint32_t vl = sb + (buf ? VL1 : VL0);
        const float* wp = wsrc + ch * 32;
#pragma unroll
        for (int j = 0; j < 2; j++) {
            int idx = tid + j * 256;
            int r = idx >> 3, c = idx & 7;      // 64 rows x 8 x 16B
            cpa16(raw + r * 144 + c * 16, wp + (long)r * 2048 + c * 4);
        }
        {
            int r = tid >> 3, c = tid & 7;      // 32 rows x 8 x 16B
            cpa16(vh + r * 144 + c * 16, vhsrc + (long)(ch * 32 + r) * 64 + c * 8);
            cpa16(vl + r * 144 + c * 16, vlsrc + (long)(ch * 32 + r) * 64 + c * 8);
        }
    };

    float acc[1][4][4];
#pragma unroll
    for (int j = 0; j < 4; j++)
#pragma unroll
        for (int k = 0; k < 4; k++) acc[0][j][k] = 0.f;

    load_chunk(0, 0);
    CP_COMMIT();
    const int crow = tid >> 2, cquar = tid & 3;   // 64 rows x 4 chunks of 8 floats
    const int aoff = warp_m * 16 * 80, boff = warp_n * 32 * 2;
    for (int ch = 0; ch < 64; ch++) {
        if (ch < 63) { load_chunk((ch + 1) & 1, ch + 1); CP_COMMIT(); CP_WAIT1(); }
        else CP_WAIT0();
        __syncthreads();
        // convert raw fp32 (64x32) -> WH/WL padded bf16
        {
            const char* rp = smem + (ch & 1 ? RAW1 : RAW0) + crow * 144 + cquar * 32;
            uint32_t uh[4], ul[4];
#pragma unroll
            for (int i = 0; i < 2; i++) {
                float4 v = *(const float4*)(rp + i * 16);
                bf16 h0, l0, h1, l1;
                split1(v.x, h0, l0); split1(v.y, h1, l1);
                uh[i * 2] = pack2(h0, h1); ul[i * 2] = pack2(l0, l1);
                split1(v.z, h0, l0); split1(v.w, h1, l1);
                uh[i * 2 + 1] = pack2(h0, h1); ul[i * 2 + 1] = pack2(l0, l1);
            }
            *(uint4*)(smem + WH + crow * 80 + cquar * 16) = make_uint4(uh[0], uh[1], uh[2], uh[3]);
            *(uint4*)(smem + WL + crow * 80 + cquar * 16) = make_uint4(ul[0], ul[1], ul[2], ul[3]);
        }
        __syncthreads();
        uint32_t vh = sb + ((ch & 1) ? VH1 : VH0) + boff;
        uint32_t vl = sb + ((ch & 1) ? VL1 : VL0) + boff;
        gemm3<1, 4, 2, true>(acc, sb + WH + aoff, sb + WL + aoff, vh, vl, 80, 144, lane);
        __syncthreads();
    }

    const int b_ = bh >> 4, h = bh & 15;
#pragma unroll
    for (int nt = 0; nt < 4; nt++) {
        int s0 = qt * 64 + warp_m * 16 + (lane >> 2);
        int dh = warp_n * 32 + nt * 8 + (lane & 3) * 2;
        long a0 = ((long)b_ * 2048 + s0) * 1024 + h * 64 + dh;
        long a1 = ((long)b_ * 2048 + s0 + 8) * 1024 + h * 64 + dh;
        bf16 hh0, ll0, hh1, ll1;
        split1(acc[0][nt][0], hh0, ll0); split1(acc[0][nt][1], hh1, ll1);
        *(uint32_t*)(Oh + a0) = pack2(hh0, hh1);
        *(uint32_t*)(Ol + a0) = pack2(ll0, ll1);
        split1(acc[0][nt][2], hh0, ll0); split1(acc[0][nt][3], hh1, ll1);
        *(uint32_t*)(Oh + a1) = pack2(hh0, hh1);
        *(uint32_t*)(Ol + a1) = pack2(ll0, ll1);
    }
}

// ---------------- dense: out = A @ W^T + b (fp32 out) ----------------
__global__ __launch_bounds__(256) void dense_kernel(
    const bf16* __restrict__ Ahi, const bf16* __restrict__ Alo,
    const bf16* __restrict__ Bhi, const bf16* __restrict__ Blo,
    const float* __restrict__ bias, float* __restrict__ outD)
{
    extern __shared__ char smem[];
    const uint32_t sb = smem_u32(smem);
    const int tid = threadIdx.x, lane = tid & 31, wid = tid >> 5;
    const int warp_m = wid >> 2, warp_n = wid & 3;
    const long m0 = (long)blockIdx.y * 128, n0 = (long)blockIdx.x * 128;

    float acc[4][4][4];
#pragma unroll
    for (int i = 0; i < 4; i++)
#pragma unroll
        for (int j = 0; j < 4; j++)
#pragma unroll
            for (int k = 0; k < 4; k++) acc[i][j][k] = 0.f;

    const bf16* srcs[4] = {Ahi + m0 * 1024, Alo + m0 * 1024,
                           Bhi + n0 * 1024, Blo + n0 * 1024};
    auto load_chunk = [&](int buf, int kb) {
        uint32_t base = sb + buf * 40960;
#pragma unroll
        for (int t = 0; t < 4; t++) {
            const bf16* s = srcs[t] + kb;
            uint32_t db = base + t * 10240;
#pragma unroll
            for (int j = 0; j < 2; j++) {
                int idx = tid + j * 256;
                int r = idx >> 2, c = idx & 3;
                cpa16(db + r * 80 + c * 16, s + (long)r * 1024 + c * 8);
            }
        }
    };

    load_chunk(0, 0);
    CP_COMMIT();
    const int aoff = warp_m * 64 * 80, boff = warp_n * 32 * 80;
    for (int ch = 0; ch < 32; ch++) {
        if (ch < 31) { load_chunk((ch + 1) & 1, (ch + 1) * 32); CP_COMMIT(); CP_WAIT1(); }
        else CP_WAIT0();
        __syncthreads();
        uint32_t b = sb + (ch & 1) * 40960;
        gemm3<4, 4, 2, false>(acc, b + aoff, b + 10240 + aoff,
                              b + 20480 + boff, b + 30720 + boff, 80, 80, lane);
        __syncthreads();
    }

#pragma unroll
    for (int mt = 0; mt < 4; mt++) {
#pragma unroll
        for (int nt = 0; nt < 4; nt++) {
            int n = (int)n0 + warp_n * 32 + nt * 8 + (lane & 3) * 2;
            float bv0 = bias[n], bv1 = bias[n + 1];
            long r0 = m0 + warp_m * 64 + mt * 16 + (lane >> 2);
            *(float2*)(outD + r0 * 1024 + n) =
                make_float2(acc[mt][nt][0] + bv0, acc[mt][nt][1] + bv1);
            *(float2*)(outD + (r0 + 8) * 1024 + n) =
                make_float2(acc[mt][nt][2] + bv0, acc[mt][nt][3] + bv1);
        }
    }
}

// ---------------- host launcher ----------------
extern "C" void kernel_launch(void* const* d_in, const int* in_sizes, int n_in,
                              void* d_out, int out_size)
{
    const float* q    = (const float*)d_in[0];
    const float* k    = (const float*)d_in[1];
    const float* v    = (const float*)d_in[2];
    const int*   mask = (const int*)d_in[3];
    const float* wq_w = (const float*)d_in[4];
    const float* wq_b = (const float*)d_in[5];
    const float* wk_w = (const float*)d_in[6];
    const float* wk_b = (const float*)d_in[7];
    const float* wv_w = (const float*)d_in[8];
    const float* wv_b = (const float*)d_in[9];
    const float* dw   = (const float*)d_in[10];
    const float* db   = (const float*)d_in[11];

    float* out = (float*)d_out;
    float* wts = out + OUT_ELEMS;

    bf16 *xqh, *xql, *xkh, *xkl, *xvh, *xvl;
    bf16 *wqh, *wql, *wkh, *wkl, *wvh, *wvl, *wdh, *wdl;
    bf16 *qph, *qpl, *kph, *kpl, *vph, *vpl, *ah, *al;
    cudaGetSymbolAddress((void**)&xqh, g_xq_hi); cudaGetSymbolAddress((void**)&xql, g_xq_lo);
    cudaGetSymbolAddress((void**)&xkh, g_xk_hi); cudaGetSymbolAddress((void**)&xkl, g_xk_lo);
    cudaGetSymbolAddress((void**)&xvh, g_xv_hi); cudaGetSymbolAddress((void**)&xvl, g_xv_lo);
    cudaGetSymbolAddress((void**)&wqh, g_wq_hi); cudaGetSymbolAddress((void**)&wql, g_wq_lo);
    cudaGetSymbolAddress((void**)&wkh, g_wk_hi); cudaGetSymbolAddress((void**)&wkl, g_wk_lo);
    cudaGetSymbolAddress((void**)&wvh, g_wv_hi); cudaGetSymbolAddress((void**)&wvl, g_wv_lo);
    cudaGetSymbolAddress((void**)&wdh, g_wd_hi); cudaGetSymbolAddress((void**)&wdl, g_wd_lo);
    cudaGetSymbolAddress((void**)&qph, g_qp_hi); cudaGetSymbolAddress((void**)&qpl, g_qp_lo);
    cudaGetSymbolAddress((void**)&kph, g_kp_hi); cudaGetSymbolAddress((void**)&kpl, g_kp_lo);
    cudaGetSymbolAddress((void**)&vph, g_vp_hi); cudaGetSymbolAddress((void**)&vpl, g_vp_lo);
    cudaGetSymbolAddress((void**)&ah,  g_ah);    cudaGetSymbolAddress((void**)&al,  g_al);

    cudaFuncSetAttribute(qkv_kernel,    cudaFuncAttributeMaxDynamicSharedMemorySize, 81920);
    cudaFuncSetAttribute(dense_kernel,  cudaFuncAttributeMaxDynamicSharedMemorySize, 81920);
    cudaFuncSetAttribute(scores_kernel, cudaFuncAttributeMaxDynamicSharedMemorySize, 92160);
    cudaFuncSetAttribute(pv_kernel,     cudaFuncAttributeMaxDynamicSharedMemorySize, 47104);

    // launch 0: input splits
    Split3Args s3;
    s3.s[0] = {q, xqh, xql}; s3.s[1] = {k, xkh, xkl}; s3.s[2] = {v, xvh, xvl};
    split3_kernel<<<dim3(2048, 1, 3), 256>>>(s3);
    // launch 1: weight splits
    Split4Args s4;
    s4.s[0] = {wq_w, wqh, wql}; s4.s[1] = {wk_w, wkh, wkl};
    s4.s[2] = {wv_w, wvh, wvl}; s4.s[3] = {dw, wdh, wdl};
    split4_kernel<<<dim3(512, 1, 4), 256>>>(s4);

    // launch 2: QKV projections
    QKVArgs qa;
    qa.p[0] = {xqh, xql, wqh, wql, wq_b, qph, qpl};
    qa.p[1] = {xkh, xkl, wkh, wkl, wk_b, kph, kpl};
    qa.p[2] = {xvh, xvl, wvh, wvl, wv_b, vph, vpl};
    qkv_kernel<<<dim3(8, 32, 3), 256, 81920>>>(qa);

    // launch 3: scores (K-streaming, 64-row q tiles)
    scores_kernel<<<dim3(32, 32), 256, 92160>>>(qph, qpl, kph, kpl, wts);
    // launch 4: softmax
    softmax_kernel<<<65536, 256>>>(wts, mask);
    // launch 5: PV (ncu -s 5 -c 1 captures this one)
    pv_kernel<<<dim3(32, 32), 256, 47104>>>(wts, vph, vpl, ah, al);
    // launch 6: dense
    dense_kernel<<<dim3(8, 32), 256, 81920>>>(ah, al, wdh, wdl, db, out);
}

// round 13
// speedup vs baseline: 1.6636x; 1.0040x over previous
#include <cuda_runtime.h>
#include <cuda_bf16.h>
#include <stdint.h>
#include <math.h>

typedef __nv_bfloat16 bf16;

constexpr long OUT_ELEMS = 4194304L;   // B*S*D

// ---------------- scratch: device globals (no allocation) ----------------
__device__ __align__(256) bf16 g_xq_hi[4194304], g_xq_lo[4194304];
__device__ __align__(256) bf16 g_xk_hi[4194304], g_xk_lo[4194304];
__device__ __align__(256) bf16 g_xv_hi[4194304], g_xv_lo[4194304];
__device__ __align__(256) bf16 g_wq_hi[1048576], g_wq_lo[1048576];
__device__ __align__(256) bf16 g_wk_hi[1048576], g_wk_lo[1048576];
__device__ __align__(256) bf16 g_wv_hi[1048576], g_wv_lo[1048576];
__device__ __align__(256) bf16 g_wd_hi[1048576], g_wd_lo[1048576];
__device__ __align__(256) bf16 g_qp_hi[4194304], g_qp_lo[4194304];  // [bh][s][64]
__device__ __align__(256) bf16 g_kp_hi[4194304], g_kp_lo[4194304];
__device__ __align__(256) bf16 g_vp_hi[4194304], g_vp_lo[4194304];
__device__ __align__(256) bf16 g_ah[4194304], g_al[4194304];        // attn hi/lo [m][1024]
__device__ __align__(256) float g_stats[131072];                    // [bh*2048+q]{M, invS}

// ---------------- helpers ----------------
__device__ __forceinline__ uint32_t smem_u32(const void* p) {
    uint32_t a;
    asm("{ .reg .u64 t; cvta.to.shared.u64 t, %1; cvt.u32.u64 %0, t; }" : "=r"(a) : "l"(p));
    return a;
}
__device__ __forceinline__ void cpa16(uint32_t d, const void* g) {
    asm volatile("cp.async.cg.shared.global [%0], [%1], 16;" :: "r"(d), "l"(g));
}
#define CP_COMMIT() asm volatile("cp.async.commit_group;" ::: "memory")
#define CP_WAIT0()  asm volatile("cp.async.wait_group 0;" ::: "memory")
#define CP_WAIT1()  asm volatile("cp.async.wait_group 1;" ::: "memory")

__device__ __forceinline__ void ldm_x4(uint32_t& r0, uint32_t& r1, uint32_t& r2, uint32_t& r3, uint32_t a) {
    asm volatile("ldmatrix.sync.aligned.m8n8.x4.shared.b16 {%0,%1,%2,%3}, [%4];"
                 : "=r"(r0), "=r"(r1), "=r"(r2), "=r"(r3) : "r"(a));
}
__device__ __forceinline__ void ldm_x4t(uint32_t& r0, uint32_t& r1, uint32_t& r2, uint32_t& r3, uint32_t a) {
    asm volatile("ldmatrix.sync.aligned.m8n8.x4.trans.shared.b16 {%0,%1,%2,%3}, [%4];"
                 : "=r"(r0), "=r"(r1), "=r"(r2), "=r"(r3) : "r"(a));
}
__device__ __forceinline__ void mma16816(float* c, const uint32_t* a, const uint32_t* b) {
    asm volatile(
        "mma.sync.aligned.m16n8k16.row.col.f32.bf16.bf16.f32 "
        "{%0,%1,%2,%3}, {%4,%5,%6,%7}, {%8,%9}, {%0,%1,%2,%3};"
        : "+f"(c[0]), "+f"(c[1]), "+f"(c[2]), "+f"(c[3])
        : "r"(a[0]), "r"(a[1]), "r"(a[2]), "r"(a[3]), "r"(b[0]), "r"(b[1]));
}

__device__ __forceinline__ uint32_t pack2(bf16 a, bf16 b) {
    return (uint32_t)__bfloat16_as_ushort(a) | ((uint32_t)__bfloat16_as_ushort(b) << 16);
}
__device__ __forceinline__ void split1(float v, bf16& h, bf16& l) {
    h = __float2bfloat16_rn(v);
    l = __float2bfloat16_rn(v - __bfloat162float(h));
}

// --------------- warp-tile GEMM core (3-term compensated) ---------------
template<int MT, int NT, int NK, bool TRB>
__device__ __forceinline__ void gemm_pass(float (&acc)[MT][NT][4],
        uint32_t ab, uint32_t bb, int astr, int bstr, int lane)
{
    const int a_row = (lane & 7) + ((lane >> 3) & 1) * 8;
    const int a_k16 = (lane >> 4) * 16;
    const int b_row = (lane & 7) + (lane >> 4) * 8;
    const int b_k16 = ((lane >> 3) & 1) * 16;
    const int bt_row = (lane & 7) + ((lane >> 3) & 1) * 8;
    const int bt_col = (lane >> 4) * 8;
#pragma unroll
    for (int ks = 0; ks < NK; ks++) {
        uint32_t af[MT][4];
#pragma unroll
        for (int mt = 0; mt < MT; mt++)
            ldm_x4(af[mt][0], af[mt][1], af[mt][2], af[mt][3],
                   ab + (mt * 16 + a_row) * astr + ks * 32 + a_k16);
        uint32_t bfr[NT][2];
#pragma unroll
        for (int np = 0; np < NT / 2; np++) {
            uint32_t r0, r1, r2, r3;
            if (TRB)
                ldm_x4t(r0, r1, r2, r3, bb + (ks * 16 + bt_row) * bstr + (np * 16 + bt_col) * 2);
            else
                ldm_x4(r0, r1, r2, r3, bb + (np * 16 + b_row) * bstr + ks * 32 + b_k16);
            bfr[2*np][0] = r0; bfr[2*np][1] = r1;
            bfr[2*np+1][0] = r2; bfr[2*np+1][1] = r3;
        }
#pragma unroll
        for (int mt = 0; mt < MT; mt++)
#pragma unroll
            for (int nt = 0; nt < NT; nt++)
                mma16816(acc[mt][nt], af[mt], bfr[nt]);
    }
}

template<int MT, int NT, int NK, bool TRB>
__device__ __forceinline__ void gemm3(float (&acc)[MT][NT][4],
        uint32_t ahi, uint32_t alo, uint32_t bhi, uint32_t blo,
        int astr, int bstr, int lane)
{
    gemm_pass<MT, NT, NK, TRB>(acc, ahi, bhi, astr, bstr, lane);
    gemm_pass<MT, NT, NK, TRB>(acc, ahi, blo, astr, bstr, lane);
    gemm_pass<MT, NT, NK, TRB>(acc, alo, bhi, astr, bstr, lane);
}

// ---------------- splits: fp32 -> hi/lo bf16, z-indexed ----------------
struct SplitSet { const float* x; bf16 *hi, *lo; };
struct Split3Args { SplitSet s[3]; };
struct Split4Args { SplitSet s[4]; };

__global__ void split3_kernel(Split3Args args) {
    const SplitSet ss = args.s[blockIdx.z];
    for (long i = blockIdx.x * blockDim.x + threadIdx.x; i < 1048576; i += (long)gridDim.x * blockDim.x) {
        float4 v = *(const float4*)(ss.x + i * 4);
        bf16 h0, l0, h1, l1, h2, l2, h3, l3;
        split1(v.x, h0, l0); split1(v.y, h1, l1);
        split1(v.z, h2, l2); split1(v.w, h3, l3);
        *(uint2*)(ss.hi + i * 4) = make_uint2(pack2(h0, h1), pack2(h2, h3));
        *(uint2*)(ss.lo + i * 4) = make_uint2(pack2(l0, l1), pack2(l2, l3));
    }
}
__global__ void split4_kernel(Split4Args args) {
    const SplitSet ss = args.s[blockIdx.z];
    for (long i = blockIdx.x * blockDim.x + threadIdx.x; i < 262144; i += (long)gridDim.x * blockDim.x) {
        float4 v = *(const float4*)(ss.x + i * 4);
        bf16 h0, l0, h1, l1, h2, l2, h3, l3;
        split1(v.x, h0, l0); split1(v.y, h1, l1);
        split1(v.z, h2, l2); split1(v.w, h3, l3);
        *(uint2*)(ss.hi + i * 4) = make_uint2(pack2(h0, h1), pack2(h2, h3));
        *(uint2*)(ss.lo + i * 4) = make_uint2(pack2(l0, l1), pack2(l2, l3));
    }
}

// ---------------- QKV proj: 3 GEMMs in one launch (z selects) ----------------
struct ProjSet { const bf16 *Ah, *Al, *Bh, *Bl; const float* bias; bf16 *Ph, *Pl; };
struct QKVArgs { ProjSet p[3]; };

__global__ __launch_bounds__(256) void qkv_kernel(QKVArgs args)
{
    extern __shared__ char smem[];
    const uint32_t sb = smem_u32(smem);
    const ProjSet ps = args.p[blockIdx.z];
    const int tid = threadIdx.x, lane = tid & 31, wid = tid >> 5;
    const int warp_m = wid >> 2, warp_n = wid & 3;
    const long m0 = (long)blockIdx.y * 128, n0 = (long)blockIdx.x * 128;

    float acc[4][4][4];
#pragma unroll
    for (int i = 0; i < 4; i++)
#pragma unroll
        for (int j = 0; j < 4; j++)
#pragma unroll
            for (int k = 0; k < 4; k++) acc[i][j][k] = 0.f;

    const bf16* srcs[4] = {ps.Ah + m0 * 1024, ps.Al + m0 * 1024,
                           ps.Bh + n0 * 1024, ps.Bl + n0 * 1024};
    auto load_chunk = [&](int buf, int kb) {
        uint32_t base = sb + buf * 40960;
#pragma unroll
        for (int t = 0; t < 4; t++) {
            const bf16* s = srcs[t] + kb;
            uint32_t db = base + t * 10240;
#pragma unroll
            for (int j = 0; j < 2; j++) {
                int idx = tid + j * 256;
                int r = idx >> 2, c = idx & 3;
                cpa16(db + r * 80 + c * 16, s + (long)r * 1024 + c * 8);
            }
        }
    };

    load_chunk(0, 0);
    CP_COMMIT();
    const int aoff = warp_m * 64 * 80, boff = warp_n * 32 * 80;
    for (int ch = 0; ch < 32; ch++) {
        if (ch < 31) { load_chunk((ch + 1) & 1, (ch + 1) * 32); CP_COMMIT(); CP_WAIT1(); }
        else CP_WAIT0();
        __syncthreads();
        uint32_t b = sb + (ch & 1) * 40960;
        gemm3<4, 4, 2, false>(acc, b + aoff, b + 10240 + aoff,
                              b + 20480 + boff, b + 30720 + boff, 80, 80, lane);
        __syncthreads();
    }

#pragma unroll
    for (int mt = 0; mt < 4; mt++) {
#pragma unroll
        for (int nt = 0; nt < 4; nt++) {
            int n = (int)n0 + warp_n * 32 + nt * 8 + (lane & 3) * 2;
            float bv0 = ps.bias[n], bv1 = ps.bias[n + 1];
            long r0 = m0 + warp_m * 64 + mt * 16 + (lane >> 2);
            long r1 = r0 + 8;
            float v00 = acc[mt][nt][0] + bv0, v01 = acc[mt][nt][1] + bv1;
            float v10 = acc[mt][nt][2] + bv0, v11 = acc[mt][nt][3] + bv1;
            int h = n >> 6, dh = n & 63;
            {
                int b_ = (int)(r0 >> 11), s_ = (int)(r0 & 2047);
                long a = ((long)(b_ * 16 + h) * 2048 + s_) * 64 + dh;
                bf16 hh0, ll0, hh1, ll1;
                split1(v00, hh0, ll0); split1(v01, hh1, ll1);
                *(uint32_t*)(ps.Ph + a) = pack2(hh0, hh1);
                *(uint32_t*)(ps.Pl + a) = pack2(ll0, ll1);
            }
            {
                int b_ = (int)(r1 >> 11), s_ = (int)(r1 & 2047);
                long a = ((long)(b_ * 16 + h) * 2048 + s_) * 64 + dh;
                bf16 hh0, ll0, hh1, ll1;
                split1(v10, hh0, ll0); split1(v11, hh1, ll1);
                *(uint32_t*)(ps.Ph + a) = pack2(hh0, hh1);
                *(uint32_t*)(ps.Pl + a) = pack2(ll0, ll1);
            }
        }
    }
}

// ---------------- scores: K-streaming + mask + online softmax stats ---------
// Grid (qt=32, bh=32). Writes masked scaled raw scores + per-row (M, invS).
__global__ __launch_bounds__(256, 2) void scores_kernel(
    const bf16* __restrict__ Qhi, const bf16* __restrict__ Qlo,
    const bf16* __restrict__ Khi, const bf16* __restrict__ Klo,
    const int* __restrict__ mask, float* __restrict__ Wt,
    float* __restrict__ stats)
{
    extern __shared__ char smem[];
    __shared__ float smm[64][4], sms[64][4];
    const uint32_t sb = smem_u32(smem);
    const int tid = threadIdx.x, lane = tid & 31, wid = tid >> 5;
    const int warp_m = wid >> 2, warp_n = wid & 3;    // 2 x 4 warps, warp tile 32x32
    const int qt = blockIdx.x, bh = blockIdx.y;
    const int b_ = bh >> 4;

    const bf16* qh = Qhi + ((long)bh * 2048 + qt * 64) * 64;
    const bf16* ql = Qlo + ((long)bh * 2048 + qt * 64) * 64;
    const bf16* kh0 = Khi + (long)bh * 2048 * 64;
    const bf16* kl0 = Klo + (long)bh * 2048 * 64;

    auto load_q = [&](uint32_t dst, const bf16* src) {
#pragma unroll
        for (int j = 0; j < 2; j++) {
            int idx = tid + j * 256;
            int r = idx >> 3, c = idx & 7;
            cpa16(dst + r * 144 + c * 16, src + (long)r * 64 + c * 8);
        }
    };
    auto load_k = [&](uint32_t dst, const bf16* src) {
#pragma unroll
        for (int j = 0; j < 4; j++) {
            int idx = tid + j * 256;
            int r = idx >> 3, c = idx & 7;
            cpa16(dst + r * 144 + c * 16, src + (long)r * 64 + c * 8);
        }
    };

    load_q(sb, qh);
    load_q(sb + 9216, ql);
    load_k(sb + 18432, kh0);
    load_k(sb + 36864, kl0);
    CP_COMMIT();

    const int aoff = warp_m * 32 * 144, boff = warp_n * 32 * 144;
    float* wbase = Wt + ((long)bh * 2048 + qt * 64) * 2048;
    const int r0b = warp_m * 32 + (lane >> 2);        // base row (mt=0, hf=0)
    const int cb = warp_n * 32 + (lane & 3) * 2;      // base col

    // online softmax state: slot = mt*2 + hf  (rows r0b + mt*16 + hf*8)
    float m_run[4] = {-1e30f, -1e30f, -1e30f, -1e30f};
    float s_run[4] = {0.f, 0.f, 0.f, 0.f};

    for (int kt = 0; kt < 16; kt++) {
        if (kt < 15) {
            uint32_t kb = sb + 18432 + ((kt + 1) & 1) * 36864;
            load_k(kb, kh0 + (long)(kt + 1) * 128 * 64);
            load_k(kb + 18432, kl0 + (long)(kt + 1) * 128 * 64);
            CP_COMMIT(); CP_WAIT1();
        } else CP_WAIT0();
        __syncthreads();

        float acc[2][4][4];
#pragma unroll
        for (int i = 0; i < 2; i++)
#pragma unroll
            for (int j = 0; j < 4; j++)
#pragma unroll
                for (int k = 0; k < 4; k++) acc[i][j][k] = 0.f;

        uint32_t kbuf = sb + 18432 + (kt & 1) * 36864;
        gemm3<2, 4, 4, false>(acc, sb + aoff, sb + 9216 + aoff,
                              kbuf + boff, kbuf + 18432 + boff, 144, 144, lane);

        // mask + scale + store raw; keep masked values in acc for stats
        float* base = wbase + kt * 128;
#pragma unroll
        for (int mt = 0; mt < 2; mt++) {
#pragma unroll
            for (int nt = 0; nt < 4; nt++) {
                int r0 = r0b + mt * 16;
                int c = cb + nt * 8;
                long q0 = (long)qt * 64 + r0;
                long kk = (long)kt * 128 + c;
                const int* mrow = mask + ((long)b_ * 2048 + q0) * 2048 + kk;
                int2 mk0 = *(const int2*)mrow;
                int2 mk1 = *(const int2*)(mrow + 8 * 2048);
                float v00 = mk0.x ? acc[mt][nt][0] * 0.125f : -1e30f;
                float v01 = mk0.y ? acc[mt][nt][1] * 0.125f : -1e30f;
                float v10 = mk1.x ? acc[mt][nt][2] * 0.125f : -1e30f;
                float v11 = mk1.y ? acc[mt][nt][3] * 0.125f : -1e30f;
                acc[mt][nt][0] = v00; acc[mt][nt][1] = v01;
                acc[mt][nt][2] = v10; acc[mt][nt][3] = v11;
                *(float2*)(base + (long)r0 * 2048 + c) = make_float2(v00, v01);
                *(float2*)(base + (long)(r0 + 8) * 2048 + c) = make_float2(v10, v11);
            }
        }

        // online stats update (per thread: 4 row-slots, 8 cols each in warp quarter)
#pragma unroll
        for (int mt = 0; mt < 2; mt++) {
#pragma unroll
            for (int hf = 0; hf < 2; hf++) {
                float m = -1e30f;
#pragma unroll
                for (int nt = 0; nt < 4; nt++)
                    m = fmaxf(m, fmaxf(acc[mt][nt][hf * 2], acc[mt][nt][hf * 2 + 1]));
                m = fmaxf(m, __shfl_xor_sync(0xffffffffu, m, 1));
                m = fmaxf(m, __shfl_xor_sync(0xffffffffu, m, 2));
                float s = 0.f;
#pragma unroll
                for (int nt = 0; nt < 4; nt++)
                    s += __expf(acc[mt][nt][hf * 2] - m) + __expf(acc[mt][nt][hf * 2 + 1] - m);
                s += __shfl_xor_sync(0xffffffffu, s, 1);
                s += __shfl_xor_sync(0xffffffffu, s, 2);
                const int slot = mt * 2 + hf;
                float mo = m_run[slot];
                float mn = fmaxf(mo, m);
                s_run[slot] = s_run[slot] * __expf(mo - mn) + s * __expf(m - mn);
                m_run[slot] = mn;
            }
        }
        __syncthreads();
    }

    // cross-warp combine: each row replicated over 4 warp_n warps
    if ((lane & 3) == 0) {
#pragma unroll
        for (int slot = 0; slot < 4; slot++) {
            int row = r0b + (slot >> 1) * 16 + (slot & 1) * 8;
            smm[row][warp_n] = m_run[slot];
            sms[row][warp_n] = s_run[slot];
        }
    }
    __syncthreads();
    if (tid < 64) {
        float M = smm[tid][0];
        M = fmaxf(M, smm[tid][1]);
        M = fmaxf(M, smm[tid][2]);
        M = fmaxf(M, smm[tid][3]);
        float S = 0.f;
#pragma unroll
        for (int w = 0; w < 4; w++) S += sms[tid][w] * __expf(smm[tid][w] - M);
        long row = (long)bh * 2048 + qt * 64 + tid;
        stats[row * 2] = M;
        stats[row * 2 + 1] = 1.f / S;
    }
}

// ---------------- PV: exp+normalize inline; writes weights + attn hi/lo ------
// 64q x 64dh tiles, 2 CTAs/SM. Reads raw masked scores, p = exp(x-M)*invS.
__global__ __launch_bounds__(256, 2) void pv_kernel(
    float* __restrict__ Wt, const bf16* __restrict__ Vhi,
    const bf16* __restrict__ Vlo, const float* __restrict__ stats,
    bf16* __restrict__ Oh, bf16* __restrict__ Ol)
{
    extern __shared__ char smem[];
    __shared__ float st[64][2];
    const uint32_t sb = smem_u32(smem);
    const int tid = threadIdx.x, lane = tid & 31, wid = tid >> 5;
    const int warp_m = wid >> 1, warp_n = wid & 1;    // 4 x 2 warps
    const int qt = blockIdx.x, bh = blockIdx.y;
    const uint32_t RAW0 = 0, RAW1 = 9216, VH0 = 18432, VH1 = 23040,
                   VL0 = 27648, VL1 = 32256, WH = 36864, WL = 41984;

    if (tid < 64) {
        long row = (long)bh * 2048 + qt * 64 + tid;
        st[tid][0] = stats[row * 2];
        st[tid][1] = stats[row * 2 + 1];
    }

    float* wsrc = Wt + ((long)bh * 2048 + qt * 64) * 2048;
    const bf16* vhsrc = Vhi + (long)bh * 2048 * 64;
    const bf16* vlsrc = Vlo + (long)bh * 2048 * 64;

    auto load_chunk = [&](int buf, int ch) {
        uint32_t raw = sb + (buf ? RAW1 : RAW0);
        uint32_t vh = sb + (buf ? VH1 : VH0);
        uint32_t vl = sb + (buf ? VL1 : VL0);
        const float* wp = wsrc + ch * 32;
#pragma unroll
        for (int j = 0; j < 2; j++) {
            int idx = tid + j * 256;
            int r = idx >> 3, c = idx & 7;      // 64 rows x 8 x 16B
            cpa16(raw + r * 144 + c * 16, wp + (long)r * 2048 + c * 4);
        }
        {
            int r = tid >> 3, c = tid & 7;      // 32 rows x 8 x 16B
            cpa16(vh + r * 144 + c * 16, vhsrc + (long)(ch * 32 + r) * 64 + c * 8);
            cpa16(vl + r * 144 + c * 16, vlsrc + (long)(ch * 32 + r) * 64 + c * 8);
        }
    };

    float acc[1][4][4];
#pragma unroll
    for (int j = 0; j < 4; j++)
#pragma unroll
        for (int k = 0; k < 4; k++) acc[0][j][k] = 0.f;

    load_chunk(0, 0);
    CP_COMMIT();
    __syncthreads();   // st[] visible
    const int crow = tid >> 2, cquar = tid & 3;   // 64 rows x 4 chunks of 8 floats
    const float M = st[crow][0], invS = st[crow][1];
    const int aoff = warp_m * 16 * 80, boff = warp_n * 32 * 2;

    for (int ch = 0; ch < 64; ch++) {
        if (ch < 63) { load_chunk((ch + 1) & 1, ch + 1); CP_COMMIT(); CP_WAIT1(); }
        else CP_WAIT0();
        __syncthreads();
        // convert raw fp32 (64x32) -> p = exp(x-M)*invS; write final weights;
        // split p into WH/WL padded bf16 for the MMA
        {
            const char* rp = smem + (ch & 1 ? RAW1 : RAW0) + crow * 144 + cquar * 32;
            float* wout = wsrc + (long)crow * 2048 + ch * 32 + cquar * 8;
            uint32_t uh[4], ul[4];
#pragma unroll
            for (int i = 0; i < 2; i++) {
                float4 v = *(const float4*)(rp + i * 16);
                v.x = __expf(v.x - M) * invS;
                v.y = __expf(v.y - M) * invS;
                v.z = __expf(v.z - M) * invS;
                v.w = __expf(v.w - M) * invS;
                *(float4*)(wout + i * 4) = v;
                bf16 h0, l0, h1, l1;
                split1(v.x, h0, l0); split1(v.y, h1, l1);
                uh[i * 2] = pack2(h0, h1); ul[i * 2] = pack2(l0, l1);
                split1(v.z, h0, l0); split1(v.w, h1, l1);
                uh[i * 2 + 1] = pack2(h0, h1); ul[i * 2 + 1] = pack2(l0, l1);
            }
            *(uint4*)(smem + WH + crow * 80 + cquar * 16) = make_uint4(uh[0], uh[1], uh[2], uh[3]);
            *(uint4*)(smem + WL + crow * 80 + cquar * 16) = make_uint4(ul[0], ul[1], ul[2], ul[3]);
        }
        __syncthreads();
        uint32_t vh = sb + ((ch & 1) ? VH1 : VH0) + boff;
        uint32_t vl = sb + ((ch & 1) ? VL1 : VL0) + boff;
        gemm3<1, 4, 2, true>(acc, sb + WH + aoff, sb + WL + aoff, vh, vl, 80, 144, lane);
        __syncthreads();
    }

    const int b_ = bh >> 4, h = bh & 15;
#pragma unroll
    for (int nt = 0; nt < 4; nt++) {
        int s0 = qt * 64 + warp_m * 16 + (lane >> 2);
        int dh = warp_n * 32 + nt * 8 + (lane & 3) * 2;
        long a0 = ((long)b_ * 2048 + s0) * 1024 + h * 64 + dh;
        long a1 = ((long)b_ * 2048 + s0 + 8) * 1024 + h * 64 + dh;
        bf16 hh0, ll0, hh1, ll1;
        split1(acc[0][nt][0], hh0, ll0); split1(acc[0][nt][1], hh1, ll1);
        *(uint32_t*)(Oh + a0) = pack2(hh0, hh1);
        *(uint32_t*)(Ol + a0) = pack2(ll0, ll1);
        split1(acc[0][nt][2], hh0, ll0); split1(acc[0][nt][3], hh1, ll1);
        *(uint32_t*)(Oh + a1) = pack2(hh0, hh1);
        *(uint32_t*)(Ol + a1) = pack2(ll0, ll1);
    }
}

// ---------------- dense: out = A @ W^T + b (fp32 out) ----------------
__global__ __launch_bounds__(256) void dense_kernel(
    const bf16* __restrict__ Ahi, const bf16* __restrict__ Alo,
    const bf16* __restrict__ Bhi, const bf16* __restrict__ Blo,
    const float* __restrict__ bias, float* __restrict__ outD)
{
    extern __shared__ char smem[];
    const uint32_t sb = smem_u32(smem);
    const int tid = threadIdx.x, lane = tid & 31, wid = tid >> 5;
    const int warp_m = wid >> 2, warp_n = wid & 3;
    const long m0 = (long)blockIdx.y * 128, n0 = (long)blockIdx.x * 128;

    float acc[4][4][4];
#pragma unroll
    for (int i = 0; i < 4; i++)
#pragma unroll
        for (int j = 0; j < 4; j++)
#pragma unroll
            for (int k = 0; k < 4; k++) acc[i][j][k] = 0.f;

    const bf16* srcs[4] = {Ahi + m0 * 1024, Alo + m0 * 1024,
                           Bhi + n0 * 1024, Blo + n0 * 1024};
    auto load_chunk = [&](int buf, int kb) {
        uint32_t base = sb + buf * 40960;
#pragma unroll
        for (int t = 0; t < 4; t++) {
            const bf16* s = srcs[t] + kb;
            uint32_t db = base + t * 10240;
#pragma unroll
            for (int j = 0; j < 2; j++) {
                int idx = tid + j * 256;
                int r = idx >> 2, c = idx & 3;
                cpa16(db + r * 80 + c * 16, s + (long)r * 1024 + c * 8);
            }
        }
    };

    load_chunk(0, 0);
    CP_COMMIT();
    const int aoff = warp_m * 64 * 80, boff = warp_n * 32 * 80;
    for (int ch = 0; ch < 32; ch++) {
        if (ch < 31) { load_chunk((ch + 1) & 1, (ch + 1) * 32); CP_COMMIT(); CP_WAIT1(); }
        else CP_WAIT0();
        __syncthreads();
        uint32_t b = sb + (ch & 1) * 40960;
        gemm3<4, 4, 2, false>(acc, b + aoff, b + 10240 + aoff,
                              b + 20480 + boff, b + 30720 + boff, 80, 80, lane);
        __syncthreads();
    }

#pragma unroll
    for (int mt = 0; mt < 4; mt++) {
#pragma unroll
        for (int nt = 0; nt < 4; nt++) {
            int n = (int)n0 + warp_n * 32 + nt * 8 + (lane & 3) * 2;
            float bv0 = bias[n], bv1 = bias[n + 1];
            long r0 = m0 + warp_m * 64 + mt * 16 + (lane >> 2);
            *(float2*)(outD + r0 * 1024 + n) =
                make_float2(acc[mt][nt][0] + bv0, acc[mt][nt][1] + bv1);
            *(float2*)(outD + (r0 + 8) * 1024 + n) =
                make_float2(acc[mt][nt][2] + bv0, acc[mt][nt][3] + bv1);
        }
    }
}

// ---------------- host launcher ----------------
extern "C" void kernel_launch(void* const* d_in, const int* in_sizes, int n_in,
                              void* d_out, int out_size)
{
    const float* q    = (const float*)d_in[0];
    const float* k    = (const float*)d_in[1];
    const float* v    = (const float*)d_in[2];
    const int*   mask = (const int*)d_in[3];
    const float* wq_w = (const float*)d_in[4];
    const float* wq_b = (const float*)d_in[5];
    const float* wk_w = (const float*)d_in[6];
    const float* wk_b = (const float*)d_in[7];
    const float* wv_w = (const float*)d_in[8];
    const float* wv_b = (const float*)d_in[9];
    const float* dw   = (const float*)d_in[10];
    const float* db   = (const float*)d_in[11];

    float* out = (float*)d_out;
    float* wts = out + OUT_ELEMS;

    bf16 *xqh, *xql, *xkh, *xkl, *xvh, *xvl;
    bf16 *wqh, *wql, *wkh, *wkl, *wvh, *wvl, *wdh, *wdl;
    bf16 *qph, *qpl, *kph, *kpl, *vph, *vpl, *ah, *al;
    float* stats;
    cudaGetSymbolAddress((void**)&xqh, g_xq_hi); cudaGetSymbolAddress((void**)&xql, g_xq_lo);
    cudaGetSymbolAddress((void**)&xkh, g_xk_hi); cudaGetSymbolAddress((void**)&xkl, g_xk_lo);
    cudaGetSymbolAddress((void**)&xvh, g_xv_hi); cudaGetSymbolAddress((void**)&xvl, g_xv_lo);
    cudaGetSymbolAddress((void**)&wqh, g_wq_hi); cudaGetSymbolAddress((void**)&wql, g_wq_lo);
    cudaGetSymbolAddress((void**)&wkh, g_wk_hi); cudaGetSymbolAddress((void**)&wkl, g_wk_lo);
    cudaGetSymbolAddress((void**)&wvh, g_wv_hi); cudaGetSymbolAddress((void**)&wvl, g_wv_lo);
    cudaGetSymbolAddress((void**)&wdh, g_wd_hi); cudaGetSymbolAddress((void**)&wdl, g_wd_lo);
    cudaGetSymbolAddress((void**)&qph, g_qp_hi); cudaGetSymbolAddress((void**)&qpl, g_qp_lo);
    cudaGetSymbolAddress((void**)&kph, g_kp_hi); cudaGetSymbolAddress((void**)&kpl, g_kp_lo);
    cudaGetSymbolAddress((void**)&vph, g_vp_hi); cudaGetSymbolAddress((void**)&vpl, g_vp_lo);
    cudaGetSymbolAddress((void**)&ah,  g_ah);    cudaGetSymbolAddress((void**)&al,  g_al);
    cudaGetSymbolAddress((void**)&stats, g_stats);

    cudaFuncSetAttribute(qkv_kernel,    cudaFuncAttributeMaxDynamicSharedMemorySize, 81920);
    cudaFuncSetAttribute(dense_kernel,  cudaFuncAttributeMaxDynamicSharedMemorySize, 81920);
    cudaFuncSetAttribute(scores_kernel, cudaFuncAttributeMaxDynamicSharedMemorySize, 92160);
    cudaFuncSetAttribute(pv_kernel,     cudaFuncAttributeMaxDynamicSharedMemorySize, 47104);

    // launch 0: input splits
    Split3Args s3;
    s3.s[0] = {q, xqh, xql}; s3.s[1] = {k, xkh, xkl}; s3.s[2] = {v, xvh, xvl};
    split3_kernel<<<dim3(2048, 1, 3), 256>>>(s3);
    // launch 1: weight splits
    Split4Args s4;
    s4.s[0] = {wq_w, wqh, wql}; s4.s[1] = {wk_w, wkh, wkl};
    s4.s[2] = {wv_w, wvh, wvl}; s4.s[3] = {dw, wdh, wdl};
    split4_kernel<<<dim3(512, 1, 4), 256>>>(s4);

    // launch 2: QKV projections
    QKVArgs qa;
    qa.p[0] = {xqh, xql, wqh, wql, wq_b, qph, qpl};
    qa.p[1] = {xkh, xkl, wkh, wkl, wk_b, kph, kpl};
    qa.p[2] = {xvh, xvl, wvh, wvl, wv_b, vph, vpl};
    qkv_kernel<<<dim3(8, 32, 3), 256, 81920>>>(qa);

    // launch 3: scores (mask + raw scores + online stats)
    scores_kernel<<<dim3(32, 32), 256, 92160>>>(qph, qpl, kph, kpl, mask, wts, stats);
    // launch 4: PV (exp + normalize + final weights + attn)
    pv_kernel<<<dim3(32, 32), 256, 47104>>>(wts, vph, vpl, stats, ah, al);
    // launch 5: dense
    dense_kernel<<<dim3(8, 32), 256, 81920>>>(ah, al, wdh, wdl, db, out);
}

// round 14
// speedup vs baseline: 1.7221x; 1.0352x over previous
#include <cuda_runtime.h>
#include <cuda_bf16.h>
#include <stdint.h>
#include <math.h>

typedef __nv_bfloat16 bf16;

constexpr long OUT_ELEMS = 4194304L;   // B*S*D

// ---------------- scratch: device globals (no allocation) ----------------
__device__ __align__(256) bf16 g_xq_hi[4194304], g_xq_lo[4194304];
__device__ __align__(256) bf16 g_xk_hi[4194304], g_xk_lo[4194304];
__device__ __align__(256) bf16 g_xv_hi[4194304], g_xv_lo[4194304];
__device__ __align__(256) bf16 g_wq_hi[1048576], g_wq_lo[1048576];
__device__ __align__(256) bf16 g_wk_hi[1048576], g_wk_lo[1048576];
__device__ __align__(256) bf16 g_wv_hi[1048576], g_wv_lo[1048576];
__device__ __align__(256) bf16 g_wd_hi[1048576], g_wd_lo[1048576];
__device__ __align__(256) bf16 g_qp_hi[4194304], g_qp_lo[4194304];  // [bh][s][64]
__device__ __align__(256) bf16 g_kp_hi[4194304], g_kp_lo[4194304];
__device__ __align__(256) bf16 g_vp_hi[4194304], g_vp_lo[4194304];
__device__ __align__(256) bf16 g_ah[4194304], g_al[4194304];        // attn hi/lo [m][1024]
__device__ __align__(256) float g_stats[131072];                    // [bh*2048+q]{M, invS}
__device__ __align__(256) uint32_t g_pm[262144];                    // packed mask bits [b*2048+q][64]

// ---------------- helpers ----------------
__device__ __forceinline__ uint32_t smem_u32(const void* p) {
    uint32_t a;
    asm("{ .reg .u64 t; cvta.to.shared.u64 t, %1; cvt.u32.u64 %0, t; }" : "=r"(a) : "l"(p));
    return a;
}
__device__ __forceinline__ void cpa16(uint32_t d, const void* g) {
    asm volatile("cp.async.cg.shared.global [%0], [%1], 16;" :: "r"(d), "l"(g));
}
#define CP_COMMIT() asm volatile("cp.async.commit_group;" ::: "memory")
#define CP_WAIT0()  asm volatile("cp.async.wait_group 0;" ::: "memory")
#define CP_WAIT1()  asm volatile("cp.async.wait_group 1;" ::: "memory")

__device__ __forceinline__ void ldm_x4(uint32_t& r0, uint32_t& r1, uint32_t& r2, uint32_t& r3, uint32_t a) {
    asm volatile("ldmatrix.sync.aligned.m8n8.x4.shared.b16 {%0,%1,%2,%3}, [%4];"
                 : "=r"(r0), "=r"(r1), "=r"(r2), "=r"(r3) : "r"(a));
}
__device__ __forceinline__ void ldm_x4t(uint32_t& r0, uint32_t& r1, uint32_t& r2, uint32_t& r3, uint32_t a) {
    asm volatile("ldmatrix.sync.aligned.m8n8.x4.trans.shared.b16 {%0,%1,%2,%3}, [%4];"
                 : "=r"(r0), "=r"(r1), "=r"(r2), "=r"(r3) : "r"(a));
}
__device__ __forceinline__ void mma16816(float* c, const uint32_t* a, const uint32_t* b) {
    asm volatile(
        "mma.sync.aligned.m16n8k16.row.col.f32.bf16.bf16.f32 "
        "{%0,%1,%2,%3}, {%4,%5,%6,%7}, {%8,%9}, {%0,%1,%2,%3};"
        : "+f"(c[0]), "+f"(c[1]), "+f"(c[2]), "+f"(c[3])
        : "r"(a[0]), "r"(a[1]), "r"(a[2]), "r"(a[3]), "r"(b[0]), "r"(b[1]));
}

__device__ __forceinline__ uint32_t pack2(bf16 a, bf16 b) {
    return (uint32_t)__bfloat16_as_ushort(a) | ((uint32_t)__bfloat16_as_ushort(b) << 16);
}
__device__ __forceinline__ void split1(float v, bf16& h, bf16& l) {
    h = __float2bfloat16_rn(v);
    l = __float2bfloat16_rn(v - __bfloat162float(h));
}

// --------------- warp-tile GEMM core (3-term compensated) ---------------
template<int MT, int NT, int NK, bool TRB>
__device__ __forceinline__ void gemm_pass(float (&acc)[MT][NT][4],
        uint32_t ab, uint32_t bb, int astr, int bstr, int lane)
{
    const int a_row = (lane & 7) + ((lane >> 3) & 1) * 8;
    const int a_k16 = (lane >> 4) * 16;
    const int b_row = (lane & 7) + (lane >> 4) * 8;
    const int b_k16 = ((lane >> 3) & 1) * 16;
    const int bt_row = (lane & 7) + ((lane >> 3) & 1) * 8;
    const int bt_col = (lane >> 4) * 8;
#pragma unroll
    for (int ks = 0; ks < NK; ks++) {
        uint32_t af[MT][4];
#pragma unroll
        for (int mt = 0; mt < MT; mt++)
            ldm_x4(af[mt][0], af[mt][1], af[mt][2], af[mt][3],
                   ab + (mt * 16 + a_row) * astr + ks * 32 + a_k16);
        uint32_t bfr[NT][2];
#pragma unroll
        for (int np = 0; np < NT / 2; np++) {
            uint32_t r0, r1, r2, r3;
            if (TRB)
                ldm_x4t(r0, r1, r2, r3, bb + (ks * 16 + bt_row) * bstr + (np * 16 + bt_col) * 2);
            else
                ldm_x4(r0, r1, r2, r3, bb + (np * 16 + b_row) * bstr + ks * 32 + b_k16);
            bfr[2*np][0] = r0; bfr[2*np][1] = r1;
            bfr[2*np+1][0] = r2; bfr[2*np+1][1] = r3;
        }
#pragma unroll
        for (int mt = 0; mt < MT; mt++)
#pragma unroll
            for (int nt = 0; nt < NT; nt++)
                mma16816(acc[mt][nt], af[mt], bfr[nt]);
    }
}

template<int MT, int NT, int NK, bool TRB>
__device__ __forceinline__ void gemm3(float (&acc)[MT][NT][4],
        uint32_t ahi, uint32_t alo, uint32_t bhi, uint32_t blo,
        int astr, int bstr, int lane)
{
    gemm_pass<MT, NT, NK, TRB>(acc, ahi, bhi, astr, bstr, lane);
    gemm_pass<MT, NT, NK, TRB>(acc, ahi, blo, astr, bstr, lane);
    gemm_pass<MT, NT, NK, TRB>(acc, alo, bhi, astr, bstr, lane);
}

// ---------------- splits: fp32 -> hi/lo bf16, z-indexed ----------------
struct SplitSet { const float* x; bf16 *hi, *lo; };
struct Split3Args { SplitSet s[3]; };
struct Split4Args { SplitSet s[4]; };

__global__ void split3_kernel(Split3Args args) {
    const SplitSet ss = args.s[blockIdx.z];
    for (long i = blockIdx.x * blockDim.x + threadIdx.x; i < 1048576; i += (long)gridDim.x * blockDim.x) {
        float4 v = *(const float4*)(ss.x + i * 4);
        bf16 h0, l0, h1, l1, h2, l2, h3, l3;
        split1(v.x, h0, l0); split1(v.y, h1, l1);
        split1(v.z, h2, l2); split1(v.w, h3, l3);
        *(uint2*)(ss.hi + i * 4) = make_uint2(pack2(h0, h1), pack2(h2, h3));
        *(uint2*)(ss.lo + i * 4) = make_uint2(pack2(l0, l1), pack2(l2, l3));
    }
}
__global__ void split4_kernel(Split4Args args) {
    const SplitSet ss = args.s[blockIdx.z];
    for (long i = blockIdx.x * blockDim.x + threadIdx.x; i < 262144; i += (long)gridDim.x * blockDim.x) {
        float4 v = *(const float4*)(ss.x + i * 4);
        bf16 h0, l0, h1, l1, h2, l2, h3, l3;
        split1(v.x, h0, l0); split1(v.y, h1, l1);
        split1(v.z, h2, l2); split1(v.w, h3, l3);
        *(uint2*)(ss.hi + i * 4) = make_uint2(pack2(h0, h1), pack2(h2, h3));
        *(uint2*)(ss.lo + i * 4) = make_uint2(pack2(l0, l1), pack2(l2, l3));
    }
}

// ---------------- pack mask into bits: pm[b*2048+q][w], bit = k%32 ----------
__global__ void pack_mask_kernel(const int* __restrict__ mask, uint32_t* __restrict__ pm) {
    long idx = (long)blockIdx.x * 256 + threadIdx.x;   // 0..262143
    const int* src = mask + idx * 32;
    uint32_t bits = 0;
#pragma unroll
    for (int i = 0; i < 8; i++) {
        int4 m4 = *(const int4*)(src + i * 4);
        bits |= (m4.x ? 1u : 0u) << (i * 4);
        bits |= (m4.y ? 1u : 0u) << (i * 4 + 1);
        bits |= (m4.z ? 1u : 0u) << (i * 4 + 2);
        bits |= (m4.w ? 1u : 0u) << (i * 4 + 3);
    }
    pm[idx] = bits;
}

// ---------------- QKV proj: 3 GEMMs in one launch (z selects) ----------------
struct ProjSet { const bf16 *Ah, *Al, *Bh, *Bl; const float* bias; bf16 *Ph, *Pl; };
struct QKVArgs { ProjSet p[3]; };

__global__ __launch_bounds__(256) void qkv_kernel(QKVArgs args)
{
    extern __shared__ char smem[];
    const uint32_t sb = smem_u32(smem);
    const ProjSet ps = args.p[blockIdx.z];
    const int tid = threadIdx.x, lane = tid & 31, wid = tid >> 5;
    const int warp_m = wid >> 2, warp_n = wid & 3;
    const long m0 = (long)blockIdx.y * 128, n0 = (long)blockIdx.x * 128;

    float acc[4][4][4];
#pragma unroll
    for (int i = 0; i < 4; i++)
#pragma unroll
        for (int j = 0; j < 4; j++)
#pragma unroll
            for (int k = 0; k < 4; k++) acc[i][j][k] = 0.f;

    const bf16* srcs[4] = {ps.Ah + m0 * 1024, ps.Al + m0 * 1024,
                           ps.Bh + n0 * 1024, ps.Bl + n0 * 1024};
    auto load_chunk = [&](int buf, int kb) {
        uint32_t base = sb + buf * 40960;
#pragma unroll
        for (int t = 0; t < 4; t++) {
            const bf16* s = srcs[t] + kb;
            uint32_t db = base + t * 10240;
#pragma unroll
            for (int j = 0; j < 2; j++) {
                int idx = tid + j * 256;
                int r = idx >> 2, c = idx & 3;
                cpa16(db + r * 80 + c * 16, s + (long)r * 1024 + c * 8);
            }
        }
    };

    load_chunk(0, 0);
    CP_COMMIT();
    const int aoff = warp_m * 64 * 80, boff = warp_n * 32 * 80;
    for (int ch = 0; ch < 32; ch++) {
        if (ch < 31) { load_chunk((ch + 1) & 1, (ch + 1) * 32); CP_COMMIT(); CP_WAIT1(); }
        else CP_WAIT0();
        __syncthreads();
        uint32_t b = sb + (ch & 1) * 40960;
        gemm3<4, 4, 2, false>(acc, b + aoff, b + 10240 + aoff,
                              b + 20480 + boff, b + 30720 + boff, 80, 80, lane);
        __syncthreads();
    }

#pragma unroll
    for (int mt = 0; mt < 4; mt++) {
#pragma unroll
        for (int nt = 0; nt < 4; nt++) {
            int n = (int)n0 + warp_n * 32 + nt * 8 + (lane & 3) * 2;
            float bv0 = ps.bias[n], bv1 = ps.bias[n + 1];
            long r0 = m0 + warp_m * 64 + mt * 16 + (lane >> 2);
            long r1 = r0 + 8;
            float v00 = acc[mt][nt][0] + bv0, v01 = acc[mt][nt][1] + bv1;
            float v10 = acc[mt][nt][2] + bv0, v11 = acc[mt][nt][3] + bv1;
            int h = n >> 6, dh = n & 63;
            {
                int b_ = (int)(r0 >> 11), s_ = (int)(r0 & 2047);
                long a = ((long)(b_ * 16 + h) * 2048 + s_) * 64 + dh;
                bf16 hh0, ll0, hh1, ll1;
                split1(v00, hh0, ll0); split1(v01, hh1, ll1);
                *(uint32_t*)(ps.Ph + a) = pack2(hh0, hh1);
                *(uint32_t*)(ps.Pl + a) = pack2(ll0, ll1);
            }
            {
                int b_ = (int)(r1 >> 11), s_ = (int)(r1 & 2047);
                long a = ((long)(b_ * 16 + h) * 2048 + s_) * 64 + dh;
                bf16 hh0, ll0, hh1, ll1;
                split1(v10, hh0, ll0); split1(v11, hh1, ll1);
                *(uint32_t*)(ps.Ph + a) = pack2(hh0, hh1);
                *(uint32_t*)(ps.Pl + a) = pack2(ll0, ll1);
            }
        }
    }
}

// ---------------- scores: K-streaming + bitmask + online softmax stats -------
// Grid (qt=32, bh=32). Writes masked scaled raw scores + per-row (M, invS).
__global__ __launch_bounds__(256, 2) void scores_kernel(
    const bf16* __restrict__ Qhi, const bf16* __restrict__ Qlo,
    const bf16* __restrict__ Khi, const bf16* __restrict__ Klo,
    const uint32_t* __restrict__ pm, float* __restrict__ Wt,
    float* __restrict__ stats)
{
    extern __shared__ char smem[];
    __shared__ float smm[64][4], sms[64][4];
    const uint32_t sb = smem_u32(smem);
    const int tid = threadIdx.x, lane = tid & 31, wid = tid >> 5;
    const int warp_m = wid >> 2, warp_n = wid & 3;    // 2 x 4 warps, warp tile 32x32
    const int qt = blockIdx.x, bh = blockIdx.y;
    const int b_ = bh >> 4;

    const bf16* qh = Qhi + ((long)bh * 2048 + qt * 64) * 64;
    const bf16* ql = Qlo + ((long)bh * 2048 + qt * 64) * 64;
    const bf16* kh0 = Khi + (long)bh * 2048 * 64;
    const bf16* kl0 = Klo + (long)bh * 2048 * 64;

    auto load_q = [&](uint32_t dst, const bf16* src) {
#pragma unroll
        for (int j = 0; j < 2; j++) {
            int idx = tid + j * 256;
            int r = idx >> 3, c = idx & 7;
            cpa16(dst + r * 144 + c * 16, src + (long)r * 64 + c * 8);
        }
    };
    auto load_k = [&](uint32_t dst, const bf16* src) {
#pragma unroll
        for (int j = 0; j < 4; j++) {
            int idx = tid + j * 256;
            int r = idx >> 3, c = idx & 7;
            cpa16(dst + r * 144 + c * 16, src + (long)r * 64 + c * 8);
        }
    };

    load_q(sb, qh);
    load_q(sb + 9216, ql);
    load_k(sb + 18432, kh0);
    load_k(sb + 36864, kl0);
    CP_COMMIT();

    const int aoff = warp_m * 32 * 144, boff = warp_n * 32 * 144;
    float* wbase = Wt + ((long)bh * 2048 + qt * 64) * 2048;
    const int r0b = warp_m * 32 + (lane >> 2);        // base row (mt=0, hf=0)
    const int cb = warp_n * 32 + (lane & 3) * 2;      // base col
    const int bsel = (lane & 3) * 2;                  // bit base within 32-col span
    // packed-mask base for this CTA's rows; word = kt*4 + warp_n
    const uint32_t* pmb = pm + ((long)b_ * 2048 + qt * 64) * 64 + warp_n;

    // online softmax state: slot = mt*2 + hf  (rows r0b + mt*16 + hf*8)
    float m_run[4] = {-1e30f, -1e30f, -1e30f, -1e30f};
    float s_run[4] = {0.f, 0.f, 0.f, 0.f};

    for (int kt = 0; kt < 16; kt++) {
        if (kt < 15) {
            uint32_t kb = sb + 18432 + ((kt + 1) & 1) * 36864;
            load_k(kb, kh0 + (long)(kt + 1) * 128 * 64);
            load_k(kb + 18432, kl0 + (long)(kt + 1) * 128 * 64);
            CP_COMMIT(); CP_WAIT1();
        } else CP_WAIT0();
        __syncthreads();

        float acc[2][4][4];
#pragma unroll
        for (int i = 0; i < 2; i++)
#pragma unroll
            for (int j = 0; j < 4; j++)
#pragma unroll
                for (int k = 0; k < 4; k++) acc[i][j][k] = 0.f;

        uint32_t kbuf = sb + 18432 + (kt & 1) * 36864;
        gemm3<2, 4, 4, false>(acc, sb + aoff, sb + 9216 + aoff,
                              kbuf + boff, kbuf + 18432 + boff, 144, 144, lane);

        // bitmask + scale + store; keep masked values in acc for stats
        float* base = wbase + kt * 128;
#pragma unroll
        for (int mt = 0; mt < 2; mt++) {
            const int r0 = r0b + mt * 16;
            const uint32_t mw0 = pmb[(long)r0 * 64 + kt * 4];
            const uint32_t mw1 = pmb[(long)(r0 + 8) * 64 + kt * 4];
#pragma unroll
            for (int nt = 0; nt < 4; nt++) {
                const int bit = nt * 8 + bsel;
                const int c = cb + nt * 8;
                float v00 = (mw0 >> bit) & 1u ? acc[mt][nt][0] * 0.125f : -1e30f;
                float v01 = (mw0 >> (bit + 1)) & 1u ? acc[mt][nt][1] * 0.125f : -1e30f;
                float v10 = (mw1 >> bit) & 1u ? acc[mt][nt][2] * 0.125f : -1e30f;
                float v11 = (mw1 >> (bit + 1)) & 1u ? acc[mt][nt][3] * 0.125f : -1e30f;
                acc[mt][nt][0] = v00; acc[mt][nt][1] = v01;
                acc[mt][nt][2] = v10; acc[mt][nt][3] = v11;
                *(float2*)(base + (long)r0 * 2048 + c) = make_float2(v00, v01);
                *(float2*)(base + (long)(r0 + 8) * 2048 + c) = make_float2(v10, v11);
            }
        }

        // online stats update (per thread: 4 row-slots, 8 cols each in warp quarter)
#pragma unroll
        for (int mt = 0; mt < 2; mt++) {
#pragma unroll
            for (int hf = 0; hf < 2; hf++) {
                float m = -1e30f;
#pragma unroll
                for (int nt = 0; nt < 4; nt++)
                    m = fmaxf(m, fmaxf(acc[mt][nt][hf * 2], acc[mt][nt][hf * 2 + 1]));
                m = fmaxf(m, __shfl_xor_sync(0xffffffffu, m, 1));
                m = fmaxf(m, __shfl_xor_sync(0xffffffffu, m, 2));
                float s = 0.f;
#pragma unroll
                for (int nt = 0; nt < 4; nt++)
                    s += __expf(acc[mt][nt][hf * 2] - m) + __expf(acc[mt][nt][hf * 2 + 1] - m);
                s += __shfl_xor_sync(0xffffffffu, s, 1);
                s += __shfl_xor_sync(0xffffffffu, s, 2);
                const int slot = mt * 2 + hf;
                float mo = m_run[slot];
                float mn = fmaxf(mo, m);
                s_run[slot] = s_run[slot] * __expf(mo - mn) + s * __expf(m - mn);
                m_run[slot] = mn;
            }
        }
        __syncthreads();
    }

    // cross-warp combine: each row replicated over 4 warp_n warps
    if ((lane & 3) == 0) {
#pragma unroll
        for (int slot = 0; slot < 4; slot++) {
            int row = r0b + (slot >> 1) * 16 + (slot & 1) * 8;
            smm[row][warp_n] = m_run[slot];
            sms[row][warp_n] = s_run[slot];
        }
    }
    __syncthreads();
    if (tid < 64) {
        float M = smm[tid][0];
        M = fmaxf(M, smm[tid][1]);
        M = fmaxf(M, smm[tid][2]);
        M = fmaxf(M, smm[tid][3]);
        float S = 0.f;
#pragma unroll
        for (int w = 0; w < 4; w++) S += sms[tid][w] * __expf(smm[tid][w] - M);
        long row = (long)bh * 2048 + qt * 64 + tid;
        stats[row * 2] = M;
        stats[row * 2 + 1] = 1.f / S;
    }
}

// ---------------- PV: exp+normalize inline; writes weights + attn hi/lo ------
__global__ __launch_bounds__(256, 2) void pv_kernel(
    float* __restrict__ Wt, const bf16* __restrict__ Vhi,
    const bf16* __restrict__ Vlo, const float* __restrict__ stats,
    bf16* __restrict__ Oh, bf16* __restrict__ Ol)
{
    extern __shared__ char smem[];
    __shared__ float st[64][2];
    const uint32_t sb = smem_u32(smem);
    const int tid = threadIdx.x, lane = tid & 31, wid = tid >> 5;
    const int warp_m = wid >> 1, warp_n = wid & 1;    // 4 x 2 warps
    const int qt = blockIdx.x, bh = blockIdx.y;
    const uint32_t RAW0 = 0, RAW1 = 9216, VH0 = 18432, VH1 = 23040,
                   VL0 = 27648, VL1 = 32256, WH = 36864, WL = 41984;

    if (tid < 64) {
        long row = (long)bh * 2048 + qt * 64 + tid;
        st[tid][0] = stats[row * 2];
        st[tid][1] = stats[row * 2 + 1];
    }

    float* wsrc = Wt + ((long)bh * 2048 + qt * 64) * 2048;
    const bf16* vhsrc = Vhi + (long)bh * 2048 * 64;
    const bf16* vlsrc = Vlo + (long)bh * 2048 * 64;

    auto load_chunk = [&](int buf, int ch) {
        uint32_t raw = sb + (buf ? RAW1 : RAW0);
        uint32_t vh = sb + (buf ? VH1 : VH0);
        uint32_t vl = sb + (buf ? VL1 : VL0);
        const float* wp = wsrc + ch * 32;
#pragma unroll
        for (int j = 0; j < 2; j++) {
            int idx = tid + j * 256;
            int r = idx >> 3, c = idx & 7;      // 64 rows x 8 x 16B
            cpa16(raw + r * 144 + c * 16, wp + (long)r * 2048 + c * 4);
        }
        {
            int r = tid >> 3, c = tid & 7;      // 32 rows x 8 x 16B
            cpa16(vh + r * 144 + c * 16, vhsrc + (long)(ch * 32 + r) * 64 + c * 8);
            cpa16(vl + r * 144 + c * 16, vlsrc + (long)(ch * 32 + r) * 64 + c * 8);
        }
    };

    float acc[1][4][4];
#pragma unroll
    for (int j = 0; j < 4; j++)
#pragma unroll
        for (int k = 0; k < 4; k++) acc[0][j][k] = 0.f;

    load_chunk(0, 0);
    CP_COMMIT();
    __syncthreads();   // st[] visible
    const int crow = tid >> 2, cquar = tid & 3;   // 64 rows x 4 chunks of 8 floats
    const float M = st[crow][0], invS = st[crow][1];
    const int aoff = warp_m * 16 * 80, boff = warp_n * 32 * 2;

    for (int ch = 0; ch < 64; ch++) {
        if (ch < 63) { load_chunk((ch + 1) & 1, ch + 1); CP_COMMIT(); CP_WAIT1(); }
        else CP_WAIT0();
        __syncthreads();
        // convert raw fp32 (64x32) -> p = exp(x-M)*invS; write final weights;
        // split p into WH/WL padded bf16 for the MMA
        {
            const char* rp = smem + (ch & 1 ? RAW1 : RAW0) + crow * 144 + cquar * 32;
            float* wout = wsrc + (long)crow * 2048 + ch * 32 + cquar * 8;
            uint32_t uh[4], ul[4];
#pragma unroll
            for (int i = 0; i < 2; i++) {
                float4 v = *(const float4*)(rp + i * 16);
                v.x = __expf(v.x - M) * invS;
                v.y = __expf(v.y - M) * invS;
                v.z = __expf(v.z - M) * invS;
                v.w = __expf(v.w - M) * invS;
                *(float4*)(wout + i * 4) = v;
                bf16 h0, l0, h1, l1;
                split1(v.x, h0, l0); split1(v.y, h1, l1);
                uh[i * 2] = pack2(h0, h1); ul[i * 2] = pack2(l0, l1);
                split1(v.z, h0, l0); split1(v.w, h1, l1);
                uh[i * 2 + 1] = pack2(h0, h1); ul[i * 2 + 1] = pack2(l0, l1);
            }
            *(uint4*)(smem + WH + crow * 80 + cquar * 16) = make_uint4(uh[0], uh[1], uh[2], uh[3]);
            *(uint4*)(smem + WL + crow * 80 + cquar * 16) = make_uint4(ul[0], ul[1], ul[2], ul[3]);
        }
        __syncthreads();
        uint32_t vh = sb + ((ch & 1) ? VH1 : VH0) + boff;
        uint32_t vl = sb + ((ch & 1) ? VL1 : VL0) + boff;
        gemm3<1, 4, 2, true>(acc, sb + WH + aoff, sb + WL + aoff, vh, vl, 80, 144, lane);
        __syncthreads();
    }

    const int b_ = bh >> 4, h = bh & 15;
#pragma unroll
    for (int nt = 0; nt < 4; nt++) {
        int s0 = qt * 64 + warp_m * 16 + (lane >> 2);
        int dh = warp_n * 32 + nt * 8 + (lane & 3) * 2;
        long a0 = ((long)b_ * 2048 + s0) * 1024 + h * 64 + dh;
        long a1 = ((long)b_ * 2048 + s0 + 8) * 1024 + h * 64 + dh;
        bf16 hh0, ll0, hh1, ll1;
        split1(acc[0][nt][0], hh0, ll0); split1(acc[0][nt][1], hh1, ll1);
        *(uint32_t*)(Oh + a0) = pack2(hh0, hh1);
        *(uint32_t*)(Ol + a0) = pack2(ll0, ll1);
        split1(acc[0][nt][2], hh0, ll0); split1(acc[0][nt][3], hh1, ll1);
        *(uint32_t*)(Oh + a1) = pack2(hh0, hh1);
        *(uint32_t*)(Ol + a1) = pack2(ll0, ll1);
    }
}

// ---------------- dense: out = A @ W^T + b (fp32 out) ----------------
__global__ __launch_bounds__(256) void dense_kernel(
    const bf16* __restrict__ Ahi, const bf16* __restrict__ Alo,
    const bf16* __restrict__ Bhi, const bf16* __restrict__ Blo,
    const float* __restrict__ bias, float* __restrict__ outD)
{
    extern __shared__ char smem[];
    const uint32_t sb = smem_u32(smem);
    const int tid = threadIdx.x, lane = tid & 31, wid = tid >> 5;
    const int warp_m = wid >> 2, warp_n = wid & 3;
    const long m0 = (long)blockIdx.y * 128, n0 = (long)blockIdx.x * 128;

    float acc[4][4][4];
#pragma unroll
    for (int i = 0; i < 4; i++)
#pragma unroll
        for (int j = 0; j < 4; j++)
#pragma unroll
            for (int k = 0; k < 4; k++) acc[i][j][k] = 0.f;

    const bf16* srcs[4] = {Ahi + m0 * 1024, Alo + m0 * 1024,
                           Bhi + n0 * 1024, Blo + n0 * 1024};
    auto load_chunk = [&](int buf, int kb) {
        uint32_t base = sb + buf * 40960;
#pragma unroll
        for (int t = 0; t < 4; t++) {
            const bf16* s = srcs[t] + kb;
            uint32_t db = base + t * 10240;
#pragma unroll
            for (int j = 0; j < 2; j++) {
                int idx = tid + j * 256;
                int r = idx >> 2, c = idx & 3;
                cpa16(db + r * 80 + c * 16, s + (long)r * 1024 + c * 8);
            }
        }
    };

    load_chunk(0, 0);
    CP_COMMIT();
    const int aoff = warp_m * 64 * 80, boff = warp_n * 32 * 80;
    for (int ch = 0; ch < 32; ch++) {
        if (ch < 31) { load_chunk((ch + 1) & 1, (ch + 1) * 32); CP_COMMIT(); CP_WAIT1(); }
        else CP_WAIT0();
        __syncthreads();
        uint32_t b = sb + (ch & 1) * 40960;
        gemm3<4, 4, 2, false>(acc, b + aoff, b + 10240 + aoff,
                              b + 20480 + boff, b + 30720 + boff, 80, 80, lane);
        __syncthreads();
    }

#pragma unroll
    for (int mt = 0; mt < 4; mt++) {
#pragma unroll
        for (int nt = 0; nt < 4; nt++) {
            int n = (int)n0 + warp_n * 32 + nt * 8 + (lane & 3) * 2;
            float bv0 = bias[n], bv1 = bias[n + 1];
            long r0 = m0 + warp_m * 64 + mt * 16 + (lane >> 2);
            *(float2*)(outD + r0 * 1024 + n) =
                make_float2(acc[mt][nt][0] + bv0, acc[mt][nt][1] + bv1);
            *(float2*)(outD + (r0 + 8) * 1024 + n) =
                make_float2(acc[mt][nt][2] + bv0, acc[mt][nt][3] + bv1);
        }
    }
}

// ---------------- host launcher ----------------
extern "C" void kernel_launch(void* const* d_in, const int* in_sizes, int n_in,
                              void* d_out, int out_size)
{
    const float* q    = (const float*)d_in[0];
    const float* k    = (const float*)d_in[1];
    const float* v    = (const float*)d_in[2];
    const int*   mask = (const int*)d_in[3];
    const float* wq_w = (const float*)d_in[4];
    const float* wq_b = (const float*)d_in[5];
    const float* wk_w = (const float*)d_in[6];
    const float* wk_b = (const float*)d_in[7];
    const float* wv_w = (const float*)d_in[8];
    const float* wv_b = (const float*)d_in[9];
    const float* dw   = (const float*)d_in[10];
    const float* db   = (const float*)d_in[11];

    float* out = (float*)d_out;
    float* wts = out + OUT_ELEMS;

    bf16 *xqh, *xql, *xkh, *xkl, *xvh, *xvl;
    bf16 *wqh, *wql, *wkh, *wkl, *wvh, *wvl, *wdh, *wdl;
    bf16 *qph, *qpl, *kph, *kpl, *vph, *vpl, *ah, *al;
    float* stats;
    uint32_t* pmp;
    cudaGetSymbolAddress((void**)&xqh, g_xq_hi); cudaGetSymbolAddress((void**)&xql, g_xq_lo);
    cudaGetSymbolAddress((void**)&xkh, g_xk_hi); cudaGetSymbolAddress((void**)&xkl, g_xk_lo);
    cudaGetSymbolAddress((void**)&xvh, g_xv_hi); cudaGetSymbolAddress((void**)&xvl, g_xv_lo);
    cudaGetSymbolAddress((void**)&wqh, g_wq_hi); cudaGetSymbolAddress((void**)&wql, g_wq_lo);
    cudaGetSymbolAddress((void**)&wkh, g_wk_hi); cudaGetSymbolAddress((void**)&wkl, g_wk_lo);
    cudaGetSymbolAddress((void**)&wvh, g_wv_hi); cudaGetSymbolAddress((void**)&wvl, g_wv_lo);
    cudaGetSymbolAddress((void**)&wdh, g_wd_hi); cudaGetSymbolAddress((void**)&wdl, g_wd_lo);
    cudaGetSymbolAddress((void**)&qph, g_qp_hi); cudaGetSymbolAddress((void**)&qpl, g_qp_lo);
    cudaGetSymbolAddress((void**)&kph, g_kp_hi); cudaGetSymbolAddress((void**)&kpl, g_kp_lo);
    cudaGetSymbolAddress((void**)&vph, g_vp_hi); cudaGetSymbolAddress((void**)&vpl, g_vp_lo);
    cudaGetSymbolAddress((void**)&ah,  g_ah);    cudaGetSymbolAddress((void**)&al,  g_al);
    cudaGetSymbolAddress((void**)&stats, g_stats);
    cudaGetSymbolAddress((void**)&pmp, g_pm);

    cudaFuncSetAttribute(qkv_kernel,    cudaFuncAttributeMaxDynamicSharedMemorySize, 81920);
    cudaFuncSetAttribute(dense_kernel,  cudaFuncAttributeMaxDynamicSharedMemorySize, 81920);
    cudaFuncSetAttribute(scores_kernel, cudaFuncAttributeMaxDynamicSharedMemorySize, 92160);
    cudaFuncSetAttribute(pv_kernel,     cudaFuncAttributeMaxDynamicSharedMemorySize, 47104);

    // launch 0: input splits
    Split3Args s3;
    s3.s[0] = {q, xqh, xql}; s3.s[1] = {k, xkh, xkl}; s3.s[2] = {v, xvh, xvl};
    split3_kernel<<<dim3(2048, 1, 3), 256>>>(s3);
    // launch 1: weight splits
    Split4Args s4;
    s4.s[0] = {wq_w, wqh, wql}; s4.s[1] = {wk_w, wkh, wkl};
    s4.s[2] = {wv_w, wvh, wvl}; s4.s[3] = {dw, wdh, wdl};
    split4_kernel<<<dim3(512, 1, 4), 256>>>(s4);
    // launch 2: pack mask bits
    pack_mask_kernel<<<1024, 256>>>(mask, pmp);

    // launch 3: QKV projections
    QKVArgs qa;
    qa.p[0] = {xqh, xql, wqh, wql, wq_b, qph, qpl};
    qa.p[1] = {xkh, xkl, wkh, wkl, wk_b, kph, kpl};
    qa.p[2] = {xvh, xvl, wvh, wvl, wv_b, vph, vpl};
    qkv_kernel<<<dim3(8, 32, 3), 256, 81920>>>(qa);

    // launch 4: scores (bitmask + raw scores + online stats)
    scores_kernel<<<dim3(32, 32), 256, 92160>>>(qph, qpl, kph, kpl, pmp, wts, stats);
    // launch 5: PV (exp + normalize + final weights + attn)
    pv_kernel<<<dim3(32, 32), 256, 47104>>>(wts, vph, vpl, stats, ah, al);
    // launch 6: dense
    dense_kernel<<<dim3(8, 32), 256, 81920>>>(ah, al, wdh, wdl, db, out);
}

// round 15
// speedup vs baseline: 1.7702x; 1.0279x over previous
#include <cuda_runtime.h>
#include <cuda_bf16.h>
#include <stdint.h>
#include <math.h>

typedef __nv_bfloat16 bf16;

constexpr long OUT_ELEMS = 4194304L;   // B*S*D

// ---------------- scratch: device globals (no allocation) ----------------
__device__ __align__(256) bf16 g_xq_hi[4194304], g_xq_lo[4194304];
__device__ __align__(256) bf16 g_xk_hi[4194304], g_xk_lo[4194304];
__device__ __align__(256) bf16 g_xv_hi[4194304], g_xv_lo[4194304];
__device__ __align__(256) bf16 g_wq_hi[1048576], g_wq_lo[1048576];
__device__ __align__(256) bf16 g_wk_hi[1048576], g_wk_lo[1048576];
__device__ __align__(256) bf16 g_wv_hi[1048576], g_wv_lo[1048576];
__device__ __align__(256) bf16 g_wd_hi[1048576], g_wd_lo[1048576];
__device__ __align__(256) bf16 g_qp_hi[4194304], g_qp_lo[4194304];  // [bh][s][64]
__device__ __align__(256) bf16 g_kp_hi[4194304], g_kp_lo[4194304];
__device__ __align__(256) bf16 g_vp_hi[4194304], g_vp_lo[4194304];
__device__ __align__(256) bf16 g_ah[4194304], g_al[4194304];        // attn hi/lo [m][1024]
__device__ __align__(256) float g_stats[131072];                    // [bh*2048+q]{M, invS}
__device__ __align__(256) uint32_t g_pm[262144];                    // packed mask bits

// ---------------- helpers ----------------
__device__ __forceinline__ uint32_t smem_u32(const void* p) {
    uint32_t a;
    asm("{ .reg .u64 t; cvta.to.shared.u64 t, %1; cvt.u32.u64 %0, t; }" : "=r"(a) : "l"(p));
    return a;
}
__device__ __forceinline__ void cpa16(uint32_t d, const void* g) {
    asm volatile("cp.async.cg.shared.global [%0], [%1], 16;" :: "r"(d), "l"(g));
}
#define CP_COMMIT() asm volatile("cp.async.commit_group;" ::: "memory")
#define CP_WAIT0()  asm volatile("cp.async.wait_group 0;" ::: "memory")
#define CP_WAIT1()  asm volatile("cp.async.wait_group 1;" ::: "memory")

__device__ __forceinline__ void ldm_x4(uint32_t& r0, uint32_t& r1, uint32_t& r2, uint32_t& r3, uint32_t a) {
    asm volatile("ldmatrix.sync.aligned.m8n8.x4.shared.b16 {%0,%1,%2,%3}, [%4];"
                 : "=r"(r0), "=r"(r1), "=r"(r2), "=r"(r3) : "r"(a));
}
__device__ __forceinline__ void ldm_x4t(uint32_t& r0, uint32_t& r1, uint32_t& r2, uint32_t& r3, uint32_t a) {
    asm volatile("ldmatrix.sync.aligned.m8n8.x4.trans.shared.b16 {%0,%1,%2,%3}, [%4];"
                 : "=r"(r0), "=r"(r1), "=r"(r2), "=r"(r3) : "r"(a));
}
__device__ __forceinline__ void mma16816(float* c, const uint32_t* a, const uint32_t* b) {
    asm volatile(
        "mma.sync.aligned.m16n8k16.row.col.f32.bf16.bf16.f32 "
        "{%0,%1,%2,%3}, {%4,%5,%6,%7}, {%8,%9}, {%0,%1,%2,%3};"
        : "+f"(c[0]), "+f"(c[1]), "+f"(c[2]), "+f"(c[3])
        : "r"(a[0]), "r"(a[1]), "r"(a[2]), "r"(a[3]), "r"(b[0]), "r"(b[1]));
}

__device__ __forceinline__ uint32_t pack2(bf16 a, bf16 b) {
    return (uint32_t)__bfloat16_as_ushort(a) | ((uint32_t)__bfloat16_as_ushort(b) << 16);
}
__device__ __forceinline__ void split1(float v, bf16& h, bf16& l) {
    h = __float2bfloat16_rn(v);
    l = __float2bfloat16_rn(v - __bfloat162float(h));
}

// --------------- warp-tile GEMM core (3-term compensated) ---------------
template<int MT, int NT, int NK, bool TRB>
__device__ __forceinline__ void gemm_pass(float (&acc)[MT][NT][4],
        uint32_t ab, uint32_t bb, int astr, int bstr, int lane)
{
    const int a_row = (lane & 7) + ((lane >> 3) & 1) * 8;
    const int a_k16 = (lane >> 4) * 16;
    const int b_row = (lane & 7) + (lane >> 4) * 8;
    const int b_k16 = ((lane >> 3) & 1) * 16;
    const int bt_row = (lane & 7) + ((lane >> 3) & 1) * 8;
    const int bt_col = (lane >> 4) * 8;
#pragma unroll
    for (int ks = 0; ks < NK; ks++) {
        uint32_t af[MT][4];
#pragma unroll
        for (int mt = 0; mt < MT; mt++)
            ldm_x4(af[mt][0], af[mt][1], af[mt][2], af[mt][3],
                   ab + (mt * 16 + a_row) * astr + ks * 32 + a_k16);
        uint32_t bfr[NT][2];
#pragma unroll
        for (int np = 0; np < NT / 2; np++) {
            uint32_t r0, r1, r2, r3;
            if (TRB)
                ldm_x4t(r0, r1, r2, r3, bb + (ks * 16 + bt_row) * bstr + (np * 16 + bt_col) * 2);
            else
                ldm_x4(r0, r1, r2, r3, bb + (np * 16 + b_row) * bstr + ks * 32 + b_k16);
            bfr[2*np][0] = r0; bfr[2*np][1] = r1;
            bfr[2*np+1][0] = r2; bfr[2*np+1][1] = r3;
        }
#pragma unroll
        for (int mt = 0; mt < MT; mt++)
#pragma unroll
            for (int nt = 0; nt < NT; nt++)
                mma16816(acc[mt][nt], af[mt], bfr[nt]);
    }
}

template<int MT, int NT, int NK, bool TRB>
__device__ __forceinline__ void gemm3(float (&acc)[MT][NT][4],
        uint32_t ahi, uint32_t alo, uint32_t bhi, uint32_t blo,
        int astr, int bstr, int lane)
{
    gemm_pass<MT, NT, NK, TRB>(acc, ahi, bhi, astr, bstr, lane);
    gemm_pass<MT, NT, NK, TRB>(acc, ahi, blo, astr, bstr, lane);
    gemm_pass<MT, NT, NK, TRB>(acc, alo, bhi, astr, bstr, lane);
}

// ---------------- splits: fp32 -> hi/lo bf16, z-indexed ----------------
struct SplitSet { const float* x; bf16 *hi, *lo; };
struct Split3Args { SplitSet s[3]; };
struct Split4Args { SplitSet s[4]; };

__global__ void split3_kernel(Split3Args args) {
    const SplitSet ss = args.s[blockIdx.z];
    for (long i = blockIdx.x * blockDim.x + threadIdx.x; i < 1048576; i += (long)gridDim.x * blockDim.x) {
        float4 v = *(const float4*)(ss.x + i * 4);
        bf16 h0, l0, h1, l1, h2, l2, h3, l3;
        split1(v.x, h0, l0); split1(v.y, h1, l1);
        split1(v.z, h2, l2); split1(v.w, h3, l3);
        *(uint2*)(ss.hi + i * 4) = make_uint2(pack2(h0, h1), pack2(h2, h3));
        *(uint2*)(ss.lo + i * 4) = make_uint2(pack2(l0, l1), pack2(l2, l3));
    }
}
__global__ void split4_kernel(Split4Args args) {
    const SplitSet ss = args.s[blockIdx.z];
    for (long i = blockIdx.x * blockDim.x + threadIdx.x; i < 262144; i += (long)gridDim.x * blockDim.x) {
        float4 v = *(const float4*)(ss.x + i * 4);
        bf16 h0, l0, h1, l1, h2, l2, h3, l3;
        split1(v.x, h0, l0); split1(v.y, h1, l1);
        split1(v.z, h2, l2); split1(v.w, h3, l3);
        *(uint2*)(ss.hi + i * 4) = make_uint2(pack2(h0, h1), pack2(h2, h3));
        *(uint2*)(ss.lo + i * 4) = make_uint2(pack2(l0, l1), pack2(l2, l3));
    }
}

// ---------------- pack mask into bits ----------------
__global__ void pack_mask_kernel(const int* __restrict__ mask, uint32_t* __restrict__ pm) {
    long idx = (long)blockIdx.x * 256 + threadIdx.x;   // 0..262143
    const int* src = mask + idx * 32;
    uint32_t bits = 0;
#pragma unroll
    for (int i = 0; i < 8; i++) {
        int4 m4 = *(const int4*)(src + i * 4);
        bits |= (m4.x ? 1u : 0u) << (i * 4);
        bits |= (m4.y ? 1u : 0u) << (i * 4 + 1);
        bits |= (m4.z ? 1u : 0u) << (i * 4 + 2);
        bits |= (m4.w ? 1u : 0u) << (i * 4 + 3);
    }
    pm[idx] = bits;
}

// ---------------- QKV proj: 64x128 tiles, 2 CTAs/SM --------------------------
// Grid (8, 64, 3). smem: per buf {AH 5120, AL 5120, BH 10240, BL 10240} = 30720;
// 2 bufs = 61440.
struct ProjSet { const bf16 *Ah, *Al, *Bh, *Bl; const float* bias; bf16 *Ph, *Pl; };
struct QKVArgs { ProjSet p[3]; };

__global__ __launch_bounds__(256, 2) void qkv_kernel(QKVArgs args)
{
    extern __shared__ char smem[];
    const uint32_t sb = smem_u32(smem);
    const ProjSet ps = args.p[blockIdx.z];
    const int tid = threadIdx.x, lane = tid & 31, wid = tid >> 5;
    const int warp_m = wid >> 2, warp_n = wid & 3;   // 2 x 4 warps, warp tile 32x32
    const long m0 = (long)blockIdx.y * 64, n0 = (long)blockIdx.x * 128;

    float acc[2][4][4];
#pragma unroll
    for (int i = 0; i < 2; i++)
#pragma unroll
        for (int j = 0; j < 4; j++)
#pragma unroll
            for (int k = 0; k < 4; k++) acc[i][j][k] = 0.f;

    const bf16* srcA[2] = {ps.Ah + m0 * 1024, ps.Al + m0 * 1024};
    const bf16* srcB[2] = {ps.Bh + n0 * 1024, ps.Bl + n0 * 1024};
    auto load_chunk = [&](int buf, int kb) {
        uint32_t base = sb + buf * 30720;
        {   // A tiles: 64 rows x 4 x 16B each
            int r = tid >> 2, c = tid & 3;
            const long off = (long)r * 1024 + kb + c * 8;
            cpa16(base + r * 80 + c * 16, srcA[0] + off);
            cpa16(base + 5120 + r * 80 + c * 16, srcA[1] + off);
        }
#pragma unroll
        for (int j = 0; j < 2; j++) {   // B tiles: 128 rows x 4 x 16B each
            int idx = tid + j * 256;
            int r = idx >> 2, c = idx & 3;
            const long off = (long)r * 1024 + kb + c * 8;
            cpa16(base + 10240 + r * 80 + c * 16, srcB[0] + off);
            cpa16(base + 20480 + r * 80 + c * 16, srcB[1] + off);
        }
    };

    load_chunk(0, 0);
    CP_COMMIT();
    const int aoff = warp_m * 32 * 80, boff = warp_n * 32 * 80;
    for (int ch = 0; ch < 32; ch++) {
        if (ch < 31) { load_chunk((ch + 1) & 1, (ch + 1) * 32); CP_COMMIT(); CP_WAIT1(); }
        else CP_WAIT0();
        __syncthreads();
        uint32_t b = sb + (ch & 1) * 30720;
        gemm3<2, 4, 2, false>(acc, b + aoff, b + 5120 + aoff,
                              b + 10240 + boff, b + 20480 + boff, 80, 80, lane);
        __syncthreads();
    }

#pragma unroll
    for (int mt = 0; mt < 2; mt++) {
#pragma unroll
        for (int nt = 0; nt < 4; nt++) {
            int n = (int)n0 + warp_n * 32 + nt * 8 + (lane & 3) * 2;
            float bv0 = ps.bias[n], bv1 = ps.bias[n + 1];
            long r0 = m0 + warp_m * 32 + mt * 16 + (lane >> 2);
            long r1 = r0 + 8;
            float v00 = acc[mt][nt][0] + bv0, v01 = acc[mt][nt][1] + bv1;
            float v10 = acc[mt][nt][2] + bv0, v11 = acc[mt][nt][3] + bv1;
            int h = n >> 6, dh = n & 63;
            {
                int b_ = (int)(r0 >> 11), s_ = (int)(r0 & 2047);
                long a = ((long)(b_ * 16 + h) * 2048 + s_) * 64 + dh;
                bf16 hh0, ll0, hh1, ll1;
                split1(v00, hh0, ll0); split1(v01, hh1, ll1);
                *(uint32_t*)(ps.Ph + a) = pack2(hh0, hh1);
                *(uint32_t*)(ps.Pl + a) = pack2(ll0, ll1);
            }
            {
                int b_ = (int)(r1 >> 11), s_ = (int)(r1 & 2047);
                long a = ((long)(b_ * 16 + h) * 2048 + s_) * 64 + dh;
                bf16 hh0, ll0, hh1, ll1;
                split1(v10, hh0, ll0); split1(v11, hh1, ll1);
                *(uint32_t*)(ps.Ph + a) = pack2(hh0, hh1);
                *(uint32_t*)(ps.Pl + a) = pack2(ll0, ll1);
            }
        }
    }
}

// ---------------- scores: K-streaming + bitmask + online softmax stats -------
__global__ __launch_bounds__(256, 2) void scores_kernel(
    const bf16* __restrict__ Qhi, const bf16* __restrict__ Qlo,
    const bf16* __restrict__ Khi, const bf16* __restrict__ Klo,
    const uint32_t* __restrict__ pm, float* __restrict__ Wt,
    float* __restrict__ stats)
{
    extern __shared__ char smem[];
    __shared__ float smm[64][4], sms[64][4];
    const uint32_t sb = smem_u32(smem);
    const int tid = threadIdx.x, lane = tid & 31, wid = tid >> 5;
    const int warp_m = wid >> 2, warp_n = wid & 3;    // 2 x 4 warps, warp tile 32x32
    const int qt = blockIdx.x, bh = blockIdx.y;
    const int b_ = bh >> 4;

    const bf16* qh = Qhi + ((long)bh * 2048 + qt * 64) * 64;
    const bf16* ql = Qlo + ((long)bh * 2048 + qt * 64) * 64;
    const bf16* kh0 = Khi + (long)bh * 2048 * 64;
    const bf16* kl0 = Klo + (long)bh * 2048 * 64;

    auto load_q = [&](uint32_t dst, const bf16* src) {
#pragma unroll
        for (int j = 0; j < 2; j++) {
            int idx = tid + j * 256;
            int r = idx >> 3, c = idx & 7;
            cpa16(dst + r * 144 + c * 16, src + (long)r * 64 + c * 8);
        }
    };
    auto load_k = [&](uint32_t dst, const bf16* src) {
#pragma unroll
        for (int j = 0; j < 4; j++) {
            int idx = tid + j * 256;
            int r = idx >> 3, c = idx & 7;
            cpa16(dst + r * 144 + c * 16, src + (long)r * 64 + c * 8);
        }
    };

    load_q(sb, qh);
    load_q(sb + 9216, ql);
    load_k(sb + 18432, kh0);
    load_k(sb + 36864, kl0);
    CP_COMMIT();

    const int aoff = warp_m * 32 * 144, boff = warp_n * 32 * 144;
    float* wbase = Wt + ((long)bh * 2048 + qt * 64) * 2048;
    const int r0b = warp_m * 32 + (lane >> 2);
    const int cb = warp_n * 32 + (lane & 3) * 2;
    const int bsel = (lane & 3) * 2;
    const uint32_t* pmb = pm + ((long)b_ * 2048 + qt * 64) * 64 + warp_n;

    float m_run[4] = {-1e30f, -1e30f, -1e30f, -1e30f};
    float s_run[4] = {0.f, 0.f, 0.f, 0.f};

    for (int kt = 0; kt < 16; kt++) {
        if (kt < 15) {
            uint32_t kb = sb + 18432 + ((kt + 1) & 1) * 36864;
            load_k(kb, kh0 + (long)(kt + 1) * 128 * 64);
            load_k(kb + 18432, kl0 + (long)(kt + 1) * 128 * 64);
            CP_COMMIT(); CP_WAIT1();
        } else CP_WAIT0();
        __syncthreads();

        float acc[2][4][4];
#pragma unroll
        for (int i = 0; i < 2; i++)
#pragma unroll
            for (int j = 0; j < 4; j++)
#pragma unroll
                for (int k = 0; k < 4; k++) acc[i][j][k] = 0.f;

        uint32_t kbuf = sb + 18432 + (kt & 1) * 36864;
        gemm3<2, 4, 4, false>(acc, sb + aoff, sb + 9216 + aoff,
                              kbuf + boff, kbuf + 18432 + boff, 144, 144, lane);

        float* base = wbase + kt * 128;
#pragma unroll
        for (int mt = 0; mt < 2; mt++) {
            const int r0 = r0b + mt * 16;
            const uint32_t mw0 = pmb[(long)r0 * 64 + kt * 4];
            const uint32_t mw1 = pmb[(long)(r0 + 8) * 64 + kt * 4];
#pragma unroll
            for (int nt = 0; nt < 4; nt++) {
                const int bit = nt * 8 + bsel;
                const int c = cb + nt * 8;
                float v00 = (mw0 >> bit) & 1u ? acc[mt][nt][0] * 0.125f : -1e30f;
                float v01 = (mw0 >> (bit + 1)) & 1u ? acc[mt][nt][1] * 0.125f : -1e30f;
                float v10 = (mw1 >> bit) & 1u ? acc[mt][nt][2] * 0.125f : -1e30f;
                float v11 = (mw1 >> (bit + 1)) & 1u ? acc[mt][nt][3] * 0.125f : -1e30f;
                acc[mt][nt][0] = v00; acc[mt][nt][1] = v01;
                acc[mt][nt][2] = v10; acc[mt][nt][3] = v11;
                *(float2*)(base + (long)r0 * 2048 + c) = make_float2(v00, v01);
                *(float2*)(base + (long)(r0 + 8) * 2048 + c) = make_float2(v10, v11);
            }
        }

#pragma unroll
        for (int mt = 0; mt < 2; mt++) {
#pragma unroll
            for (int hf = 0; hf < 2; hf++) {
                float m = -1e30f;
#pragma unroll
                for (int nt = 0; nt < 4; nt++)
                    m = fmaxf(m, fmaxf(acc[mt][nt][hf * 2], acc[mt][nt][hf * 2 + 1]));
                m = fmaxf(m, __shfl_xor_sync(0xffffffffu, m, 1));
                m = fmaxf(m, __shfl_xor_sync(0xffffffffu, m, 2));
                float s = 0.f;
#pragma unroll
                for (int nt = 0; nt < 4; nt++)
                    s += __expf(acc[mt][nt][hf * 2] - m) + __expf(acc[mt][nt][hf * 2 + 1] - m);
                s += __shfl_xor_sync(0xffffffffu, s, 1);
                s += __shfl_xor_sync(0xffffffffu, s, 2);
                const int slot = mt * 2 + hf;
                float mo = m_run[slot];
                float mn = fmaxf(mo, m);
                s_run[slot] = s_run[slot] * __expf(mo - mn) + s * __expf(m - mn);
                m_run[slot] = mn;
            }
        }
        __syncthreads();
    }

    if ((lane & 3) == 0) {
#pragma unroll
        for (int slot = 0; slot < 4; slot++) {
            int row = r0b + (slot >> 1) * 16 + (slot & 1) * 8;
            smm[row][warp_n] = m_run[slot];
            sms[row][warp_n] = s_run[slot];
        }
    }
    __syncthreads();
    if (tid < 64) {
        float M = smm[tid][0];
        M = fmaxf(M, smm[tid][1]);
        M = fmaxf(M, smm[tid][2]);
        M = fmaxf(M, smm[tid][3]);
        float S = 0.f;
#pragma unroll
        for (int w = 0; w < 4; w++) S += sms[tid][w] * __expf(smm[tid][w] - M);
        long row = (long)bh * 2048 + qt * 64 + tid;
        stats[row * 2] = M;
        stats[row * 2 + 1] = 1.f / S;
    }
}

// ---------------- PV: exp+normalize inline; writes weights + attn hi/lo ------
__global__ __launch_bounds__(256, 2) void pv_kernel(
    float* __restrict__ Wt, const bf16* __restrict__ Vhi,
    const bf16* __restrict__ Vlo, const float* __restrict__ stats,
    bf16* __restrict__ Oh, bf16* __restrict__ Ol)
{
    extern __shared__ char smem[];
    __shared__ float st[64][2];
    const uint32_t sb = smem_u32(smem);
    const int tid = threadIdx.x, lane = tid & 31, wid = tid >> 5;
    const int warp_m = wid >> 1, warp_n = wid & 1;    // 4 x 2 warps
    const int qt = blockIdx.x, bh = blockIdx.y;
    const uint32_t RAW0 = 0, RAW1 = 9216, VH0 = 18432, VH1 = 23040,
                   VL0 = 27648, VL1 = 32256, WH = 36864, WL = 41984;

    if (tid < 64) {
        long row = (long)bh * 2048 + qt * 64 + tid;
        st[tid][0] = stats[row * 2];
        st[tid][1] = stats[row * 2 + 1];
    }

    float* wsrc = Wt + ((long)bh * 2048 + qt * 64) * 2048;
    const bf16* vhsrc = Vhi + (long)bh * 2048 * 64;
    const bf16* vlsrc = Vlo + (long)bh * 2048 * 64;

    auto load_chunk = [&](int buf, int ch) {
        uint32_t raw = sb + (buf ? RAW1 : RAW0);
        uint32_t vh = sb + (buf ? VH1 : VH0);
        uint32_t vl = sb + (buf ? VL1 : VL0);
        const float* wp = wsrc + ch * 32;
#pragma unroll
        for (int j = 0; j < 2; j++) {
            int idx = tid + j * 256;
            int r = idx >> 3, c = idx & 7;
            cpa16(raw + r * 144 + c * 16, wp + (long)r * 2048 + c * 4);
        }
        {
            int r = tid >> 3, c = tid & 7;
            cpa16(vh + r * 144 + c * 16, vhsrc + (long)(ch * 32 + r) * 64 + c * 8);
            cpa16(vl + r * 144 + c * 16, vlsrc + (long)(ch * 32 + r) * 64 + c * 8);
        }
    };

    float acc[1][4][4];
#pragma unroll
    for (int j = 0; j < 4; j++)
#pragma unroll
        for (int k = 0; k < 4; k++) acc[0][j][k] = 0.f;

    load_chunk(0, 0);
    CP_COMMIT();
    __syncthreads();   // st[] visible
    const int crow = tid >> 2, cquar = tid & 3;
    const float M = st[crow][0], invS = st[crow][1];
    const int aoff = warp_m * 16 * 80, boff = warp_n * 32 * 2;

    for (int ch = 0; ch < 64; ch++) {
        if (ch < 63) { load_chunk((ch + 1) & 1, ch + 1); CP_COMMIT(); CP_WAIT1(); }
        else CP_WAIT0();
        __syncthreads();
        {
            const char* rp = smem + (ch & 1 ? RAW1 : RAW0) + crow * 144 + cquar * 32;
            float* wout = wsrc + (long)crow * 2048 + ch * 32 + cquar * 8;
            uint32_t uh[4], ul[4];
#pragma unroll
            for (int i = 0; i < 2; i++) {
                float4 v = *(const float4*)(rp + i * 16);
                v.x = __expf(v.x - M) * invS;
                v.y = __expf(v.y - M) * invS;
                v.z = __expf(v.z - M) * invS;
                v.w = __expf(v.w - M) * invS;
                *(float4*)(wout + i * 4) = v;
                bf16 h0, l0, h1, l1;
                split1(v.x, h0, l0); split1(v.y, h1, l1);
                uh[i * 2] = pack2(h0, h1); ul[i * 2] = pack2(l0, l1);
                split1(v.z, h0, l0); split1(v.w, h1, l1);
                uh[i * 2 + 1] = pack2(h0, h1); ul[i * 2 + 1] = pack2(l0, l1);
            }
            *(uint4*)(smem + WH + crow * 80 + cquar * 16) = make_uint4(uh[0], uh[1], uh[2], uh[3]);
            *(uint4*)(smem + WL + crow * 80 + cquar * 16) = make_uint4(ul[0], ul[1], ul[2], ul[3]);
        }
        __syncthreads();
        uint32_t vh = sb + ((ch & 1) ? VH1 : VH0) + boff;
        uint32_t vl = sb + ((ch & 1) ? VL1 : VL0) + boff;
        gemm3<1, 4, 2, true>(acc, sb + WH + aoff, sb + WL + aoff, vh, vl, 80, 144, lane);
        __syncthreads();
    }

    const int b_ = bh >> 4, h = bh & 15;
#pragma unroll
    for (int nt = 0; nt < 4; nt++) {
        int s0 = qt * 64 + warp_m * 16 + (lane >> 2);
        int dh = warp_n * 32 + nt * 8 + (lane & 3) * 2;
        long a0 = ((long)b_ * 2048 + s0) * 1024 + h * 64 + dh;
        long a1 = ((long)b_ * 2048 + s0 + 8) * 1024 + h * 64 + dh;
        bf16 hh0, ll0, hh1, ll1;
        split1(acc[0][nt][0], hh0, ll0); split1(acc[0][nt][1], hh1, ll1);
        *(uint32_t*)(Oh + a0) = pack2(hh0, hh1);
        *(uint32_t*)(Ol + a0) = pack2(ll0, ll1);
        split1(acc[0][nt][2], hh0, ll0); split1(acc[0][nt][3], hh1, ll1);
        *(uint32_t*)(Oh + a1) = pack2(hh0, hh1);
        *(uint32_t*)(Ol + a1) = pack2(ll0, ll1);
    }
}

// ---------------- dense: 64x128 tiles, 2 CTAs/SM ----------------
__global__ __launch_bounds__(256, 2) void dense_kernel(
    const bf16* __restrict__ Ahi, const bf16* __restrict__ Alo,
    const bf16* __restrict__ Bhi, const bf16* __restrict__ Blo,
    const float* __restrict__ bias, float* __restrict__ outD)
{
    extern __shared__ char smem[];
    const uint32_t sb = smem_u32(smem);
    const int tid = threadIdx.x, lane = tid & 31, wid = tid >> 5;
    const int warp_m = wid >> 2, warp_n = wid & 3;   // 2 x 4
    const long m0 = (long)blockIdx.y * 64, n0 = (long)blockIdx.x * 128;

    float acc[2][4][4];
#pragma unroll
    for (int i = 0; i < 2; i++)
#pragma unroll
        for (int j = 0; j < 4; j++)
#pragma unroll
            for (int k = 0; k < 4; k++) acc[i][j][k] = 0.f;

    const bf16* srcA[2] = {Ahi + m0 * 1024, Alo + m0 * 1024};
    const bf16* srcB[2] = {Bhi + n0 * 1024, Blo + n0 * 1024};
    auto load_chunk = [&](int buf, int kb) {
        uint32_t base = sb + buf * 30720;
        {
            int r = tid >> 2, c = tid & 3;
            const long off = (long)r * 1024 + kb + c * 8;
            cpa16(base + r * 80 + c * 16, srcA[0] + off);
            cpa16(base + 5120 + r * 80 + c * 16, srcA[1] + off);
        }
#pragma unroll
        for (int j = 0; j < 2; j++) {
            int idx = tid + j * 256;
            int r = idx >> 2, c = idx & 3;
            const long off = (long)r * 1024 + kb + c * 8;
            cpa16(base + 10240 + r * 80 + c * 16, srcB[0] + off);
            cpa16(base + 20480 + r * 80 + c * 16, srcB[1] + off);
        }
    };

    load_chunk(0, 0);
    CP_COMMIT();
    const int aoff = warp_m * 32 * 80, boff = warp_n * 32 * 80;
    for (int ch = 0; ch < 32; ch++) {
        if (ch < 31) { load_chunk((ch + 1) & 1, (ch + 1) * 32); CP_COMMIT(); CP_WAIT1(); }
        else CP_WAIT0();
        __syncthreads();
        uint32_t b = sb + (ch & 1) * 30720;
        gemm3<2, 4, 2, false>(acc, b + aoff, b + 5120 + aoff,
                              b + 10240 + boff, b + 20480 + boff, 80, 80, lane);
        __syncthreads();
    }

#pragma unroll
    for (int mt = 0; mt < 2; mt++) {
#pragma unroll
        for (int nt = 0; nt < 4; nt++) {
            int n = (int)n0 + warp_n * 32 + nt * 8 + (lane & 3) * 2;
            float bv0 = bias[n], bv1 = bias[n + 1];
            long r0 = m0 + warp_m * 32 + mt * 16 + (lane >> 2);
            *(float2*)(outD + r0 * 1024 + n) =
                make_float2(acc[mt][nt][0] + bv0, acc[mt][nt][1] + bv1);
            *(float2*)(outD + (r0 + 8) * 1024 + n) =
                make_float2(acc[mt][nt][2] + bv0, acc[mt][nt][3] + bv1);
        }
    }
}

// ---------------- host launcher ----------------
extern "C" void kernel_launch(void* const* d_in, const int* in_sizes, int n_in,
                              void* d_out, int out_size)
{
    const float* q    = (const float*)d_in[0];
    const float* k    = (const float*)d_in[1];
    const float* v    = (const float*)d_in[2];
    const int*   mask = (const int*)d_in[3];
    const float* wq_w = (const float*)d_in[4];
    const float* wq_b = (const float*)d_in[5];
    const float* wk_w = (const float*)d_in[6];
    const float* wk_b = (const float*)d_in[7];
    const float* wv_w = (const float*)d_in[8];
    const float* wv_b = (const float*)d_in[9];
    const float* dw   = (const float*)d_in[10];
    const float* db   = (const float*)d_in[11];

    float* out = (float*)d_out;
    float* wts = out + OUT_ELEMS;

    bf16 *xqh, *xql, *xkh, *xkl, *xvh, *xvl;
    bf16 *wqh, *wql, *wkh, *wkl, *wvh, *wvl, *wdh, *wdl;
    bf16 *qph, *qpl, *kph, *kpl, *vph, *vpl, *ah, *al;
    float* stats;
    uint32_t* pmp;
    cudaGetSymbolAddress((void**)&xqh, g_xq_hi); cudaGetSymbolAddress((void**)&xql, g_xq_lo);
    cudaGetSymbolAddress((void**)&xkh, g_xk_hi); cudaGetSymbolAddress((void**)&xkl, g_xk_lo);
    cudaGetSymbolAddress((void**)&xvh, g_xv_hi); cudaGetSymbolAddress((void**)&xvl, g_xv_lo);
    cudaGetSymbolAddress((void**)&wqh, g_wq_hi); cudaGetSymbolAddress((void**)&wql, g_wq_lo);
    cudaGetSymbolAddress((void**)&wkh, g_wk_hi); cudaGetSymbolAddress((void**)&wkl, g_wk_lo);
    cudaGetSymbolAddress((void**)&wvh, g_wv_hi); cudaGetSymbolAddress((void**)&wvl, g_wv_lo);
    cudaGetSymbolAddress((void**)&wdh, g_wd_hi); cudaGetSymbolAddress((void**)&wdl, g_wd_lo);
    cudaGetSymbolAddress((void**)&qph, g_qp_hi); cudaGetSymbolAddress((void**)&qpl, g_qp_lo);
    cudaGetSymbolAddress((void**)&kph, g_kp_hi); cudaGetSymbolAddress((void**)&kpl, g_kp_lo);
    cudaGetSymbolAddress((void**)&vph, g_vp_hi); cudaGetSymbolAddress((void**)&vpl, g_vp_lo);
    cudaGetSymbolAddress((void**)&ah,  g_ah);    cudaGetSymbolAddress((void**)&al,  g_al);
    cudaGetSymbolAddress((void**)&stats, g_stats);
    cudaGetSymbolAddress((void**)&pmp, g_pm);

    cudaFuncSetAttribute(qkv_kernel,    cudaFuncAttributeMaxDynamicSharedMemorySize, 61440);
    cudaFuncSetAttribute(dense_kernel,  cudaFuncAttributeMaxDynamicSharedMemorySize, 61440);
    cudaFuncSetAttribute(scores_kernel, cudaFuncAttributeMaxDynamicSharedMemorySize, 92160);
    cudaFuncSetAttribute(pv_kernel,     cudaFuncAttributeMaxDynamicSharedMemorySize, 47104);

    // launch 0: input splits
    Split3Args s3;
    s3.s[0] = {q, xqh, xql}; s3.s[1] = {k, xkh, xkl}; s3.s[2] = {v, xvh, xvl};
    split3_kernel<<<dim3(2048, 1, 3), 256>>>(s3);
    // launch 1: weight splits
    Split4Args s4;
    s4.s[0] = {wq_w, wqh, wql}; s4.s[1] = {wk_w, wkh, wkl};
    s4.s[2] = {wv_w, wvh, wvl}; s4.s[3] = {dw, wdh, wdl};
    split4_kernel<<<dim3(512, 1, 4), 256>>>(s4);
    // launch 2: pack mask bits
    pack_mask_kernel<<<1024, 256>>>(mask, pmp);

    // launch 3: QKV projections (64-row tiles, 2 CTAs/SM)
    QKVArgs qa;
    qa.p[0] = {xqh, xql, wqh, wql, wq_b, qph, qpl};
    qa.p[1] = {xkh, xkl, wkh, wkl, wk_b, kph, kpl};
    qa.p[2] = {xvh, xvl, wvh, wvl, wv_b, vph, vpl};
    qkv_kernel<<<dim3(8, 64, 3), 256, 61440>>>(qa);

    // launch 4: scores (bitmask + raw scores + online stats)
    scores_kernel<<<dim3(32, 32), 256, 92160>>>(qph, qpl, kph, kpl, pmp, wts, stats);
    // launch 5: PV (exp + normalize + final weights + attn)
    pv_kernel<<<dim3(32, 32), 256, 47104>>>(wts, vph, vpl, stats, ah, al);
    // launch 6: dense (64-row tiles, 2 CTAs/SM)
    dense_kernel<<<dim3(8, 64), 256, 61440>>>(ah, al, wdh, wdl, db, out);
}

// round 16
// speedup vs baseline: 1.8407x; 1.0398x over previous
#include <cuda_runtime.h>
#include <cuda_bf16.h>
#include <stdint.h>
#include <math.h>

typedef __nv_bfloat16 bf16;

constexpr long OUT_ELEMS = 4194304L;   // B*S*D

// ---------------- scratch: device globals (no allocation) ----------------
__device__ __align__(256) bf16 g_xq_hi[4194304], g_xq_lo[4194304];
__device__ __align__(256) bf16 g_xk_hi[4194304], g_xk_lo[4194304];
__device__ __align__(256) bf16 g_xv_hi[4194304], g_xv_lo[4194304];
__device__ __align__(256) bf16 g_wq_hi[1048576], g_wq_lo[1048576];
__device__ __align__(256) bf16 g_wk_hi[1048576], g_wk_lo[1048576];
__device__ __align__(256) bf16 g_wv_hi[1048576], g_wv_lo[1048576];
__device__ __align__(256) bf16 g_wd_hi[1048576], g_wd_lo[1048576];
__device__ __align__(256) bf16 g_qp_hi[4194304], g_qp_lo[4194304];  // [bh][s][64]
__device__ __align__(256) bf16 g_kp_hi[4194304], g_kp_lo[4194304];
__device__ __align__(256) bf16 g_vp_hi[4194304], g_vp_lo[4194304];
__device__ __align__(256) bf16 g_ah[4194304], g_al[4194304];        // attn hi/lo [m][1024]
__device__ __align__(256) float g_stats[131072];                    // [bh*2048+q]{M, invS}
__device__ __align__(256) uint32_t g_pm[262144];                    // packed mask bits

// ---------------- helpers ----------------
__device__ __forceinline__ uint32_t smem_u32(const void* p) {
    uint32_t a;
    asm("{ .reg .u64 t; cvta.to.shared.u64 t, %1; cvt.u32.u64 %0, t; }" : "=r"(a) : "l"(p));
    return a;
}
__device__ __forceinline__ void cpa16(uint32_t d, const void* g) {
    asm volatile("cp.async.cg.shared.global [%0], [%1], 16;" :: "r"(d), "l"(g));
}
#define CP_COMMIT() asm volatile("cp.async.commit_group;" ::: "memory")
#define CP_WAIT0()  asm volatile("cp.async.wait_group 0;" ::: "memory")
#define CP_WAIT1()  asm volatile("cp.async.wait_group 1;" ::: "memory")

__device__ __forceinline__ void ldm_x4(uint32_t& r0, uint32_t& r1, uint32_t& r2, uint32_t& r3, uint32_t a) {
    asm volatile("ldmatrix.sync.aligned.m8n8.x4.shared.b16 {%0,%1,%2,%3}, [%4];"
                 : "=r"(r0), "=r"(r1), "=r"(r2), "=r"(r3) : "r"(a));
}
__device__ __forceinline__ void ldm_x4t(uint32_t& r0, uint32_t& r1, uint32_t& r2, uint32_t& r3, uint32_t a) {
    asm volatile("ldmatrix.sync.aligned.m8n8.x4.trans.shared.b16 {%0,%1,%2,%3}, [%4];"
                 : "=r"(r0), "=r"(r1), "=r"(r2), "=r"(r3) : "r"(a));
}
__device__ __forceinline__ void mma16816(float* c, const uint32_t* a, const uint32_t* b) {
    asm volatile(
        "mma.sync.aligned.m16n8k16.row.col.f32.bf16.bf16.f32 "
        "{%0,%1,%2,%3}, {%4,%5,%6,%7}, {%8,%9}, {%0,%1,%2,%3};"
        : "+f"(c[0]), "+f"(c[1]), "+f"(c[2]), "+f"(c[3])
        : "r"(a[0]), "r"(a[1]), "r"(a[2]), "r"(a[3]), "r"(b[0]), "r"(b[1]));
}

__device__ __forceinline__ uint32_t pack2(bf16 a, bf16 b) {
    return (uint32_t)__bfloat16_as_ushort(a) | ((uint32_t)__bfloat16_as_ushort(b) << 16);
}
__device__ __forceinline__ void split1(float v, bf16& h, bf16& l) {
    h = __float2bfloat16_rn(v);
    l = __float2bfloat16_rn(v - __bfloat162float(h));
}

// --------------- fused 3-term warp-tile GEMM core ---------------
// Per k-step: load A hi+lo fragments once; per B pair load Bhi/Blo and issue
// hi*hi + hi*lo + lo*hi immediately. 4 tile-fragment loads per k-step (vs 6).
template<int MT, int NT, int NK, bool TRB>
__device__ __forceinline__ void gemm3(float (&acc)[MT][NT][4],
        uint32_t ahi, uint32_t alo, uint32_t bhi, uint32_t blo,
        int astr, int bstr, int lane)
{
    const int a_row = (lane & 7) + ((lane >> 3) & 1) * 8;
    const int a_k16 = (lane >> 4) * 16;
    const int b_row = (lane & 7) + (lane >> 4) * 8;
    const int b_k16 = ((lane >> 3) & 1) * 16;
    const int bt_row = (lane & 7) + ((lane >> 3) & 1) * 8;
    const int bt_col = (lane >> 4) * 8;
#pragma unroll
    for (int ks = 0; ks < NK; ks++) {
        uint32_t afh[MT][4], afl[MT][4];
#pragma unroll
        for (int mt = 0; mt < MT; mt++) {
            const int aoffs = (mt * 16 + a_row) * astr + ks * 32 + a_k16;
            ldm_x4(afh[mt][0], afh[mt][1], afh[mt][2], afh[mt][3], ahi + aoffs);
            ldm_x4(afl[mt][0], afl[mt][1], afl[mt][2], afl[mt][3], alo + aoffs);
        }
#pragma unroll
        for (int np = 0; np < NT / 2; np++) {
            uint32_t bh[2][2], bl[2][2];
            {
                uint32_t r0, r1, r2, r3;
                if (TRB) {
                    const int boffs = (ks * 16 + bt_row) * bstr + (np * 16 + bt_col) * 2;
                    ldm_x4t(r0, r1, r2, r3, bhi + boffs);
                    bh[0][0] = r0; bh[0][1] = r1; bh[1][0] = r2; bh[1][1] = r3;
                    ldm_x4t(r0, r1, r2, r3, blo + boffs);
                    bl[0][0] = r0; bl[0][1] = r1; bl[1][0] = r2; bl[1][1] = r3;
                } else {
                    const int boffs = (np * 16 + b_row) * bstr + ks * 32 + b_k16;
                    ldm_x4(r0, r1, r2, r3, bhi + boffs);
                    bh[0][0] = r0; bh[0][1] = r1; bh[1][0] = r2; bh[1][1] = r3;
                    ldm_x4(r0, r1, r2, r3, blo + boffs);
                    bl[0][0] = r0; bl[0][1] = r1; bl[1][0] = r2; bl[1][1] = r3;
                }
            }
#pragma unroll
            for (int mt = 0; mt < MT; mt++) {
#pragma unroll
                for (int j = 0; j < 2; j++) {
                    float* c = acc[mt][2 * np + j];
                    mma16816(c, afh[mt], bh[j]);
                    mma16816(c, afh[mt], bl[j]);
                    mma16816(c, afl[mt], bh[j]);
                }
            }
        }
    }
}

// ---------------- splits: fp32 -> hi/lo bf16, z-indexed ----------------
struct SplitSet { const float* x; bf16 *hi, *lo; };
struct Split3Args { SplitSet s[3]; };
struct Split4Args { SplitSet s[4]; };

__global__ void split3_kernel(Split3Args args) {
    const SplitSet ss = args.s[blockIdx.z];
    for (long i = blockIdx.x * blockDim.x + threadIdx.x; i < 1048576; i += (long)gridDim.x * blockDim.x) {
        float4 v = *(const float4*)(ss.x + i * 4);
        bf16 h0, l0, h1, l1, h2, l2, h3, l3;
        split1(v.x, h0, l0); split1(v.y, h1, l1);
        split1(v.z, h2, l2); split1(v.w, h3, l3);
        *(uint2*)(ss.hi + i * 4) = make_uint2(pack2(h0, h1), pack2(h2, h3));
        *(uint2*)(ss.lo + i * 4) = make_uint2(pack2(l0, l1), pack2(l2, l3));
    }
}
__global__ void split4_kernel(Split4Args args) {
    const SplitSet ss = args.s[blockIdx.z];
    for (long i = blockIdx.x * blockDim.x + threadIdx.x; i < 262144; i += (long)gridDim.x * blockDim.x) {
        float4 v = *(const float4*)(ss.x + i * 4);
        bf16 h0, l0, h1, l1, h2, l2, h3, l3;
        split1(v.x, h0, l0); split1(v.y, h1, l1);
        split1(v.z, h2, l2); split1(v.w, h3, l3);
        *(uint2*)(ss.hi + i * 4) = make_uint2(pack2(h0, h1), pack2(h2, h3));
        *(uint2*)(ss.lo + i * 4) = make_uint2(pack2(l0, l1), pack2(l2, l3));
    }
}

// ---------------- pack mask into bits ----------------
__global__ void pack_mask_kernel(const int* __restrict__ mask, uint32_t* __restrict__ pm) {
    long idx = (long)blockIdx.x * 256 + threadIdx.x;   // 0..262143
    const int* src = mask + idx * 32;
    uint32_t bits = 0;
#pragma unroll
    for (int i = 0; i < 8; i++) {
        int4 m4 = *(const int4*)(src + i * 4);
        bits |= (m4.x ? 1u : 0u) << (i * 4);
        bits |= (m4.y ? 1u : 0u) << (i * 4 + 1);
        bits |= (m4.z ? 1u : 0u) << (i * 4 + 2);
        bits |= (m4.w ? 1u : 0u) << (i * 4 + 3);
    }
    pm[idx] = bits;
}

// ---------------- QKV proj: 64x128 tiles, 2 CTAs/SM --------------------------
struct ProjSet { const bf16 *Ah, *Al, *Bh, *Bl; const float* bias; bf16 *Ph, *Pl; };
struct QKVArgs { ProjSet p[3]; };

__global__ __launch_bounds__(256, 2) void qkv_kernel(QKVArgs args)
{
    extern __shared__ char smem[];
    const uint32_t sb = smem_u32(smem);
    const ProjSet ps = args.p[blockIdx.z];
    const int tid = threadIdx.x, lane = tid & 31, wid = tid >> 5;
    const int warp_m = wid >> 2, warp_n = wid & 3;   // 2 x 4 warps, warp tile 32x32
    const long m0 = (long)blockIdx.y * 64, n0 = (long)blockIdx.x * 128;

    float acc[2][4][4];
#pragma unroll
    for (int i = 0; i < 2; i++)
#pragma unroll
        for (int j = 0; j < 4; j++)
#pragma unroll
            for (int k = 0; k < 4; k++) acc[i][j][k] = 0.f;

    const bf16* srcA[2] = {ps.Ah + m0 * 1024, ps.Al + m0 * 1024};
    const bf16* srcB[2] = {ps.Bh + n0 * 1024, ps.Bl + n0 * 1024};
    auto load_chunk = [&](int buf, int kb) {
        uint32_t base = sb + buf * 30720;
        {
            int r = tid >> 2, c = tid & 3;
            const long off = (long)r * 1024 + kb + c * 8;
            cpa16(base + r * 80 + c * 16, srcA[0] + off);
            cpa16(base + 5120 + r * 80 + c * 16, srcA[1] + off);
        }
#pragma unroll
        for (int j = 0; j < 2; j++) {
            int idx = tid + j * 256;
            int r = idx >> 2, c = idx & 3;
            const long off = (long)r * 1024 + kb + c * 8;
            cpa16(base + 10240 + r * 80 + c * 16, srcB[0] + off);
            cpa16(base + 20480 + r * 80 + c * 16, srcB[1] + off);
        }
    };

    load_chunk(0, 0);
    CP_COMMIT();
    const int aoff = warp_m * 32 * 80, boff = warp_n * 32 * 80;
    for (int ch = 0; ch < 32; ch++) {
        if (ch < 31) { load_chunk((ch + 1) & 1, (ch + 1) * 32); CP_COMMIT(); CP_WAIT1(); }
        else CP_WAIT0();
        __syncthreads();
        uint32_t b = sb + (ch & 1) * 30720;
        gemm3<2, 4, 2, false>(acc, b + aoff, b + 5120 + aoff,
                              b + 10240 + boff, b + 20480 + boff, 80, 80, lane);
        __syncthreads();
    }

#pragma unroll
    for (int mt = 0; mt < 2; mt++) {
#pragma unroll
        for (int nt = 0; nt < 4; nt++) {
            int n = (int)n0 + warp_n * 32 + nt * 8 + (lane & 3) * 2;
            float bv0 = ps.bias[n], bv1 = ps.bias[n + 1];
            long r0 = m0 + warp_m * 32 + mt * 16 + (lane >> 2);
            long r1 = r0 + 8;
            float v00 = acc[mt][nt][0] + bv0, v01 = acc[mt][nt][1] + bv1;
            float v10 = acc[mt][nt][2] + bv0, v11 = acc[mt][nt][3] + bv1;
            int h = n >> 6, dh = n & 63;
            {
                int b_ = (int)(r0 >> 11), s_ = (int)(r0 & 2047);
                long a = ((long)(b_ * 16 + h) * 2048 + s_) * 64 + dh;
                bf16 hh0, ll0, hh1, ll1;
                split1(v00, hh0, ll0); split1(v01, hh1, ll1);
                *(uint32_t*)(ps.Ph + a) = pack2(hh0, hh1);
                *(uint32_t*)(ps.Pl + a) = pack2(ll0, ll1);
            }
            {
                int b_ = (int)(r1 >> 11), s_ = (int)(r1 & 2047);
                long a = ((long)(b_ * 16 + h) * 2048 + s_) * 64 + dh;
                bf16 hh0, ll0, hh1, ll1;
                split1(v10, hh0, ll0); split1(v11, hh1, ll1);
                *(uint32_t*)(ps.Ph + a) = pack2(hh0, hh1);
                *(uint32_t*)(ps.Pl + a) = pack2(ll0, ll1);
            }
        }
    }
}

// ---------------- scores: K-streaming + bitmask + online softmax stats -------
__global__ __launch_bounds__(256, 2) void scores_kernel(
    const bf16* __restrict__ Qhi, const bf16* __restrict__ Qlo,
    const bf16* __restrict__ Khi, const bf16* __restrict__ Klo,
    const uint32_t* __restrict__ pm, float* __restrict__ Wt,
    float* __restrict__ stats)
{
    extern __shared__ char smem[];
    __shared__ float smm[64][4], sms[64][4];
    const uint32_t sb = smem_u32(smem);
    const int tid = threadIdx.x, lane = tid & 31, wid = tid >> 5;
    const int warp_m = wid >> 2, warp_n = wid & 3;    // 2 x 4 warps, warp tile 32x32
    const int qt = blockIdx.x, bh = blockIdx.y;
    const int b_ = bh >> 4;

    const bf16* qh = Qhi + ((long)bh * 2048 + qt * 64) * 64;
    const bf16* ql = Qlo + ((long)bh * 2048 + qt * 64) * 64;
    const bf16* kh0 = Khi + (long)bh * 2048 * 64;
    const bf16* kl0 = Klo + (long)bh * 2048 * 64;

    auto load_q = [&](uint32_t dst, const bf16* src) {
#pragma unroll
        for (int j = 0; j < 2; j++) {
            int idx = tid + j * 256;
            int r = idx >> 3, c = idx & 7;
            cpa16(dst + r * 144 + c * 16, src + (long)r * 64 + c * 8);
        }
    };
    auto load_k = [&](uint32_t dst, const bf16* src) {
#pragma unroll
        for (int j = 0; j < 4; j++) {
            int idx = tid + j * 256;
            int r = idx >> 3, c = idx & 7;
            cpa16(dst + r * 144 + c * 16, src + (long)r * 64 + c * 8);
        }
    };

    load_q(sb, qh);
    load_q(sb + 9216, ql);
    load_k(sb + 18432, kh0);
    load_k(sb + 36864, kl0);
    CP_COMMIT();

    const int aoff = warp_m * 32 * 144, boff = warp_n * 32 * 144;
    float* wbase = Wt + ((long)bh * 2048 + qt * 64) * 2048;
    const int r0b = warp_m * 32 + (lane >> 2);
    const int cb = warp_n * 32 + (lane & 3) * 2;
    const int bsel = (lane & 3) * 2;
    const uint32_t* pmb = pm + ((long)b_ * 2048 + qt * 64) * 64 + warp_n;

    float m_run[4] = {-1e30f, -1e30f, -1e30f, -1e30f};
    float s_run[4] = {0.f, 0.f, 0.f, 0.f};

    for (int kt = 0; kt < 16; kt++) {
        if (kt < 15) {
            uint32_t kb = sb + 18432 + ((kt + 1) & 1) * 36864;
            load_k(kb, kh0 + (long)(kt + 1) * 128 * 64);
            load_k(kb + 18432, kl0 + (long)(kt + 1) * 128 * 64);
            CP_COMMIT(); CP_WAIT1();
        } else CP_WAIT0();
        __syncthreads();

        float acc[2][4][4];
#pragma unroll
        for (int i = 0; i < 2; i++)
#pragma unroll
            for (int j = 0; j < 4; j++)
#pragma unroll
                for (int k = 0; k < 4; k++) acc[i][j][k] = 0.f;

        uint32_t kbuf = sb + 18432 + (kt & 1) * 36864;
        gemm3<2, 4, 4, false>(acc, sb + aoff, sb + 9216 + aoff,
                              kbuf + boff, kbuf + 18432 + boff, 144, 144, lane);

        float* base = wbase + kt * 128;
#pragma unroll
        for (int mt = 0; mt < 2; mt++) {
            const int r0 = r0b + mt * 16;
            const uint32_t mw0 = pmb[(long)r0 * 64 + kt * 4];
            const uint32_t mw1 = pmb[(long)(r0 + 8) * 64 + kt * 4];
#pragma unroll
            for (int nt = 0; nt < 4; nt++) {
                const int bit = nt * 8 + bsel;
                const int c = cb + nt * 8;
                float v00 = (mw0 >> bit) & 1u ? acc[mt][nt][0] * 0.125f : -1e30f;
                float v01 = (mw0 >> (bit + 1)) & 1u ? acc[mt][nt][1] * 0.125f : -1e30f;
                float v10 = (mw1 >> bit) & 1u ? acc[mt][nt][2] * 0.125f : -1e30f;
                float v11 = (mw1 >> (bit + 1)) & 1u ? acc[mt][nt][3] * 0.125f : -1e30f;
                acc[mt][nt][0] = v00; acc[mt][nt][1] = v01;
                acc[mt][nt][2] = v10; acc[mt][nt][3] = v11;
                *(float2*)(base + (long)r0 * 2048 + c) = make_float2(v00, v01);
                *(float2*)(base + (long)(r0 + 8) * 2048 + c) = make_float2(v10, v11);
            }
        }

#pragma unroll
        for (int mt = 0; mt < 2; mt++) {
#pragma unroll
            for (int hf = 0; hf < 2; hf++) {
                float m = -1e30f;
#pragma unroll
                for (int nt = 0; nt < 4; nt++)
                    m = fmaxf(m, fmaxf(acc[mt][nt][hf * 2], acc[mt][nt][hf * 2 + 1]));
                m = fmaxf(m, __shfl_xor_sync(0xffffffffu, m, 1));
                m = fmaxf(m, __shfl_xor_sync(0xffffffffu, m, 2));
                float s = 0.f;
#pragma unroll
                for (int nt = 0; nt < 4; nt++)
                    s += __expf(acc[mt][nt][hf * 2] - m) + __expf(acc[mt][nt][hf * 2 + 1] - m);
                s += __shfl_xor_sync(0xffffffffu, s, 1);
                s += __shfl_xor_sync(0xffffffffu, s, 2);
                const int slot = mt * 2 + hf;
                float mo = m_run[slot];
                float mn = fmaxf(mo, m);
                s_run[slot] = s_run[slot] * __expf(mo - mn) + s * __expf(m - mn);
                m_run[slot] = mn;
            }
        }
        __syncthreads();
    }

    if ((lane & 3) == 0) {
#pragma unroll
        for (int slot = 0; slot < 4; slot++) {
            int row = r0b + (slot >> 1) * 16 + (slot & 1) * 8;
            smm[row][warp_n] = m_run[slot];
            sms[row][warp_n] = s_run[slot];
        }
    }
    __syncthreads();
    if (tid < 64) {
        float M = smm[tid][0];
        M = fmaxf(M, smm[tid][1]);
        M = fmaxf(M, smm[tid][2]);
        M = fmaxf(M, smm[tid][3]);
        float S = 0.f;
#pragma unroll
        for (int w = 0; w < 4; w++) S += sms[tid][w] * __expf(smm[tid][w] - M);
        long row = (long)bh * 2048 + qt * 64 + tid;
        stats[row * 2] = M;
        stats[row * 2 + 1] = 1.f / S;
    }
}

// ---------------- PV: exp+normalize inline; writes weights + attn hi/lo ------
__global__ __launch_bounds__(256, 2) void pv_kernel(
    float* __restrict__ Wt, const bf16* __restrict__ Vhi,
    const bf16* __restrict__ Vlo, const float* __restrict__ stats,
    bf16* __restrict__ Oh, bf16* __restrict__ Ol)
{
    extern __shared__ char smem[];
    __shared__ float st[64][2];
    const uint32_t sb = smem_u32(smem);
    const int tid = threadIdx.x, lane = tid & 31, wid = tid >> 5;
    const int warp_m = wid >> 1, warp_n = wid & 1;    // 4 x 2 warps
    const int qt = blockIdx.x, bh = blockIdx.y;
    const uint32_t RAW0 = 0, RAW1 = 9216, VH0 = 18432, VH1 = 23040,
                   VL0 = 27648, VL1 = 32256, WH = 36864, WL = 41984;

    if (tid < 64) {
        long row = (long)bh * 2048 + qt * 64 + tid;
        st[tid][0] = stats[row * 2];
        st[tid][1] = stats[row * 2 + 1];
    }

    float* wsrc = Wt + ((long)bh * 2048 + qt * 64) * 2048;
    const bf16* vhsrc = Vhi + (long)bh * 2048 * 64;
    const bf16* vlsrc = Vlo + (long)bh * 2048 * 64;

    auto load_chunk = [&](int buf, int ch) {
        uint32_t raw = sb + (buf ? RAW1 : RAW0);
        uint32_t vh = sb + (buf ? VH1 : VH0);
        uint32_t vl = sb + (buf ? VL1 : VL0);
        const float* wp = wsrc + ch * 32;
#pragma unroll
        for (int j = 0; j < 2; j++) {
            int idx = tid + j * 256;
            int r = idx >> 3, c = idx & 7;
            cpa16(raw + r * 144 + c * 16, wp + (long)r * 2048 + c * 4);
        }
        {
            int r = tid >> 3, c = tid & 7;
            cpa16(vh + r * 144 + c * 16, vhsrc + (long)(ch * 32 + r) * 64 + c * 8);
            cpa16(vl + r * 144 + c * 16, vlsrc + (long)(ch * 32 + r) * 64 + c * 8);
        }
    };

    float acc[1][4][4];
#pragma unroll
    for (int j = 0; j < 4; j++)
#pragma unroll
        for (int k = 0; k < 4; k++) acc[0][j][k] = 0.f;

    load_chunk(0, 0);
    CP_COMMIT();
    __syncthreads();   // st[] visible
    const int crow = tid >> 2, cquar = tid & 3;
    const float M = st[crow][0], invS = st[crow][1];
    const int aoff = warp_m * 16 * 80, boff = warp_n * 32 * 2;

    for (int ch = 0; ch < 64; ch++) {
        if (ch < 63) { load_chunk((ch + 1) & 1, ch + 1); CP_COMMIT(); CP_WAIT1(); }
        else CP_WAIT0();
        __syncthreads();
        {
            const char* rp = smem + (ch & 1 ? RAW1 : RAW0) + crow * 144 + cquar * 32;
            float* wout = wsrc + (long)crow * 2048 + ch * 32 + cquar * 8;
            uint32_t uh[4], ul[4];
#pragma unroll
            for (int i = 0; i < 2; i++) {
                float4 v = *(const float4*)(rp + i * 16);
                v.x = __expf(v.x - M) * invS;
                v.y = __expf(v.y - M) * invS;
                v.z = __expf(v.z - M) * invS;
                v.w = __expf(v.w - M) * invS;
                *(float4*)(wout + i * 4) = v;
                bf16 h0, l0, h1, l1;
                split1(v.x, h0, l0); split1(v.y, h1, l1);
                uh[i * 2] = pack2(h0, h1); ul[i * 2] = pack2(l0, l1);
                split1(v.z, h0, l0); split1(v.w, h1, l1);
                uh[i * 2 + 1] = pack2(h0, h1); ul[i * 2 + 1] = pack2(l0, l1);
            }
            *(uint4*)(smem + WH + crow * 80 + cquar * 16) = make_uint4(uh[0], uh[1], uh[2], uh[3]);
            *(uint4*)(smem + WL + crow * 80 + cquar * 16) = make_uint4(ul[0], ul[1], ul[2], ul[3]);
        }
        __syncthreads();
        uint32_t vh = sb + ((ch & 1) ? VH1 : VH0) + boff;
        uint32_t vl = sb + ((ch & 1) ? VL1 : VL0) + boff;
        gemm3<1, 4, 2, true>(acc, sb + WH + aoff, sb + WL + aoff, vh, vl, 80, 144, lane);
        __syncthreads();
    }

    const int b_ = bh >> 4, h = bh & 15;
#pragma unroll
    for (int nt = 0; nt < 4; nt++) {
        int s0 = qt * 64 + warp_m * 16 + (lane >> 2);
        int dh = warp_n * 32 + nt * 8 + (lane & 3) * 2;
        long a0 = ((long)b_ * 2048 + s0) * 1024 + h * 64 + dh;
        long a1 = ((long)b_ * 2048 + s0 + 8) * 1024 + h * 64 + dh;
        bf16 hh0, ll0, hh1, ll1;
        split1(acc[0][nt][0], hh0, ll0); split1(acc[0][nt][1], hh1, ll1);
        *(uint32_t*)(Oh + a0) = pack2(hh0, hh1);
        *(uint32_t*)(Ol + a0) = pack2(ll0, ll1);
        split1(acc[0][nt][2], hh0, ll0); split1(acc[0][nt][3], hh1, ll1);
        *(uint32_t*)(Oh + a1) = pack2(hh0, hh1);
        *(uint32_t*)(Ol + a1) = pack2(ll0, ll1);
    }
}

// ---------------- dense: 64x128 tiles, 2 CTAs/SM ----------------
__global__ __launch_bounds__(256, 2) void dense_kernel(
    const bf16* __restrict__ Ahi, const bf16* __restrict__ Alo,
    const bf16* __restrict__ Bhi, const bf16* __restrict__ Blo,
    const float* __restrict__ bias, float* __restrict__ outD)
{
    extern __shared__ char smem[];
    const uint32_t sb = smem_u32(smem);
    const int tid = threadIdx.x, lane = tid & 31, wid = tid >> 5;
    const int warp_m = wid >> 2, warp_n = wid & 3;   // 2 x 4
    const long m0 = (long)blockIdx.y * 64, n0 = (long)blockIdx.x * 128;

    float acc[2][4][4];
#pragma unroll
    for (int i = 0; i < 2; i++)
#pragma unroll
        for (int j = 0; j < 4; j++)
#pragma unroll
            for (int k = 0; k < 4; k++) acc[i][j][k] = 0.f;

    const bf16* srcA[2] = {Ahi + m0 * 1024, Alo + m0 * 1024};
    const bf16* srcB[2] = {Bhi + n0 * 1024, Blo + n0 * 1024};
    auto load_chunk = [&](int buf, int kb) {
        uint32_t base = sb + buf * 30720;
        {
            int r = tid >> 2, c = tid & 3;
            const long off = (long)r * 1024 + kb + c * 8;
            cpa16(base + r * 80 + c * 16, srcA[0] + off);
            cpa16(base + 5120 + r * 80 + c * 16, srcA[1] + off);
        }
#pragma unroll
        for (int j = 0; j < 2; j++) {
            int idx = tid + j * 256;
            int r = idx >> 2, c = idx & 3;
            const long off = (long)r * 1024 + kb + c * 8;
            cpa16(base + 10240 + r * 80 + c * 16, srcB[0] + off);
            cpa16(base + 20480 + r * 80 + c * 16, srcB[1] + off);
        }
    };

    load_chunk(0, 0);
    CP_COMMIT();
    const int aoff = warp_m * 32 * 80, boff = warp_n * 32 * 80;
    for (int ch = 0; ch < 32; ch++) {
        if (ch < 31) { load_chunk((ch + 1) & 1, (ch + 1) * 32); CP_COMMIT(); CP_WAIT1(); }
        else CP_WAIT0();
        __syncthreads();
        uint32_t b = sb + (ch & 1) * 30720;
        gemm3<2, 4, 2, false>(acc, b + aoff, b + 5120 + aoff,
                              b + 10240 + boff, b + 20480 + boff, 80, 80, lane);
        __syncthreads();
    }

#pragma unroll
    for (int mt = 0; mt < 2; mt++) {
#pragma unroll
        for (int nt = 0; nt < 4; nt++) {
            int n = (int)n0 + warp_n * 32 + nt * 8 + (lane & 3) * 2;
            float bv0 = bias[n], bv1 = bias[n + 1];
            long r0 = m0 + warp_m * 32 + mt * 16 + (lane >> 2);
            *(float2*)(outD + r0 * 1024 + n) =
                make_float2(acc[mt][nt][0] + bv0, acc[mt][nt][1] + bv1);
            *(float2*)(outD + (r0 + 8) * 1024 + n) =
                make_float2(acc[mt][nt][2] + bv0, acc[mt][nt][3] + bv1);
        }
    }
}

// ---------------- host launcher ----------------
extern "C" void kernel_launch(void* const* d_in, const int* in_sizes, int n_in,
                              void* d_out, int out_size)
{
    const float* q    = (const float*)d_in[0];
    const float* k    = (const float*)d_in[1];
    const float* v    = (const float*)d_in[2];
    const int*   mask = (const int*)d_in[3];
    const float* wq_w = (const float*)d_in[4];
    const float* wq_b = (const float*)d_in[5];
    const float* wk_w = (const float*)d_in[6];
    const float* wk_b = (const float*)d_in[7];
    const float* wv_w = (const float*)d_in[8];
    const float* wv_b = (const float*)d_in[9];
    const float* dw   = (const float*)d_in[10];
    const float* db   = (const float*)d_in[11];

    float* out = (float*)d_out;
    float* wts = out + OUT_ELEMS;

    bf16 *xqh, *xql, *xkh, *xkl, *xvh, *xvl;
    bf16 *wqh, *wql, *wkh, *wkl, *wvh, *wvl, *wdh, *wdl;
    bf16 *qph, *qpl, *kph, *kpl, *vph, *vpl, *ah, *al;
    float* stats;
    uint32_t* pmp;
    cudaGetSymbolAddress((void**)&xqh, g_xq_hi); cudaGetSymbolAddress((void**)&xql, g_xq_lo);
    cudaGetSymbolAddress((void**)&xkh, g_xk_hi); cudaGetSymbolAddress((void**)&xkl, g_xk_lo);
    cudaGetSymbolAddress((void**)&xvh, g_xv_hi); cudaGetSymbolAddress((void**)&xvl, g_xv_lo);
    cudaGetSymbolAddress((void**)&wqh, g_wq_hi); cudaGetSymbolAddress((void**)&wql, g_wq_lo);
    cudaGetSymbolAddress((void**)&wkh, g_wk_hi); cudaGetSymbolAddress((void**)&wkl, g_wk_lo);
    cudaGetSymbolAddress((void**)&wvh, g_wv_hi); cudaGetSymbolAddress((void**)&wvl, g_wv_lo);
    cudaGetSymbolAddress((void**)&wdh, g_wd_hi); cudaGetSymbolAddress((void**)&wdl, g_wd_lo);
    cudaGetSymbolAddress((void**)&qph, g_qp_hi); cudaGetSymbolAddress((void**)&qpl, g_qp_lo);
    cudaGetSymbolAddress((void**)&kph, g_kp_hi); cudaGetSymbolAddress((void**)&kpl, g_kp_lo);
    cudaGetSymbolAddress((void**)&vph, g_vp_hi); cudaGetSymbolAddress((void**)&vpl, g_vp_lo);
    cudaGetSymbolAddress((void**)&ah,  g_ah);    cudaGetSymbolAddress((void**)&al,  g_al);
    cudaGetSymbolAddress((void**)&stats, g_stats);
    cudaGetSymbolAddress((void**)&pmp, g_pm);

    cudaFuncSetAttribute(qkv_kernel,    cudaFuncAttributeMaxDynamicSharedMemorySize, 61440);
    cudaFuncSetAttribute(dense_kernel,  cudaFuncAttributeMaxDynamicSharedMemorySize, 61440);
    cudaFuncSetAttribute(scores_kernel, cudaFuncAttributeMaxDynamicSharedMemorySize, 92160);
    cudaFuncSetAttribute(pv_kernel,     cudaFuncAttributeMaxDynamicSharedMemorySize, 47104);

    // launch 0: input splits
    Split3Args s3;
    s3.s[0] = {q, xqh, xql}; s3.s[1] = {k, xkh, xkl}; s3.s[2] = {v, xvh, xvl};
    split3_kernel<<<dim3(2048, 1, 3), 256>>>(s3);
    // launch 1: weight splits
    Split4Args s4;
    s4.s[0] = {wq_w, wqh, wql}; s4.s[1] = {wk_w, wkh, wkl};
    s4.s[2] = {wv_w, wvh, wvl}; s4.s[3] = {dw, wdh, wdl};
    split4_kernel<<<dim3(512, 1, 4), 256>>>(s4);
    // launch 2: pack mask bits
    pack_mask_kernel<<<1024, 256>>>(mask, pmp);

    // launch 3: QKV projections
    QKVArgs qa;
    qa.p[0] = {xqh, xql, wqh, wql, wq_b, qph, qpl};
    qa.p[1] = {xkh, xkl, wkh, wkl, wk_b, kph, kpl};
    qa.p[2] = {xvh, xvl, wvh, wvl, wv_b, vph, vpl};
    qkv_kernel<<<dim3(8, 64, 3), 256, 61440>>>(qa);

    // launch 4: scores (bitmask + raw scores + online stats)
    scores_kernel<<<dim3(32, 32), 256, 92160>>>(qph, qpl, kph, kpl, pmp, wts, stats);
    // launch 5: PV (exp + normalize + final weights + attn)
    pv_kernel<<<dim3(32, 32), 256, 47104>>>(wts, vph, vpl, stats, ah, al);
    // launch 6: dense
    dense_kernel<<<dim3(8, 64), 256, 61440>>>(ah, al, wdh, wdl, db, out);
}